// round 4
// baseline (speedup 1.0000x reference)
#include <cuda_runtime.h>
#include <math.h>
#include <stdint.h>

// ---------------- problem constants ----------------
#define BATCH   2
#define SEQ     2048
#define HDIM    2048          // hidden size
#define TB      4096          // BATCH*SEQ tokens
#define HNUM    4
#define DKH     256           // HEAD_K
#define DVH     512           // HEAD_V
#define KD      1024          // HNUM*DKH
#define VD      2048          // HNUM*DVH
#define CH      64            // CHUNK
#define NCHUNK  32            // SEQ/CH
#define SCALE   0.0625f       // DKH^-0.5
#define INV_GN  0.0625f       // 1/GATE_NORMALIZER
#define EPS_F   1e-5f

// ---------------- device scratch (no allocation allowed) ----------------
__device__ float d_q   [(size_t)TB * KD];
__device__ float d_k   [(size_t)TB * KD];
__device__ float d_v   [(size_t)TB * VD];
__device__ float d_gbuf[(size_t)TB * VD];
__device__ float d_gk  [(size_t)TB * KD];   // becomes in-chunk inclusive cumsum
__device__ float d_o   [(size_t)TB * VD];
__device__ float d_x16 [(size_t)TB * 16];
__device__ float d_C   [(size_t)BATCH * HNUM * NCHUNK * DKH * DVH]; // chunk KtV, then pre-chunk states

// ---------------- generic fp32 SGEMM: C[M,N] = A[M,K] @ B[K,N] ----------------
// BM=BN=128, BK=16, 256 threads, 8x8 per-thread tile. M%128==0, N%128==0, K%16==0.
__global__ __launch_bounds__(256) void sgemm_kernel(
    const float* __restrict__ A, const float* __restrict__ B, float* __restrict__ C,
    int M, int N, int K)
{
    __shared__ float As[16][128];  // [k][m] (transposed)
    __shared__ float Bs[16][128];  // [k][n]

    const int tid = threadIdx.x;
    const int tx  = tid & 15;      // n-dir
    const int ty  = tid >> 4;      // m-dir
    const int bn0 = blockIdx.x * 128;
    const int bm0 = blockIdx.y * 128;

    const float* Ab = A + (size_t)bm0 * K;
    const float* Bb = B + bn0;

    const int a_row = tid >> 2;           // 0..63
    const int a_col = (tid & 3) << 2;     // 0,4,8,12
    const int b_row = tid >> 5;           // 0..7
    const int b_col = (tid & 31) << 2;    // 0..124

    float acc[8][8];
    #pragma unroll
    for (int i = 0; i < 8; i++)
        #pragma unroll
        for (int j = 0; j < 8; j++) acc[i][j] = 0.f;

    for (int k0 = 0; k0 < K; k0 += 16) {
        float4 a0 = *(const float4*)(Ab + (size_t)a_row        * K + k0 + a_col);
        float4 a1 = *(const float4*)(Ab + (size_t)(a_row + 64) * K + k0 + a_col);
        As[a_col + 0][a_row]      = a0.x;
        As[a_col + 1][a_row]      = a0.y;
        As[a_col + 2][a_row]      = a0.z;
        As[a_col + 3][a_row]      = a0.w;
        As[a_col + 0][a_row + 64] = a1.x;
        As[a_col + 1][a_row + 64] = a1.y;
        As[a_col + 2][a_row + 64] = a1.z;
        As[a_col + 3][a_row + 64] = a1.w;
        float4 b0 = *(const float4*)(Bb + (size_t)(k0 + b_row)     * N + b_col);
        float4 b1 = *(const float4*)(Bb + (size_t)(k0 + b_row + 8) * N + b_col);
        *(float4*)&Bs[b_row][b_col]     = b0;
        *(float4*)&Bs[b_row + 8][b_col] = b1;
        __syncthreads();

        #pragma unroll
        for (int kk = 0; kk < 16; kk++) {
            float ar[8], br[8];
            *(float4*)(ar)     = *(float4*)&As[kk][ty * 8];
            *(float4*)(ar + 4) = *(float4*)&As[kk][ty * 8 + 4];
            *(float4*)(br)     = *(float4*)&Bs[kk][tx * 8];
            *(float4*)(br + 4) = *(float4*)&Bs[kk][tx * 8 + 4];
            #pragma unroll
            for (int i = 0; i < 8; i++)
                #pragma unroll
                for (int j = 0; j < 8; j++)
                    acc[i][j] = fmaf(ar[i], br[j], acc[i][j]);
        }
        __syncthreads();
    }

    #pragma unroll
    for (int i = 0; i < 8; i++) {
        size_t row = (size_t)(bm0 + ty * 8 + i);
        float* Cr = C + row * N + bn0 + tx * 8;
        *(float4*)(Cr)     = make_float4(acc[i][0], acc[i][1], acc[i][2], acc[i][3]);
        *(float4*)(Cr + 4) = make_float4(acc[i][4], acc[i][5], acc[i][6], acc[i][7]);
    }
}

// ---------------- gate low-rank: x16 = x @ Wgk1  (T x 2048) @ (2048 x 16) ----------------
__global__ __launch_bounds__(256) void gk1_kernel(
    const float* __restrict__ x, const float* __restrict__ W, float* __restrict__ out)
{
    const int t = blockIdx.x;
    const float* xr = x + (size_t)t * HDIM;
    float acc[16];
    #pragma unroll
    for (int j = 0; j < 16; j++) acc[j] = 0.f;

    for (int i = threadIdx.x; i < HDIM; i += 256) {
        float xv = xr[i];
        const float* wr = W + (size_t)i * 16;
        #pragma unroll
        for (int j = 0; j < 16; j++) acc[j] = fmaf(xv, wr[j], acc[j]);
    }
    #pragma unroll
    for (int j = 0; j < 16; j++)
        #pragma unroll
        for (int off = 16; off > 0; off >>= 1)
            acc[j] += __shfl_down_sync(0xffffffffu, acc[j], off);

    __shared__ float red[8][16];
    const int warp = threadIdx.x >> 5, lane = threadIdx.x & 31;
    if (lane == 0) {
        #pragma unroll
        for (int j = 0; j < 16; j++) red[warp][j] = acc[j];
    }
    __syncthreads();
    if (threadIdx.x < 16) {
        float s = 0.f;
        #pragma unroll
        for (int w = 0; w < 8; w++) s += red[w][threadIdx.x];
        out[(size_t)t * 16 + threadIdx.x] = s;
    }
}

// ---------------- gk = logsigmoid(x16 @ Wgk2 + b) / 16 ----------------
__global__ __launch_bounds__(256) void gk2_kernel(
    const float* __restrict__ x16, const float* __restrict__ W2,
    const float* __restrict__ bias, float* __restrict__ gk)
{
    const int t = blockIdx.x;
    __shared__ float xs[16];
    if (threadIdx.x < 16) xs[threadIdx.x] = x16[(size_t)t * 16 + threadIdx.x];
    __syncthreads();
    for (int j = threadIdx.x; j < KD; j += 256) {
        float s = bias[j];
        #pragma unroll
        for (int r = 0; r < 16; r++) s = fmaf(xs[r], W2[(size_t)r * KD + j], s);
        float ls = fminf(s, 0.f) - log1pf(expf(-fabsf(s)));   // stable log_sigmoid
        gk[(size_t)t * KD + j] = ls * INV_GN;
    }
}

// ---------------- in-chunk inclusive cumsum of gk (in place) ----------------
__global__ __launch_bounds__(1024) void cumsum_kernel(float* __restrict__ gk)
{
    const int bn = blockIdx.x;                 // b*NCHUNK + n
    const int b = bn / NCHUNK, n = bn % NCHUNK;
    const size_t t0 = (size_t)b * SEQ + (size_t)n * CH;
    const int c = threadIdx.x;                 // 0..1023 column
    float s = 0.f;
    for (int i = 0; i < CH; i++) {
        size_t idx = (t0 + i) * KD + c;
        s += gk[idx];
        gk[idx] = s;
    }
}

// ---------------- GLA phase 1: C[bhn] = k_dec^T @ v  (per-chunk summary) ----------------
// grid.x = 16  (2 dk-tiles of 128 x 8 dv-tiles of 64), grid.y = B*H*NCHUNK
__global__ __launch_bounds__(256) void chunk_kv_kernel(
    const float* __restrict__ k, const float* __restrict__ v,
    const float* __restrict__ gc, float* __restrict__ C)
{
    const int bhn = blockIdx.y;
    const int n = bhn % NCHUNK;
    const int bh = bhn / NCHUNK;
    const int h = bh % HNUM, b = bh / HNUM;
    const int dk0 = (blockIdx.x >> 3) * 128;
    const int dv0 = (blockIdx.x & 7) * 64;
    const size_t t0 = (size_t)b * SEQ + (size_t)n * CH;
    const int kc = h * DKH + dk0;
    const int vc = h * DVH + dv0;

    __shared__ float kd[64][128];
    __shared__ float vs[64][64];

    const int tid = threadIdx.x;
    // load kdec = k * exp(g_last - g)
    #pragma unroll
    for (int r = 0; r < 8; r++) {
        int f = tid + 256 * r;                // 2048 float4 groups
        int c = f >> 5;                       // 32 float4 per 128-row
        int off = (f & 31) << 2;
        size_t rb = (t0 + c) * KD + kc + off;
        size_t lb = (t0 + 63) * KD + kc + off;
        float4 kv = *(const float4*)(k + rb);
        float4 gv = *(const float4*)(gc + rb);
        float4 gl = *(const float4*)(gc + lb);
        float4 o4;
        o4.x = kv.x * expf(gl.x - gv.x);
        o4.y = kv.y * expf(gl.y - gv.y);
        o4.z = kv.z * expf(gl.z - gv.z);
        o4.w = kv.w * expf(gl.w - gv.w);
        *(float4*)&kd[c][off] = o4;
    }
    #pragma unroll
    for (int r = 0; r < 4; r++) {
        int f = tid + 256 * r;                // 1024 float4 groups
        int c = f >> 4;
        int off = (f & 15) << 2;
        *(float4*)&vs[c][off] = *(const float4*)(v + (t0 + c) * VD + vc + off);
    }
    __syncthreads();

    const int tx = tid & 15, ty = tid >> 4;
    float acc[8][4];
    #pragma unroll
    for (int i = 0; i < 8; i++)
        #pragma unroll
        for (int j = 0; j < 4; j++) acc[i][j] = 0.f;

    #pragma unroll 8
    for (int c = 0; c < 64; c++) {
        float a[8], bb[4];
        *(float4*)(a)     = *(float4*)&kd[c][ty * 8];
        *(float4*)(a + 4) = *(float4*)&kd[c][ty * 8 + 4];
        *(float4*)(bb)    = *(float4*)&vs[c][tx * 4];
        #pragma unroll
        for (int i = 0; i < 8; i++)
            #pragma unroll
            for (int j = 0; j < 4; j++)
                acc[i][j] = fmaf(a[i], bb[j], acc[i][j]);
    }

    const size_t cbase = (size_t)bhn * DKH * DVH;
    #pragma unroll
    for (int i = 0; i < 8; i++) {
        float* Cp = C + cbase + (size_t)(dk0 + ty * 8 + i) * DVH + dv0 + tx * 4;
        *(float4*)Cp = make_float4(acc[i][0], acc[i][1], acc[i][2], acc[i][3]);
    }
}

// ---------------- GLA scan: sequential over chunks; C[n] <- state BEFORE chunk n ----------------
// grid.x = 16 (dv slices of 32), grid.y = B*H ; 256 threads
__global__ __launch_bounds__(256) void scan_kernel(
    const float* __restrict__ gc, float* __restrict__ C)
{
    const int bh = blockIdx.y;
    const int h = bh % HNUM, b = bh / HNUM;
    const int dv0 = blockIdx.x * 32;
    const int tid = threadIdx.x;

    __shared__ float Ssm[256 * 32];   // [dk][dv-slice]
    __shared__ float eg[256];

    #pragma unroll
    for (int r = 0; r < 32; r++) Ssm[tid + 256 * r] = 0.f;

    for (int n = 0; n < NCHUNK; n++) {
        const size_t t0 = (size_t)b * SEQ + (size_t)n * CH;
        eg[tid] = expf(gc[(t0 + 63) * KD + h * DKH + tid]);   // per-dk chunk decay
        __syncthreads();
        const size_t base = (size_t)((bh * NCHUNK) + n) * DKH * DVH;
        #pragma unroll
        for (int r = 0; r < 32; r++) {
            int e = tid + 256 * r;
            int dk = e >> 5;
            int dv = dv0 + (e & 31);
            size_t idx = base + (size_t)dk * DVH + dv;
            float cv = C[idx];
            float s  = Ssm[e];
            C[idx] = s;                          // state before this chunk
            Ssm[e] = fmaf(s, eg[dk], cv);        // carry forward
        }
        __syncthreads();
    }
}

// ---------------- GLA phase 2: o = tril(q_g k_g^T) @ v + q_g @ S_init ----------------
// grid.x = 4 (dv tiles of 128), grid.y = B*H*NCHUNK ; 256 threads
__global__ __launch_bounds__(256) void gla_out_kernel(
    const float* __restrict__ q, const float* __restrict__ k,
    const float* __restrict__ v, const float* __restrict__ gc,
    const float* __restrict__ C, float* __restrict__ o)
{
    const int bhn = blockIdx.y;
    const int n = bhn % NCHUNK;
    const int bh = bhn / NCHUNK;
    const int h = bh % HNUM, b = bh / HNUM;
    const int dv0 = blockIdx.x * 128;
    const size_t t0 = (size_t)b * SEQ + (size_t)n * CH;
    const int kc = h * DKH;
    const int vc = h * DVH + dv0;
    const int tid = threadIdx.x, tx = tid & 15, ty = tid >> 4;

    __shared__ float pool[64 * 65 + 32 * 64 + 32 * 128];
    float* Asm = pool;                         // [64][65]
    float* P1  = pool + 64 * 65;               // [32][64]
    float* P2  = pool + 64 * 65 + 32 * 64;     // [32][128] (or [32][64])

    // ---- A = tril(q_g @ k_g^T) ----
    float accA[4][4];
    #pragma unroll
    for (int i = 0; i < 4; i++)
        #pragma unroll
        for (int j = 0; j < 4; j++) accA[i][j] = 0.f;

    for (int d0 = 0; d0 < DKH; d0 += 32) {
        #pragma unroll
        for (int r = 0; r < 2; r++) {
            int f = tid + 256 * r;            // 512 float4 groups (64 rows x 8)
            int c = f >> 3;
            int off = (f & 7) << 2;
            size_t base = (t0 + c) * KD + kc + d0 + off;
            float4 qv = *(const float4*)(q + base);
            float4 gv = *(const float4*)(gc + base);
            float4 kv = *(const float4*)(k + base);
            P1[(off + 0) * 64 + c] = qv.x * expf(gv.x) * SCALE;
            P1[(off + 1) * 64 + c] = qv.y * expf(gv.y) * SCALE;
            P1[(off + 2) * 64 + c] = qv.z * expf(gv.z) * SCALE;
            P1[(off + 3) * 64 + c] = qv.w * expf(gv.w) * SCALE;
            P2[(off + 0) * 64 + c] = kv.x * expf(-gv.x);
            P2[(off + 1) * 64 + c] = kv.y * expf(-gv.y);
            P2[(off + 2) * 64 + c] = kv.z * expf(-gv.z);
            P2[(off + 3) * 64 + c] = kv.w * expf(-gv.w);
        }
        __syncthreads();
        #pragma unroll
        for (int kk = 0; kk < 32; kk++) {
            float a[4], bb[4];
            *(float4*)a  = *(float4*)&P1[kk * 64 + ty * 4];
            *(float4*)bb = *(float4*)&P2[kk * 64 + tx * 4];
            #pragma unroll
            for (int i = 0; i < 4; i++)
                #pragma unroll
                for (int j = 0; j < 4; j++)
                    accA[i][j] = fmaf(a[i], bb[j], accA[i][j]);
        }
        __syncthreads();
    }
    #pragma unroll
    for (int i = 0; i < 4; i++)
        #pragma unroll
        for (int j = 0; j < 4; j++) {
            int ri = ty * 4 + i, cj = tx * 4 + j;
            Asm[ri * 65 + cj] = (ri >= cj) ? accA[i][j] : 0.f;
        }
    __syncthreads();

    float acc[4][8];
    #pragma unroll
    for (int i = 0; i < 4; i++)
        #pragma unroll
        for (int j = 0; j < 8; j++) acc[i][j] = 0.f;

    // ---- intra: o += A @ v ----
    for (int j0 = 0; j0 < 64; j0 += 32) {
        #pragma unroll
        for (int r = 0; r < 4; r++) {
            int f = tid + 256 * r;            // 1024 float4 (32 rows x 32)
            int c = f >> 5;
            int off = (f & 31) << 2;
            *(float4*)&P2[c * 128 + off] =
                *(const float4*)(v + (t0 + j0 + c) * VD + vc + off);
        }
        __syncthreads();
        #pragma unroll
        for (int jj = 0; jj < 32; jj++) {
            float bb[8];
            *(float4*)(bb)     = *(float4*)&P2[jj * 128 + tx * 8];
            *(float4*)(bb + 4) = *(float4*)&P2[jj * 128 + tx * 8 + 4];
            #pragma unroll
            for (int ii = 0; ii < 4; ii++) {
                float a = Asm[(ty * 4 + ii) * 65 + j0 + jj];
                #pragma unroll
                for (int j = 0; j < 8; j++) acc[ii][j] = fmaf(a, bb[j], acc[ii][j]);
            }
        }
        __syncthreads();
    }

    // ---- inter: o += q_g @ S_init ----
    const size_t sb = (size_t)bhn * DKH * DVH;
    for (int d0 = 0; d0 < DKH; d0 += 32) {
        #pragma unroll
        for (int r = 0; r < 2; r++) {
            int f = tid + 256 * r;
            int c = f >> 3;
            int off = (f & 7) << 2;
            size_t base = (t0 + c) * KD + kc + d0 + off;
            float4 qv = *(const float4*)(q + base);
            float4 gv = *(const float4*)(gc + base);
            P1[(off + 0) * 64 + c] = qv.x * expf(gv.x) * SCALE;
            P1[(off + 1) * 64 + c] = qv.y * expf(gv.y) * SCALE;
            P1[(off + 2) * 64 + c] = qv.z * expf(gv.z) * SCALE;
            P1[(off + 3) * 64 + c] = qv.w * expf(gv.w) * SCALE;
        }
        #pragma unroll
        for (int r = 0; r < 4; r++) {
            int f = tid + 256 * r;
            int c = f >> 5;
            int off = (f & 31) << 2;
            *(float4*)&P2[c * 128 + off] =
                *(const float4*)(C + sb + (size_t)(d0 + c) * DVH + dv0 + off);
        }
        __syncthreads();
        #pragma unroll
        for (int kk = 0; kk < 32; kk++) {
            float a[4], bb[8];
            *(float4*)a        = *(float4*)&P1[kk * 64 + ty * 4];
            *(float4*)(bb)     = *(float4*)&P2[kk * 128 + tx * 8];
            *(float4*)(bb + 4) = *(float4*)&P2[kk * 128 + tx * 8 + 4];
            #pragma unroll
            for (int ii = 0; ii < 4; ii++)
                #pragma unroll
                for (int j = 0; j < 8; j++)
                    acc[ii][j] = fmaf(a[ii], bb[j], acc[ii][j]);
        }
        __syncthreads();
    }

    // ---- store o ----
    #pragma unroll
    for (int ii = 0; ii < 4; ii++) {
        size_t row = t0 + ty * 4 + ii;
        float* op = o + row * VD + vc + tx * 8;
        *(float4*)(op)     = make_float4(acc[ii][0], acc[ii][1], acc[ii][2], acc[ii][3]);
        *(float4*)(op + 4) = make_float4(acc[ii][4], acc[ii][5], acc[ii][6], acc[ii][7]);
    }
}

// ---------------- rmsnorm (per head) * g_norm_weight * silu(g), in place ----------------
__global__ __launch_bounds__(256) void post_kernel(
    float* __restrict__ o, const float* __restrict__ g, const float* __restrict__ w)
{
    const int t = blockIdx.x, h = blockIdx.y;
    const size_t base = (size_t)t * VD + (size_t)h * DVH;
    const int tid = threadIdx.x;

    float v0 = o[base + tid];
    float v1 = o[base + tid + 256];
    float ss = v0 * v0 + v1 * v1;
    #pragma unroll
    for (int off = 16; off > 0; off >>= 1)
        ss += __shfl_down_sync(0xffffffffu, ss, off);

    __shared__ float red[8];
    __shared__ float inv_s;
    if ((tid & 31) == 0) red[tid >> 5] = ss;
    __syncthreads();
    if (tid == 0) {
        float s = 0.f;
        #pragma unroll
        for (int wi = 0; wi < 8; wi++) s += red[wi];
        inv_s = rsqrtf(s * (1.f / DVH) + EPS_F);
    }
    __syncthreads();
    const float inv = inv_s;

    float g0 = g[base + tid];
    float g1 = g[base + tid + 256];
    float s0 = g0 / (1.f + expf(-g0));
    float s1 = g1 / (1.f + expf(-g1));
    o[base + tid]       = v0 * inv * w[tid]       * s0;
    o[base + tid + 256] = v1 * inv * w[tid + 256] * s1;
}

// ---------------- launch ----------------
extern "C" void kernel_launch(void* const* d_in, const int* in_sizes, int n_in,
                              void* d_out, int out_size)
{
    const float* x    = (const float*)d_in[0];
    const float* Wq   = (const float*)d_in[1];
    const float* Wk   = (const float*)d_in[2];
    const float* Wv   = (const float*)d_in[3];
    const float* Wgk1 = (const float*)d_in[4];
    const float* Wgk2 = (const float*)d_in[5];
    const float* bgk2 = (const float*)d_in[6];
    const float* Wg   = (const float*)d_in[7];
    const float* gnw  = (const float*)d_in[8];
    const float* Wo   = (const float*)d_in[9];
    float* out = (float*)d_out;

    float *q, *k, *v, *g, *gk, *o, *x16, *C;
    cudaGetSymbolAddress((void**)&q,   d_q);
    cudaGetSymbolAddress((void**)&k,   d_k);
    cudaGetSymbolAddress((void**)&v,   d_v);
    cudaGetSymbolAddress((void**)&g,   d_gbuf);
    cudaGetSymbolAddress((void**)&gk,  d_gk);
    cudaGetSymbolAddress((void**)&o,   d_o);
    cudaGetSymbolAddress((void**)&x16, d_x16);
    cudaGetSymbolAddress((void**)&C,   d_C);

    // projections
    sgemm_kernel<<<dim3(KD / 128, TB / 128), 256>>>(x, Wq, q, TB, KD, HDIM);
    sgemm_kernel<<<dim3(KD / 128, TB / 128), 256>>>(x, Wk, k, TB, KD, HDIM);
    sgemm_kernel<<<dim3(VD / 128, TB / 128), 256>>>(x, Wv, v, TB, VD, HDIM);
    sgemm_kernel<<<dim3(VD / 128, TB / 128), 256>>>(x, Wg, g, TB, VD, HDIM);

    // gate path
    gk1_kernel<<<TB, 256>>>(x, Wgk1, x16);
    gk2_kernel<<<TB, 256>>>(x16, Wgk2, bgk2, gk);
    cumsum_kernel<<<BATCH * NCHUNK, 1024>>>(gk);

    // GLA
    chunk_kv_kernel<<<dim3(16, BATCH * HNUM * NCHUNK), 256>>>(k, v, gk, C);
    scan_kernel<<<dim3(16, BATCH * HNUM), 256>>>(gk, C);
    gla_out_kernel<<<dim3(4, BATCH * HNUM * NCHUNK), 256>>>(q, k, v, gk, C, o);

    // epilogue
    post_kernel<<<dim3(TB, HNUM), 256>>>(o, g, gnw);
    sgemm_kernel<<<dim3(VD / 128, TB / 128), 256>>>(o, Wo, out, TB, VD, VD);
}

// round 7
// speedup vs baseline: 1.1620x; 1.1620x over previous
#include <cuda_runtime.h>
#include <math.h>
#include <stdint.h>

// ---------------- problem constants ----------------
#define BATCH   2
#define SEQ     2048
#define HDIM    2048          // hidden size
#define TB      4096          // BATCH*SEQ tokens
#define HNUM    4
#define DKH     256           // HEAD_K
#define DVH     512           // HEAD_V
#define KD      1024          // HNUM*DKH
#define VD      2048          // HNUM*DVH
#define CH      64            // CHUNK
#define NCHUNK  32            // SEQ/CH
#define SCALE   0.0625f       // DKH^-0.5
#define INV_GN  0.0625f       // 1/GATE_NORMALIZER
#define EPS_F   1e-5f

// ---------------- device scratch (no allocation allowed) ----------------
__device__ float d_q   [(size_t)TB * KD];
__device__ float d_k   [(size_t)TB * KD];
__device__ float d_v   [(size_t)TB * VD];
__device__ float d_gbuf[(size_t)TB * VD];
__device__ float d_gk  [(size_t)TB * KD];   // becomes in-chunk inclusive cumsum
__device__ float d_o   [(size_t)TB * VD];
__device__ float d_x16 [(size_t)TB * 16];
__device__ float d_C   [(size_t)BATCH * HNUM * NCHUNK * DKH * DVH]; // chunk KtV, then pre-chunk states

// ---------------- packed f32x2 helpers (FFMA2 — ptxas never auto-fuses) ----------------
__device__ __forceinline__ unsigned long long pack2(float a) {
    unsigned long long r;
    asm("mov.b64 %0, {%1, %1};" : "=l"(r) : "f"(a));
    return r;
}
__device__ __forceinline__ unsigned long long fma2(unsigned long long a,
                                                   unsigned long long b,
                                                   unsigned long long c) {
    unsigned long long d;
    asm("fma.rn.f32x2 %0, %1, %2, %3;" : "=l"(d) : "l"(a), "l"(b), "l"(c));
    return d;
}
__device__ __forceinline__ float2 unpack2(unsigned long long v) {
    float2 r;
    asm("mov.b64 {%0, %1}, %2;" : "=f"(r.x), "=f"(r.y) : "l"(v));
    return r;
}

// ---------------- fp32 SGEMM body: C[128,128] tile of A[M,K] @ B[K,N] ----------------
// 256 threads, 8x8 per-thread in 4+4 fragment layout (conflict-free LDS), f32x2 FMA.
__device__ __forceinline__ void sgemm_body(
    const float* __restrict__ A, const float* __restrict__ B, float* __restrict__ C,
    int N, int K, int bn0, int bm0)
{
    __shared__ __align__(16) float As[16][128];  // [k][m] (transposed)
    __shared__ __align__(16) float Bs[16][128];  // [k][n]

    const int tid = threadIdx.x;
    const int tx  = tid & 15;      // n-dir
    const int ty  = tid >> 4;      // m-dir

    const int a_row = tid >> 2;           // 0..63
    const int a_col = (tid & 3) << 2;     // 0,4,8,12
    const int b_row = tid >> 5;           // 0..7
    const int b_col = (tid & 31) << 2;    // 0..124

    const float* Ap0 = A + (size_t)(bm0 + a_row)      * K + a_col;
    const float* Ap1 = A + (size_t)(bm0 + a_row + 64) * K + a_col;
    const float* Bp0 = B + (size_t)b_row       * N + bn0 + b_col;
    const float* Bp1 = B + (size_t)(b_row + 8) * N + bn0 + b_col;
    const size_t bstep = (size_t)16 * N;

    // acc[i][jp]: rows i<4 -> ty*4+i, i>=4 -> 64+ty*4+(i-4)
    // col pairs: jp0 -> tx*4+{0,1}, jp1 -> tx*4+{2,3}, jp2 -> 64+tx*4+{0,1}, jp3 -> 64+tx*4+{2,3}
    unsigned long long acc[8][4];
    #pragma unroll
    for (int i = 0; i < 8; i++)
        #pragma unroll
        for (int j = 0; j < 4; j++) acc[i][j] = 0ull;

    for (int k0 = 0; k0 < K; k0 += 16) {
        float4 a0 = *(const float4*)(Ap0 + k0);
        float4 a1 = *(const float4*)(Ap1 + k0);
        As[a_col + 0][a_row]      = a0.x;
        As[a_col + 1][a_row]      = a0.y;
        As[a_col + 2][a_row]      = a0.z;
        As[a_col + 3][a_row]      = a0.w;
        As[a_col + 0][a_row + 64] = a1.x;
        As[a_col + 1][a_row + 64] = a1.y;
        As[a_col + 2][a_row + 64] = a1.z;
        As[a_col + 3][a_row + 64] = a1.w;
        float4 b0 = *(const float4*)Bp0;
        float4 b1 = *(const float4*)Bp1;
        Bp0 += bstep; Bp1 += bstep;
        *(float4*)&Bs[b_row][b_col]     = b0;
        *(float4*)&Bs[b_row + 8][b_col] = b1;
        __syncthreads();

        #pragma unroll
        for (int kk = 0; kk < 16; kk++) {
            float4 af0 = *(const float4*)&As[kk][ty * 4];        // broadcast within half-warp
            float4 af1 = *(const float4*)&As[kk][64 + ty * 4];
            ulonglong2 bq0 = *(const ulonglong2*)&Bs[kk][tx * 4];      // 16B stride, conflict-free
            ulonglong2 bq1 = *(const ulonglong2*)&Bs[kk][64 + tx * 4];
            unsigned long long bv[4] = { bq0.x, bq0.y, bq1.x, bq1.y };
            float a[8] = { af0.x, af0.y, af0.z, af0.w, af1.x, af1.y, af1.z, af1.w };
            #pragma unroll
            for (int i = 0; i < 8; i++) {
                unsigned long long av = pack2(a[i]);
                #pragma unroll
                for (int jp = 0; jp < 4; jp++)
                    acc[i][jp] = fma2(av, bv[jp], acc[i][jp]);
            }
        }
        __syncthreads();
    }

    #pragma unroll
    for (int i = 0; i < 8; i++) {
        int row = bm0 + ((i < 4) ? (ty * 4 + i) : (64 + ty * 4 + (i - 4)));
        float2 p0 = unpack2(acc[i][0]);
        float2 p1 = unpack2(acc[i][1]);
        float2 p2 = unpack2(acc[i][2]);
        float2 p3 = unpack2(acc[i][3]);
        float* Cr = C + (size_t)row * N + bn0;
        *(float4*)(Cr + tx * 4)      = make_float4(p0.x, p0.y, p1.x, p1.y);
        *(float4*)(Cr + 64 + tx * 4) = make_float4(p2.x, p2.y, p3.x, p3.y);
    }
}

// fused Q/K/V/G projections: one launch, 48 n-tiles x 32 m-tiles
__global__ __launch_bounds__(256) void qkvg_gemm_kernel(
    const float* __restrict__ x,
    const float* __restrict__ Wq, const float* __restrict__ Wk,
    const float* __restrict__ Wv, const float* __restrict__ Wg,
    float* __restrict__ q, float* __restrict__ k,
    float* __restrict__ v, float* __restrict__ g)
{
    const int nt = blockIdx.x;
    const float* B; float* C; int N, nb;
    if (nt < 8)       { B = Wq; C = q; N = KD; nb = nt; }
    else if (nt < 16) { B = Wk; C = k; N = KD; nb = nt - 8; }
    else if (nt < 32) { B = Wv; C = v; N = VD; nb = nt - 16; }
    else              { B = Wg; C = g; N = VD; nb = nt - 32; }
    sgemm_body(x, B, C, N, HDIM, nb * 128, blockIdx.y * 128);
}

__global__ __launch_bounds__(256) void sgemm_kernel(
    const float* __restrict__ A, const float* __restrict__ B, float* __restrict__ C,
    int N, int K)
{
    sgemm_body(A, B, C, N, K, blockIdx.x * 128, blockIdx.y * 128);
}

// ---------------- gate low-rank: x16 = x @ Wgk1  (T x 2048) @ (2048 x 16) ----------------
__global__ __launch_bounds__(256) void gk1_kernel(
    const float* __restrict__ x, const float* __restrict__ W, float* __restrict__ out)
{
    const int t = blockIdx.x;
    const float* xr = x + (size_t)t * HDIM;
    float acc[16];
    #pragma unroll
    for (int j = 0; j < 16; j++) acc[j] = 0.f;

    for (int i = threadIdx.x; i < HDIM; i += 256) {
        float xv = xr[i];
        const float* wr = W + (size_t)i * 16;
        #pragma unroll
        for (int j = 0; j < 16; j++) acc[j] = fmaf(xv, wr[j], acc[j]);
    }
    #pragma unroll
    for (int j = 0; j < 16; j++)
        #pragma unroll
        for (int off = 16; off > 0; off >>= 1)
            acc[j] += __shfl_down_sync(0xffffffffu, acc[j], off);

    __shared__ float red[8][16];
    const int warp = threadIdx.x >> 5, lane = threadIdx.x & 31;
    if (lane == 0) {
        #pragma unroll
        for (int j = 0; j < 16; j++) red[warp][j] = acc[j];
    }
    __syncthreads();
    if (threadIdx.x < 16) {
        float s = 0.f;
        #pragma unroll
        for (int w = 0; w < 8; w++) s += red[w][threadIdx.x];
        out[(size_t)t * 16 + threadIdx.x] = s;
    }
}

// ---------------- gk = logsigmoid(x16 @ Wgk2 + b) / 16 ----------------
__global__ __launch_bounds__(256) void gk2_kernel(
    const float* __restrict__ x16, const float* __restrict__ W2,
    const float* __restrict__ bias, float* __restrict__ gk)
{
    const int t = blockIdx.x;
    __shared__ float xs[16];
    if (threadIdx.x < 16) xs[threadIdx.x] = x16[(size_t)t * 16 + threadIdx.x];
    __syncthreads();
    for (int j = threadIdx.x; j < KD; j += 256) {
        float s = bias[j];
        #pragma unroll
        for (int r = 0; r < 16; r++) s = fmaf(xs[r], W2[(size_t)r * KD + j], s);
        float ls = fminf(s, 0.f) - log1pf(expf(-fabsf(s)));   // stable log_sigmoid
        gk[(size_t)t * KD + j] = ls * INV_GN;
    }
}

// ---------------- in-chunk inclusive cumsum of gk (in place) ----------------
__global__ __launch_bounds__(1024) void cumsum_kernel(float* __restrict__ gk)
{
    const int bn = blockIdx.x;                 // b*NCHUNK + n
    const int b = bn / NCHUNK, n = bn % NCHUNK;
    const size_t t0 = (size_t)b * SEQ + (size_t)n * CH;
    const int c = threadIdx.x;                 // 0..1023 column
    float s = 0.f;
    for (int i = 0; i < CH; i++) {
        size_t idx = (t0 + i) * KD + c;
        s += gk[idx];
        gk[idx] = s;
    }
}

// ---------------- GLA phase 1: C[bhn] = k_dec^T @ v  (per-chunk summary) ----------------
// grid.x = 16  (2 dk-tiles of 128 x 8 dv-tiles of 64), grid.y = B*H*NCHUNK
__global__ __launch_bounds__(256) void chunk_kv_kernel(
    const float* __restrict__ k, const float* __restrict__ v,
    const float* __restrict__ gc, float* __restrict__ C)
{
    const int bhn = blockIdx.y;
    const int n = bhn % NCHUNK;
    const int bh = bhn / NCHUNK;
    const int h = bh % HNUM, b = bh / HNUM;
    const int dk0 = (blockIdx.x >> 3) * 128;
    const int dv0 = (blockIdx.x & 7) * 64;
    const size_t t0 = (size_t)b * SEQ + (size_t)n * CH;
    const int kc = h * DKH + dk0;
    const int vc = h * DVH + dv0;

    __shared__ __align__(16) float kd[64][128];
    __shared__ __align__(16) float vs[64][64];

    const int tid = threadIdx.x;
    // load kdec = k * exp(g_last - g)
    #pragma unroll
    for (int r = 0; r < 8; r++) {
        int f = tid + 256 * r;                // 2048 float4 groups
        int c = f >> 5;                       // 32 float4 per 128-row
        int off = (f & 31) << 2;
        size_t rb = (t0 + c) * KD + kc + off;
        size_t lb = (t0 + 63) * KD + kc + off;
        float4 kv = *(const float4*)(k + rb);
        float4 gv = *(const float4*)(gc + rb);
        float4 gl = *(const float4*)(gc + lb);
        float4 o4;
        o4.x = kv.x * expf(gl.x - gv.x);
        o4.y = kv.y * expf(gl.y - gv.y);
        o4.z = kv.z * expf(gl.z - gv.z);
        o4.w = kv.w * expf(gl.w - gv.w);
        *(float4*)&kd[c][off] = o4;
    }
    #pragma unroll
    for (int r = 0; r < 4; r++) {
        int f = tid + 256 * r;                // 1024 float4 groups
        int c = f >> 4;
        int off = (f & 15) << 2;
        *(float4*)&vs[c][off] = *(const float4*)(v + (t0 + c) * VD + vc + off);
    }
    __syncthreads();

    const int tx = tid & 15, ty = tid >> 4;
    unsigned long long acc[8][2];
    #pragma unroll
    for (int i = 0; i < 8; i++) { acc[i][0] = 0ull; acc[i][1] = 0ull; }

    #pragma unroll 8
    for (int c = 0; c < 64; c++) {
        float4 af0 = *(const float4*)&kd[c][ty * 8];       // broadcast within half-warp
        float4 af1 = *(const float4*)&kd[c][ty * 8 + 4];
        ulonglong2 bq = *(const ulonglong2*)&vs[c][tx * 4]; // contiguous, conflict-free
        float a[8] = { af0.x, af0.y, af0.z, af0.w, af1.x, af1.y, af1.z, af1.w };
        #pragma unroll
        for (int i = 0; i < 8; i++) {
            unsigned long long av = pack2(a[i]);
            acc[i][0] = fma2(av, bq.x, acc[i][0]);
            acc[i][1] = fma2(av, bq.y, acc[i][1]);
        }
    }

    const size_t cbase = (size_t)bhn * DKH * DVH;
    #pragma unroll
    for (int i = 0; i < 8; i++) {
        float2 p0 = unpack2(acc[i][0]);
        float2 p1 = unpack2(acc[i][1]);
        float* Cp = C + cbase + (size_t)(dk0 + ty * 8 + i) * DVH + dv0 + tx * 4;
        *(float4*)Cp = make_float4(p0.x, p0.y, p1.x, p1.y);
    }
}

// ---------------- GLA scan: sequential over chunks; C[n] <- state BEFORE chunk n ----------------
// grid.x = 16 (dv slices of 32), grid.y = B*H ; 256 threads
__global__ __launch_bounds__(256) void scan_kernel(
    const float* __restrict__ gc, float* __restrict__ C)
{
    const int bh = blockIdx.y;
    const int h = bh % HNUM, b = bh / HNUM;
    const int dv0 = blockIdx.x * 32;
    const int tid = threadIdx.x;

    __shared__ float Ssm[256 * 32];   // [dk][dv-slice]
    __shared__ float eg[256];

    #pragma unroll
    for (int r = 0; r < 32; r++) Ssm[tid + 256 * r] = 0.f;

    for (int n = 0; n < NCHUNK; n++) {
        const size_t t0 = (size_t)b * SEQ + (size_t)n * CH;
        eg[tid] = expf(gc[(t0 + 63) * KD + h * DKH + tid]);   // per-dk chunk decay
        __syncthreads();
        const size_t base = (size_t)((bh * NCHUNK) + n) * DKH * DVH;
        #pragma unroll
        for (int r = 0; r < 32; r++) {
            int e = tid + 256 * r;
            int dk = e >> 5;
            int dv = dv0 + (e & 31);
            size_t idx = base + (size_t)dk * DVH + dv;
            float cv = C[idx];
            float s  = Ssm[e];
            C[idx] = s;                          // state before this chunk
            Ssm[e] = fmaf(s, eg[dk], cv);        // carry forward
        }
        __syncthreads();
    }
}

// ---------------- GLA phase 2: o = tril(q_g k_g^T) @ v + q_g @ S_init ----------------
// grid.x = 4 (dv tiles of 128), grid.y = B*H*NCHUNK ; 256 threads
__global__ __launch_bounds__(256) void gla_out_kernel(
    const float* __restrict__ q, const float* __restrict__ k,
    const float* __restrict__ v, const float* __restrict__ gc,
    const float* __restrict__ C, float* __restrict__ o)
{
    const int bhn = blockIdx.y;
    const int n = bhn % NCHUNK;
    const int bh = bhn / NCHUNK;
    const int h = bh % HNUM, b = bh / HNUM;
    const int dv0 = blockIdx.x * 128;
    const size_t t0 = (size_t)b * SEQ + (size_t)n * CH;
    const int kc = h * DKH;
    const int vc = h * DVH + dv0;
    const int tid = threadIdx.x, tx = tid & 15, ty = tid >> 4;

    __shared__ __align__(16) float pool[64 * 65 + 32 * 64 + 32 * 128];
    float* Asm = pool;                         // [64][65]
    float* P1  = pool + 64 * 65;               // [32][64]
    float* P2  = pool + 64 * 65 + 32 * 64;     // [32][128] (or [32][64])

    // ---- A = tril(q_g @ k_g^T) ----
    unsigned long long accA[4][2];
    #pragma unroll
    for (int i = 0; i < 4; i++) { accA[i][0] = 0ull; accA[i][1] = 0ull; }

    for (int d0 = 0; d0 < DKH; d0 += 32) {
        #pragma unroll
        for (int r = 0; r < 2; r++) {
            int f = tid + 256 * r;            // 512 float4 groups (64 rows x 8)
            int c = f >> 3;
            int off = (f & 7) << 2;
            size_t base = (t0 + c) * KD + kc + d0 + off;
            float4 qv = *(const float4*)(q + base);
            float4 gv = *(const float4*)(gc + base);
            float4 kv = *(const float4*)(k + base);
            P1[(off + 0) * 64 + c] = qv.x * expf(gv.x) * SCALE;
            P1[(off + 1) * 64 + c] = qv.y * expf(gv.y) * SCALE;
            P1[(off + 2) * 64 + c] = qv.z * expf(gv.z) * SCALE;
            P1[(off + 3) * 64 + c] = qv.w * expf(gv.w) * SCALE;
            P2[(off + 0) * 64 + c] = kv.x * expf(-gv.x);
            P2[(off + 1) * 64 + c] = kv.y * expf(-gv.y);
            P2[(off + 2) * 64 + c] = kv.z * expf(-gv.z);
            P2[(off + 3) * 64 + c] = kv.w * expf(-gv.w);
        }
        __syncthreads();
        #pragma unroll
        for (int kk = 0; kk < 32; kk++) {
            float4 a4 = *(const float4*)&P1[kk * 64 + ty * 4];       // broadcast
            ulonglong2 bq = *(const ulonglong2*)&P2[kk * 64 + tx * 4]; // conflict-free
            float a[4] = { a4.x, a4.y, a4.z, a4.w };
            #pragma unroll
            for (int i = 0; i < 4; i++) {
                unsigned long long av = pack2(a[i]);
                accA[i][0] = fma2(av, bq.x, accA[i][0]);
                accA[i][1] = fma2(av, bq.y, accA[i][1]);
            }
        }
        __syncthreads();
    }
    #pragma unroll
    for (int i = 0; i < 4; i++) {
        float2 p0 = unpack2(accA[i][0]);
        float2 p1 = unpack2(accA[i][1]);
        float vals[4] = { p0.x, p0.y, p1.x, p1.y };
        int ri = ty * 4 + i;
        #pragma unroll
        for (int j = 0; j < 4; j++) {
            int cj = tx * 4 + j;
            Asm[ri * 65 + cj] = (ri >= cj) ? vals[j] : 0.f;
        }
    }
    __syncthreads();

    // acc[ii][jp]: row ty*4+ii; col pairs jp0/1 -> tx*4+{0,1}/{2,3}, jp2/3 -> 64+tx*4+{0,1}/{2,3}
    unsigned long long acc[4][4];
    #pragma unroll
    for (int i = 0; i < 4; i++)
        #pragma unroll
        for (int j = 0; j < 4; j++) acc[i][j] = 0ull;

    // ---- intra: o += A @ v ----
    for (int j0 = 0; j0 < 64; j0 += 32) {
        #pragma unroll
        for (int r = 0; r < 4; r++) {
            int f = tid + 256 * r;            // 1024 float4 (32 rows x 32)
            int c = f >> 5;
            int off = (f & 31) << 2;
            *(float4*)&P2[c * 128 + off] =
                *(const float4*)(v + (t0 + j0 + c) * VD + vc + off);
        }
        __syncthreads();
        #pragma unroll
        for (int jj = 0; jj < 32; jj++) {
            ulonglong2 b0 = *(const ulonglong2*)&P2[jj * 128 + tx * 4];
            ulonglong2 b1 = *(const ulonglong2*)&P2[jj * 128 + 64 + tx * 4];
            unsigned long long bv[4] = { b0.x, b0.y, b1.x, b1.y };
            #pragma unroll
            for (int ii = 0; ii < 4; ii++) {
                unsigned long long av = pack2(Asm[(ty * 4 + ii) * 65 + j0 + jj]);
                #pragma unroll
                for (int jp = 0; jp < 4; jp++)
                    acc[ii][jp] = fma2(av, bv[jp], acc[ii][jp]);
            }
        }
        __syncthreads();
    }

    // ---- inter: o += q_g @ S_init ----
    const size_t sb = (size_t)bhn * DKH * DVH;
    for (int d0 = 0; d0 < DKH; d0 += 32) {
        #pragma unroll
        for (int r = 0; r < 2; r++) {
            int f = tid + 256 * r;
            int c = f >> 3;
            int off = (f & 7) << 2;
            size_t base = (t0 + c) * KD + kc + d0 + off;
            float4 qv = *(const float4*)(q + base);
            float4 gv = *(const float4*)(gc + base);
            P1[(off + 0) * 64 + c] = qv.x * expf(gv.x) * SCALE;
            P1[(off + 1) * 64 + c] = qv.y * expf(gv.y) * SCALE;
            P1[(off + 2) * 64 + c] = qv.z * expf(gv.z) * SCALE;
            P1[(off + 3) * 64 + c] = qv.w * expf(gv.w) * SCALE;
        }
        #pragma unroll
        for (int r = 0; r < 4; r++) {
            int f = tid + 256 * r;
            int c = f >> 5;
            int off = (f & 31) << 2;
            *(float4*)&P2[c * 128 + off] =
                *(const float4*)(C + sb + (size_t)(d0 + c) * DVH + dv0 + off);
        }
        __syncthreads();
        #pragma unroll
        for (int kk = 0; kk < 32; kk++) {
            float4 a4 = *(const float4*)&P1[kk * 64 + ty * 4];
            ulonglong2 b0 = *(const ulonglong2*)&P2[kk * 128 + tx * 4];
            ulonglong2 b1 = *(const ulonglong2*)&P2[kk * 128 + 64 + tx * 4];
            unsigned long long bv[4] = { b0.x, b0.y, b1.x, b1.y };
            float a[4] = { a4.x, a4.y, a4.z, a4.w };
            #pragma unroll
            for (int ii = 0; ii < 4; ii++) {
                unsigned long long av = pack2(a[ii]);
                #pragma unroll
                for (int jp = 0; jp < 4; jp++)
                    acc[ii][jp] = fma2(av, bv[jp], acc[ii][jp]);
            }
        }
        __syncthreads();
    }

    // ---- store o ----
    #pragma unroll
    for (int ii = 0; ii < 4; ii++) {
        size_t row = t0 + ty * 4 + ii;
        float2 p0 = unpack2(acc[ii][0]);
        float2 p1 = unpack2(acc[ii][1]);
        float2 p2 = unpack2(acc[ii][2]);
        float2 p3 = unpack2(acc[ii][3]);
        float* op = o + row * VD + vc;
        *(float4*)(op + tx * 4)      = make_float4(p0.x, p0.y, p1.x, p1.y);
        *(float4*)(op + 64 + tx * 4) = make_float4(p2.x, p2.y, p3.x, p3.y);
    }
}

// ---------------- rmsnorm (per head) * g_norm_weight * silu(g), in place ----------------
__global__ __launch_bounds__(256) void post_kernel(
    float* __restrict__ o, const float* __restrict__ g, const float* __restrict__ w)
{
    const int t = blockIdx.x, h = blockIdx.y;
    const size_t base = (size_t)t * VD + (size_t)h * DVH;
    const int tid = threadIdx.x;

    float v0 = o[base + tid];
    float v1 = o[base + tid + 256];
    float ss = v0 * v0 + v1 * v1;
    #pragma unroll
    for (int off = 16; off > 0; off >>= 1)
        ss += __shfl_down_sync(0xffffffffu, ss, off);

    __shared__ float red[8];
    __shared__ float inv_s;
    if ((tid & 31) == 0) red[tid >> 5] = ss;
    __syncthreads();
    if (tid == 0) {
        float s = 0.f;
        #pragma unroll
        for (int wi = 0; wi < 8; wi++) s += red[wi];
        inv_s = rsqrtf(s * (1.f / DVH) + EPS_F);
    }
    __syncthreads();
    const float inv = inv_s;

    float g0 = g[base + tid];
    float g1 = g[base + tid + 256];
    float s0 = g0 / (1.f + expf(-g0));
    float s1 = g1 / (1.f + expf(-g1));
    o[base + tid]       = v0 * inv * w[tid]       * s0;
    o[base + tid + 256] = v1 * inv * w[tid + 256] * s1;
}

// ---------------- launch ----------------
extern "C" void kernel_launch(void* const* d_in, const int* in_sizes, int n_in,
                              void* d_out, int out_size)
{
    const float* x    = (const float*)d_in[0];
    const float* Wq   = (const float*)d_in[1];
    const float* Wk   = (const float*)d_in[2];
    const float* Wv   = (const float*)d_in[3];
    const float* Wgk1 = (const float*)d_in[4];
    const float* Wgk2 = (const float*)d_in[5];
    const float* bgk2 = (const float*)d_in[6];
    const float* Wg   = (const float*)d_in[7];
    const float* gnw  = (const float*)d_in[8];
    const float* Wo   = (const float*)d_in[9];
    float* out = (float*)d_out;

    float *q, *k, *v, *g, *gk, *o, *x16, *C;
    cudaGetSymbolAddress((void**)&q,   d_q);
    cudaGetSymbolAddress((void**)&k,   d_k);
    cudaGetSymbolAddress((void**)&v,   d_v);
    cudaGetSymbolAddress((void**)&g,   d_gbuf);
    cudaGetSymbolAddress((void**)&gk,  d_gk);
    cudaGetSymbolAddress((void**)&o,   d_o);
    cudaGetSymbolAddress((void**)&x16, d_x16);
    cudaGetSymbolAddress((void**)&C,   d_C);

    // fused projections (Wq|Wk|Wv|Wg share the x operand)
    qkvg_gemm_kernel<<<dim3(48, TB / 128), 256>>>(x, Wq, Wk, Wv, Wg, q, k, v, g);

    // gate path
    gk1_kernel<<<TB, 256>>>(x, Wgk1, x16);
    gk2_kernel<<<TB, 256>>>(x16, Wgk2, bgk2, gk);
    cumsum_kernel<<<BATCH * NCHUNK, 1024>>>(gk);

    // GLA
    chunk_kv_kernel<<<dim3(16, BATCH * HNUM * NCHUNK), 256>>>(k, v, gk, C);
    scan_kernel<<<dim3(16, BATCH * HNUM), 256>>>(gk, C);
    gla_out_kernel<<<dim3(4, BATCH * HNUM * NCHUNK), 256>>>(q, k, v, gk, C, o);

    // epilogue
    post_kernel<<<dim3(TB, HNUM), 256>>>(o, g, gnw);
    sgemm_kernel<<<dim3(VD / 128, TB / 128), 256>>>(o, Wo, out, VD, VD);
}

// round 9
// speedup vs baseline: 1.6813x; 1.4470x over previous
#include <cuda_runtime.h>
#include <cuda_bf16.h>
#include <math.h>
#include <stdint.h>

// ---------------- problem constants ----------------
#define BATCH   2
#define SEQ     2048
#define HDIM    2048          // hidden size
#define TB      4096          // BATCH*SEQ tokens
#define HNUM    4
#define DKH     256           // HEAD_K
#define DVH     512           // HEAD_V
#define KD      1024          // HNUM*DKH
#define VD      2048          // HNUM*DVH
#define CH      64            // CHUNK
#define NCHUNK  32            // SEQ/CH
#define SCALE   0.0625f       // DKH^-0.5
#define INV_GN  0.0625f       // 1/GATE_NORMALIZER
#define EPS_F   1e-5f

#define GEMM_K  2048          // K dim for every big GEMM
#define BKG     32            // K per SMEM slab
#define NITG    (GEMM_K / BKG) // 64
#define QKVG_NT 48            // 6144/128 output column tiles
#define TPAD    40            // padded row length in bf16 (20 banks -> conflict-free frags)
#define TS      (128 * TPAD)  // bf16 elems per tile

// ---------------- device scratch (no allocation allowed) ----------------
__device__ float d_q   [(size_t)TB * KD];
__device__ float d_k   [(size_t)TB * KD];
__device__ float d_v   [(size_t)TB * VD];
__device__ float d_gbuf[(size_t)TB * VD];
__device__ float d_gk  [(size_t)TB * KD];
__device__ float d_o   [(size_t)TB * VD];
__device__ float d_x16 [(size_t)TB * 16];
__device__ float d_C   [(size_t)BATCH * HNUM * NCHUNK * DKH * DVH];

// bf16 split buffers for tensor-core GEMMs
__device__ __nv_bfloat16 d_xhi [(size_t)TB * HDIM];
__device__ __nv_bfloat16 d_xlo [(size_t)TB * HDIM];
__device__ __nv_bfloat16 d_wthi[(size_t)(2 * KD + 2 * VD) * GEMM_K]; // [6144][2048]
__device__ __nv_bfloat16 d_wtlo[(size_t)(2 * KD + 2 * VD) * GEMM_K];
__device__ __nv_bfloat16 d_wohi[(size_t)HDIM * GEMM_K];              // [2048][2048]
__device__ __nv_bfloat16 d_wolo[(size_t)HDIM * GEMM_K];
__device__ __nv_bfloat16 d_ohi [(size_t)TB * VD];
__device__ __nv_bfloat16 d_olo [(size_t)TB * VD];

// ---------------- packed f32x2 helpers (GLA kernels) ----------------
__device__ __forceinline__ unsigned long long pack2(float a) {
    unsigned long long r;
    asm("mov.b64 %0, {%1, %1};" : "=l"(r) : "f"(a));
    return r;
}
__device__ __forceinline__ unsigned long long fma2(unsigned long long a,
                                                   unsigned long long b,
                                                   unsigned long long c) {
    unsigned long long d;
    asm("fma.rn.f32x2 %0, %1, %2, %3;" : "=l"(d) : "l"(a), "l"(b), "l"(c));
    return d;
}
__device__ __forceinline__ float2 unpack2(unsigned long long v) {
    float2 r;
    asm("mov.b64 {%0, %1}, %2;" : "=f"(r.x), "=f"(r.y) : "l"(v));
    return r;
}

// ---------------- HMMA / cp.async helpers (baseline sm_80+ features) ----------------
__device__ __forceinline__ void mma_bf16(float* c, const uint32_t* a, const uint32_t* b) {
    asm volatile(
        "mma.sync.aligned.m16n8k16.row.col.f32.bf16.bf16.f32 "
        "{%0,%1,%2,%3}, {%4,%5,%6,%7}, {%8,%9}, {%0,%1,%2,%3};"
        : "+f"(c[0]), "+f"(c[1]), "+f"(c[2]), "+f"(c[3])
        : "r"(a[0]), "r"(a[1]), "r"(a[2]), "r"(a[3]), "r"(b[0]), "r"(b[1]));
}
__device__ __forceinline__ void cp_async16(uint32_t dst, const void* src) {
    asm volatile("cp.async.cg.shared.global [%0], [%1], 16;" :: "r"(dst), "l"(src));
}
__device__ __forceinline__ void cp_commit() {
    asm volatile("cp.async.commit_group;");
}
__device__ __forceinline__ void cp_wait0() {
    asm volatile("cp.async.wait_group 0;" ::: "memory");
}
__device__ __forceinline__ uint32_t smem_u32(const void* p) {
    return (uint32_t)__cvta_generic_to_shared(p);
}

// ---------------- split conversion: fp32 -> (hi, lo) bf16 ----------------
__global__ __launch_bounds__(256) void split_kernel(
    const float* __restrict__ in, __nv_bfloat16* __restrict__ hi,
    __nv_bfloat16* __restrict__ lo)
{
    size_t i = (size_t)blockIdx.x * 256 + threadIdx.x;   // one float4 per thread
    float4 v = ((const float4*)in)[i];
    __nv_bfloat16 h0 = __float2bfloat16(v.x);
    __nv_bfloat16 h1 = __float2bfloat16(v.y);
    __nv_bfloat16 h2 = __float2bfloat16(v.z);
    __nv_bfloat16 h3 = __float2bfloat16(v.w);
    __nv_bfloat16 l0 = __float2bfloat16(v.x - __bfloat162float(h0));
    __nv_bfloat16 l1 = __float2bfloat16(v.y - __bfloat162float(h1));
    __nv_bfloat16 l2 = __float2bfloat16(v.z - __bfloat162float(h2));
    __nv_bfloat16 l3 = __float2bfloat16(v.w - __bfloat162float(h3));
    __nv_bfloat162* hp = (__nv_bfloat162*)hi;
    __nv_bfloat162* lp = (__nv_bfloat162*)lo;
    __nv_bfloat162 a; a.x = h0; a.y = h1;
    __nv_bfloat162 b; b.x = h2; b.y = h3;
    hp[i * 2] = a; hp[i * 2 + 1] = b;
    a.x = l0; a.y = l1; b.x = l2; b.y = l3;
    lp[i * 2] = a; lp[i * 2 + 1] = b;
}

// ---------------- transpose + split: W[K=2048][N] -> Wt_hi/lo [N][2048] ----------------
__global__ __launch_bounds__(256) void tsplit_kernel(
    const float* __restrict__ W, __nv_bfloat16* __restrict__ hiT,
    __nv_bfloat16* __restrict__ loT, int N)
{
    __shared__ float t[32][33];
    const int n0 = blockIdx.x * 32, k0 = blockIdx.y * 32;
    const int tx = threadIdx.x & 31, ty = threadIdx.x >> 5;   // 32 x 8
    #pragma unroll
    for (int j = 0; j < 4; j++)
        t[ty + 8 * j][tx] = W[(size_t)(k0 + ty + 8 * j) * N + n0 + tx];
    __syncthreads();
    #pragma unroll
    for (int j = 0; j < 4; j++) {
        float v = t[tx][ty + 8 * j];
        __nv_bfloat16 h = __float2bfloat16(v);
        size_t idx = (size_t)(n0 + ty + 8 * j) * GEMM_K + k0 + tx;
        hiT[idx] = h;
        loT[idx] = __float2bfloat16(v - __bfloat162float(h));
    }
}

// ---------------- HMMA GEMM: 128x128 output tile, K=2048, split bf16 ----------------
// A (hi/lo): [M][2048] K-major. Bt (hi/lo): [Ntot][2048] K-major (W^T).
// D = Ah Bh^T + Ah Bl^T + Al Bh^T (fp32 accum in registers).
// 256 threads = 8 warps (2m x 4n), warp tile 64x32, mma m16n8k16.
__device__ void gemm_mma_body(
    const __nv_bfloat16* __restrict__ Ahi, const __nv_bfloat16* __restrict__ Alo,
    const __nv_bfloat16* __restrict__ Bhi, const __nv_bfloat16* __restrict__ Blo,
    int m0, int nrow0, float* __restrict__ dst, int ldc, int col0)
{
    extern __shared__ __nv_bfloat16 S[];   // 8 tiles of TS: [buf][Ahi,Alo,Bhi,Blo]

    const int tid  = threadIdx.x;
    const int lane = tid & 31, wid = tid >> 5;
    const int wm = wid & 1, wn = wid >> 1;     // 2 x 4 warp grid
    const int g = lane >> 2, t = lane & 3;

    float acc[4][4][4];
    #pragma unroll
    for (int i = 0; i < 4; i++)
        #pragma unroll
        for (int j = 0; j < 4; j++)
            #pragma unroll
            for (int r = 0; r < 4; r++) acc[i][j][r] = 0.f;

    auto tile_load = [&](const __nv_bfloat16* __restrict__ src, int row0, int k0, int sb) {
        #pragma unroll
        for (int j = 0; j < 2; j++) {
            int f = tid + 256 * j;            // 0..511: 128 rows x 4 uint4
            int row = f >> 2, c4 = f & 3;
            cp_async16(smem_u32(&S[sb + row * TPAD + c4 * 8]),
                       src + (size_t)(row0 + row) * GEMM_K + k0 + c4 * 8);
        }
    };

    // preload slab 0
    tile_load(Ahi, m0, 0, 0);
    tile_load(Alo, m0, 0, TS);
    tile_load(Bhi, nrow0, 0, 2 * TS);
    tile_load(Blo, nrow0, 0, 3 * TS);
    cp_commit();

    for (int it = 0; it < NITG; it++) {
        cp_wait0();
        __syncthreads();
        const int sb = (it & 1) * 4 * TS;
        if (it + 1 < NITG) {
            const int nb = ((it + 1) & 1) * 4 * TS;
            const int k0 = (it + 1) * BKG;
            tile_load(Ahi, m0, k0, nb);
            tile_load(Alo, m0, k0, nb + TS);
            tile_load(Bhi, nrow0, k0, nb + 2 * TS);
            tile_load(Blo, nrow0, k0, nb + 3 * TS);
            cp_commit();
        }
        #pragma unroll
        for (int ks = 0; ks < 2; ks++) {
            const int kc = ks * 16;
            uint32_t ah[4][4], al[4][4], bh[4][2], bl[4][2];
            #pragma unroll
            for (int mt = 0; mt < 4; mt++) {
                int r0 = sb + (wm * 64 + mt * 16 + g) * TPAD + kc + 2 * t;
                ah[mt][0] = *(const uint32_t*)&S[r0];
                ah[mt][1] = *(const uint32_t*)&S[r0 + 8 * TPAD];
                ah[mt][2] = *(const uint32_t*)&S[r0 + 8];
                ah[mt][3] = *(const uint32_t*)&S[r0 + 8 * TPAD + 8];
                al[mt][0] = *(const uint32_t*)&S[r0 + TS];
                al[mt][1] = *(const uint32_t*)&S[r0 + TS + 8 * TPAD];
                al[mt][2] = *(const uint32_t*)&S[r0 + TS + 8];
                al[mt][3] = *(const uint32_t*)&S[r0 + TS + 8 * TPAD + 8];
            }
            #pragma unroll
            for (int nt = 0; nt < 4; nt++) {
                int r0 = sb + 2 * TS + (wn * 32 + nt * 8 + g) * TPAD + kc + 2 * t;
                bh[nt][0] = *(const uint32_t*)&S[r0];
                bh[nt][1] = *(const uint32_t*)&S[r0 + 8];
                bl[nt][0] = *(const uint32_t*)&S[r0 + TS];
                bl[nt][1] = *(const uint32_t*)&S[r0 + TS + 8];
            }
            #pragma unroll
            for (int mt = 0; mt < 4; mt++)
                #pragma unroll
                for (int nt = 0; nt < 4; nt++) {
                    mma_bf16(acc[mt][nt], ah[mt], bh[nt]);
                    mma_bf16(acc[mt][nt], ah[mt], bl[nt]);
                    mma_bf16(acc[mt][nt], al[mt], bh[nt]);
                }
        }
        __syncthreads();
    }

    // epilogue
    #pragma unroll
    for (int mt = 0; mt < 4; mt++) {
        int r = m0 + wm * 64 + mt * 16 + g;
        #pragma unroll
        for (int nt = 0; nt < 4; nt++) {
            int cc = col0 + wn * 32 + nt * 8 + 2 * t;
            *(float2*)&dst[(size_t)r * ldc + cc]       = make_float2(acc[mt][nt][0], acc[mt][nt][1]);
            *(float2*)&dst[(size_t)(r + 8) * ldc + cc] = make_float2(acc[mt][nt][2], acc[mt][nt][3]);
        }
    }
}

#define SMEM_DYN (8 * TS * 2)   // 81920 bytes

// fused Q/K/V/G projection GEMM: grid (48 n-tiles, 32 m-tiles)
__global__ __launch_bounds__(256) void qkvg_tc_kernel(
    const __nv_bfloat16* __restrict__ xhi, const __nv_bfloat16* __restrict__ xlo,
    const __nv_bfloat16* __restrict__ wthi, const __nv_bfloat16* __restrict__ wtlo,
    float* __restrict__ q, float* __restrict__ k,
    float* __restrict__ v, float* __restrict__ g)
{
    const int nt = blockIdx.x;
    const int m0 = blockIdx.y * 128;
    float* dst; int ldc, col0;
    if (nt < 8)       { dst = q; ldc = KD; col0 = nt * 128; }
    else if (nt < 16) { dst = k; ldc = KD; col0 = (nt - 8) * 128; }
    else if (nt < 32) { dst = v; ldc = VD; col0 = (nt - 16) * 128; }
    else              { dst = g; ldc = VD; col0 = (nt - 32) * 128; }
    gemm_mma_body(xhi, xlo, wthi, wtlo, m0, nt * 128, dst, ldc, col0);
}

// output GEMM: out = o @ Wo ; grid (16 n-tiles, 32 m-tiles)
__global__ __launch_bounds__(256) void wo_tc_kernel(
    const __nv_bfloat16* __restrict__ ohi, const __nv_bfloat16* __restrict__ olo,
    const __nv_bfloat16* __restrict__ wohi, const __nv_bfloat16* __restrict__ wolo,
    float* __restrict__ out)
{
    const int nt = blockIdx.x;
    const int m0 = blockIdx.y * 128;
    gemm_mma_body(ohi, olo, wohi, wolo, m0, nt * 128, out, HDIM, nt * 128);
}

// ---------------- gate low-rank: x16 = x @ Wgk1 ----------------
__global__ __launch_bounds__(256) void gk1_kernel(
    const float* __restrict__ x, const float* __restrict__ W, float* __restrict__ out)
{
    const int t = blockIdx.x;
    const float* xr = x + (size_t)t * HDIM;
    float acc[16];
    #pragma unroll
    for (int j = 0; j < 16; j++) acc[j] = 0.f;

    for (int i = threadIdx.x; i < HDIM; i += 256) {
        float xv = xr[i];
        const float* wr = W + (size_t)i * 16;
        #pragma unroll
        for (int j = 0; j < 16; j++) acc[j] = fmaf(xv, wr[j], acc[j]);
    }
    #pragma unroll
    for (int j = 0; j < 16; j++)
        #pragma unroll
        for (int off = 16; off > 0; off >>= 1)
            acc[j] += __shfl_down_sync(0xffffffffu, acc[j], off);

    __shared__ float red[8][16];
    const int warp = threadIdx.x >> 5, lane = threadIdx.x & 31;
    if (lane == 0) {
        #pragma unroll
        for (int j = 0; j < 16; j++) red[warp][j] = acc[j];
    }
    __syncthreads();
    if (threadIdx.x < 16) {
        float s = 0.f;
        #pragma unroll
        for (int w = 0; w < 8; w++) s += red[w][threadIdx.x];
        out[(size_t)t * 16 + threadIdx.x] = s;
    }
}

// ---------------- gk = logsigmoid(x16 @ Wgk2 + b) / 16 ----------------
__global__ __launch_bounds__(256) void gk2_kernel(
    const float* __restrict__ x16, const float* __restrict__ W2,
    const float* __restrict__ bias, float* __restrict__ gk)
{
    const int t = blockIdx.x;
    __shared__ float xs[16];
    if (threadIdx.x < 16) xs[threadIdx.x] = x16[(size_t)t * 16 + threadIdx.x];
    __syncthreads();
    for (int j = threadIdx.x; j < KD; j += 256) {
        float s = bias[j];
        #pragma unroll
        for (int r = 0; r < 16; r++) s = fmaf(xs[r], W2[(size_t)r * KD + j], s);
        float ls = fminf(s, 0.f) - log1pf(expf(-fabsf(s)));   // stable log_sigmoid
        gk[(size_t)t * KD + j] = ls * INV_GN;
    }
}

// ---------------- in-chunk inclusive cumsum of gk (in place) ----------------
__global__ __launch_bounds__(1024) void cumsum_kernel(float* __restrict__ gk)
{
    const int bn = blockIdx.x;
    const int b = bn / NCHUNK, n = bn % NCHUNK;
    const size_t t0 = (size_t)b * SEQ + (size_t)n * CH;
    const int c = threadIdx.x;
    float s = 0.f;
    for (int i = 0; i < CH; i++) {
        size_t idx = (t0 + i) * KD + c;
        s += gk[idx];
        gk[idx] = s;
    }
}

// ---------------- GLA phase 1: C[bhn] = k_dec^T @ v ----------------
__global__ __launch_bounds__(256) void chunk_kv_kernel(
    const float* __restrict__ k, const float* __restrict__ v,
    const float* __restrict__ gc, float* __restrict__ C)
{
    const int bhn = blockIdx.y;
    const int n = bhn % NCHUNK;
    const int bh = bhn / NCHUNK;
    const int h = bh % HNUM, b = bh / HNUM;
    const int dk0 = (blockIdx.x >> 3) * 128;
    const int dv0 = (blockIdx.x & 7) * 64;
    const size_t t0 = (size_t)b * SEQ + (size_t)n * CH;
    const int kc = h * DKH + dk0;
    const int vc = h * DVH + dv0;

    __shared__ __align__(16) float kd[64][128];
    __shared__ __align__(16) float vs[64][64];

    const int tid = threadIdx.x;
    #pragma unroll
    for (int r = 0; r < 8; r++) {
        int f = tid + 256 * r;
        int c = f >> 5;
        int off = (f & 31) << 2;
        size_t rb = (t0 + c) * KD + kc + off;
        size_t lb = (t0 + 63) * KD + kc + off;
        float4 kv = *(const float4*)(k + rb);
        float4 gv = *(const float4*)(gc + rb);
        float4 gl = *(const float4*)(gc + lb);
        float4 o4;
        o4.x = kv.x * expf(gl.x - gv.x);
        o4.y = kv.y * expf(gl.y - gv.y);
        o4.z = kv.z * expf(gl.z - gv.z);
        o4.w = kv.w * expf(gl.w - gv.w);
        *(float4*)&kd[c][off] = o4;
    }
    #pragma unroll
    for (int r = 0; r < 4; r++) {
        int f = tid + 256 * r;
        int c = f >> 4;
        int off = (f & 15) << 2;
        *(float4*)&vs[c][off] = *(const float4*)(v + (t0 + c) * VD + vc + off);
    }
    __syncthreads();

    const int tx = tid & 15, ty = tid >> 4;
    unsigned long long acc[8][2];
    #pragma unroll
    for (int i = 0; i < 8; i++) { acc[i][0] = 0ull; acc[i][1] = 0ull; }

    #pragma unroll 8
    for (int c = 0; c < 64; c++) {
        float4 af0 = *(const float4*)&kd[c][ty * 8];
        float4 af1 = *(const float4*)&kd[c][ty * 8 + 4];
        ulonglong2 bq = *(const ulonglong2*)&vs[c][tx * 4];
        float a[8] = { af0.x, af0.y, af0.z, af0.w, af1.x, af1.y, af1.z, af1.w };
        #pragma unroll
        for (int i = 0; i < 8; i++) {
            unsigned long long av = pack2(a[i]);
            acc[i][0] = fma2(av, bq.x, acc[i][0]);
            acc[i][1] = fma2(av, bq.y, acc[i][1]);
        }
    }

    const size_t cbase = (size_t)bhn * DKH * DVH;
    #pragma unroll
    for (int i = 0; i < 8; i++) {
        float2 p0 = unpack2(acc[i][0]);
        float2 p1 = unpack2(acc[i][1]);
        float* Cp = C + cbase + (size_t)(dk0 + ty * 8 + i) * DVH + dv0 + tx * 4;
        *(float4*)Cp = make_float4(p0.x, p0.y, p1.x, p1.y);
    }
}

// ---------------- GLA scan ----------------
__global__ __launch_bounds__(256) void scan_kernel(
    const float* __restrict__ gc, float* __restrict__ C)
{
    const int bh = blockIdx.y;
    const int h = bh % HNUM, b = bh / HNUM;
    const int dv0 = blockIdx.x * 32;
    const int tid = threadIdx.x;

    __shared__ float Ssm[256 * 32];
    __shared__ float eg[256];

    #pragma unroll
    for (int r = 0; r < 32; r++) Ssm[tid + 256 * r] = 0.f;

    for (int n = 0; n < NCHUNK; n++) {
        const size_t t0 = (size_t)b * SEQ + (size_t)n * CH;
        eg[tid] = expf(gc[(t0 + 63) * KD + h * DKH + tid]);
        __syncthreads();
        const size_t base = (size_t)((bh * NCHUNK) + n) * DKH * DVH;
        #pragma unroll
        for (int r = 0; r < 32; r++) {
            int e = tid + 256 * r;
            int dk = e >> 5;
            int dv = dv0 + (e & 31);
            size_t idx = base + (size_t)dk * DVH + dv;
            float cv = C[idx];
            float s  = Ssm[e];
            C[idx] = s;
            Ssm[e] = fmaf(s, eg[dk], cv);
        }
        __syncthreads();
    }
}

// ---------------- GLA phase 2 ----------------
__global__ __launch_bounds__(256) void gla_out_kernel(
    const float* __restrict__ q, const float* __restrict__ k,
    const float* __restrict__ v, const float* __restrict__ gc,
    const float* __restrict__ C, float* __restrict__ o)
{
    const int bhn = blockIdx.y;
    const int n = bhn % NCHUNK;
    const int bh = bhn / NCHUNK;
    const int h = bh % HNUM, b = bh / HNUM;
    const int dv0 = blockIdx.x * 128;
    const size_t t0 = (size_t)b * SEQ + (size_t)n * CH;
    const int kc = h * DKH;
    const int vc = h * DVH + dv0;
    const int tid = threadIdx.x, tx = tid & 15, ty = tid >> 4;

    __shared__ __align__(16) float pool[64 * 65 + 32 * 64 + 32 * 128];
    float* Asm = pool;
    float* P1  = pool + 64 * 65;
    float* P2  = pool + 64 * 65 + 32 * 64;

    unsigned long long accA[4][2];
    #pragma unroll
    for (int i = 0; i < 4; i++) { accA[i][0] = 0ull; accA[i][1] = 0ull; }

    for (int d0 = 0; d0 < DKH; d0 += 32) {
        #pragma unroll
        for (int r = 0; r < 2; r++) {
            int f = tid + 256 * r;
            int c = f >> 3;
            int off = (f & 7) << 2;
            size_t base = (t0 + c) * KD + kc + d0 + off;
            float4 qv = *(const float4*)(q + base);
            float4 gv = *(const float4*)(gc + base);
            float4 kv = *(const float4*)(k + base);
            P1[(off + 0) * 64 + c] = qv.x * expf(gv.x) * SCALE;
            P1[(off + 1) * 64 + c] = qv.y * expf(gv.y) * SCALE;
            P1[(off + 2) * 64 + c] = qv.z * expf(gv.z) * SCALE;
            P1[(off + 3) * 64 + c] = qv.w * expf(gv.w) * SCALE;
            P2[(off + 0) * 64 + c] = kv.x * expf(-gv.x);
            P2[(off + 1) * 64 + c] = kv.y * expf(-gv.y);
            P2[(off + 2) * 64 + c] = kv.z * expf(-gv.z);
            P2[(off + 3) * 64 + c] = kv.w * expf(-gv.w);
        }
        __syncthreads();
        #pragma unroll
        for (int kk = 0; kk < 32; kk++) {
            float4 a4 = *(const float4*)&P1[kk * 64 + ty * 4];
            ulonglong2 bq = *(const ulonglong2*)&P2[kk * 64 + tx * 4];
            float a[4] = { a4.x, a4.y, a4.z, a4.w };
            #pragma unroll
            for (int i = 0; i < 4; i++) {
                unsigned long long av = pack2(a[i]);
                accA[i][0] = fma2(av, bq.x, accA[i][0]);
                accA[i][1] = fma2(av, bq.y, accA[i][1]);
            }
        }
        __syncthreads();
    }
    #pragma unroll
    for (int i = 0; i < 4; i++) {
        float2 p0 = unpack2(accA[i][0]);
        float2 p1 = unpack2(accA[i][1]);
        float vals[4] = { p0.x, p0.y, p1.x, p1.y };
        int ri = ty * 4 + i;
        #pragma unroll
        for (int j = 0; j < 4; j++) {
            int cj = tx * 4 + j;
            Asm[ri * 65 + cj] = (ri >= cj) ? vals[j] : 0.f;
        }
    }
    __syncthreads();

    unsigned long long acc[4][4];
    #pragma unroll
    for (int i = 0; i < 4; i++)
        #pragma unroll
        for (int j = 0; j < 4; j++) acc[i][j] = 0ull;

    for (int j0 = 0; j0 < 64; j0 += 32) {
        #pragma unroll
        for (int r = 0; r < 4; r++) {
            int f = tid + 256 * r;
            int c = f >> 5;
            int off = (f & 31) << 2;
            *(float4*)&P2[c * 128 + off] =
                *(const float4*)(v + (t0 + j0 + c) * VD + vc + off);
        }
        __syncthreads();
        #pragma unroll
        for (int jj = 0; jj < 32; jj++) {
            ulonglong2 b0 = *(const ulonglong2*)&P2[jj * 128 + tx * 4];
            ulonglong2 b1 = *(const ulonglong2*)&P2[jj * 128 + 64 + tx * 4];
            unsigned long long bv[4] = { b0.x, b0.y, b1.x, b1.y };
            #pragma unroll
            for (int ii = 0; ii < 4; ii++) {
                unsigned long long av = pack2(Asm[(ty * 4 + ii) * 65 + j0 + jj]);
                #pragma unroll
                for (int jp = 0; jp < 4; jp++)
                    acc[ii][jp] = fma2(av, bv[jp], acc[ii][jp]);
            }
        }
        __syncthreads();
    }

    const size_t sb = (size_t)bhn * DKH * DVH;
    for (int d0 = 0; d0 < DKH; d0 += 32) {
        #pragma unroll
        for (int r = 0; r < 2; r++) {
            int f = tid + 256 * r;
            int c = f >> 3;
            int off = (f & 7) << 2;
            size_t base = (t0 + c) * KD + kc + d0 + off;
            float4 qv = *(const float4*)(q + base);
            float4 gv = *(const float4*)(gc + base);
            P1[(off + 0) * 64 + c] = qv.x * expf(gv.x) * SCALE;
            P1[(off + 1) * 64 + c] = qv.y * expf(gv.y) * SCALE;
            P1[(off + 2) * 64 + c] = qv.z * expf(gv.z) * SCALE;
            P1[(off + 3) * 64 + c] = qv.w * expf(gv.w) * SCALE;
        }
        #pragma unroll
        for (int r = 0; r < 4; r++) {
            int f = tid + 256 * r;
            int c = f >> 5;
            int off = (f & 31) << 2;
            *(float4*)&P2[c * 128 + off] =
                *(const float4*)(C + sb + (size_t)(d0 + c) * DVH + dv0 + off);
        }
        __syncthreads();
        #pragma unroll
        for (int kk = 0; kk < 32; kk++) {
            float4 a4 = *(const float4*)&P1[kk * 64 + ty * 4];
            ulonglong2 b0 = *(const ulonglong2*)&P2[kk * 128 + tx * 4];
            ulonglong2 b1 = *(const ulonglong2*)&P2[kk * 128 + 64 + tx * 4];
            unsigned long long bv[4] = { b0.x, b0.y, b1.x, b1.y };
            float a[4] = { a4.x, a4.y, a4.z, a4.w };
            #pragma unroll
            for (int ii = 0; ii < 4; ii++) {
                unsigned long long av = pack2(a[ii]);
                #pragma unroll
                for (int jp = 0; jp < 4; jp++)
                    acc[ii][jp] = fma2(av, bv[jp], acc[ii][jp]);
            }
        }
        __syncthreads();
    }

    #pragma unroll
    for (int ii = 0; ii < 4; ii++) {
        size_t row = t0 + ty * 4 + ii;
        float2 p0 = unpack2(acc[ii][0]);
        float2 p1 = unpack2(acc[ii][1]);
        float2 p2 = unpack2(acc[ii][2]);
        float2 p3 = unpack2(acc[ii][3]);
        float* op = o + row * VD + vc;
        *(float4*)(op + tx * 4)      = make_float4(p0.x, p0.y, p1.x, p1.y);
        *(float4*)(op + 64 + tx * 4) = make_float4(p2.x, p2.y, p3.x, p3.y);
    }
}

// ---------------- rmsnorm * g_norm_weight * silu(g) -> bf16 split ----------------
__global__ __launch_bounds__(256) void post_kernel(
    const float* __restrict__ o, const float* __restrict__ g, const float* __restrict__ w,
    __nv_bfloat16* __restrict__ ohi, __nv_bfloat16* __restrict__ olo)
{
    const int t = blockIdx.x, h = blockIdx.y;
    const size_t base = (size_t)t * VD + (size_t)h * DVH;
    const int tid = threadIdx.x;

    float v0 = o[base + tid];
    float v1 = o[base + tid + 256];
    float ss = v0 * v0 + v1 * v1;
    #pragma unroll
    for (int off = 16; off > 0; off >>= 1)
        ss += __shfl_down_sync(0xffffffffu, ss, off);

    __shared__ float red[8];
    __shared__ float inv_s;
    if ((tid & 31) == 0) red[tid >> 5] = ss;
    __syncthreads();
    if (tid == 0) {
        float s = 0.f;
        #pragma unroll
        for (int wi = 0; wi < 8; wi++) s += red[wi];
        inv_s = rsqrtf(s * (1.f / DVH) + EPS_F);
    }
    __syncthreads();
    const float inv = inv_s;

    float g0 = g[base + tid];
    float g1 = g[base + tid + 256];
    float s0 = g0 / (1.f + expf(-g0));
    float s1 = g1 / (1.f + expf(-g1));
    float r0 = v0 * inv * w[tid]       * s0;
    float r1 = v1 * inv * w[tid + 256] * s1;

    __nv_bfloat16 h0 = __float2bfloat16(r0);
    __nv_bfloat16 h1 = __float2bfloat16(r1);
    ohi[base + tid]       = h0;
    ohi[base + tid + 256] = h1;
    olo[base + tid]       = __float2bfloat16(r0 - __bfloat162float(h0));
    olo[base + tid + 256] = __float2bfloat16(r1 - __bfloat162float(h1));
}

// ---------------- launch ----------------
extern "C" void kernel_launch(void* const* d_in, const int* in_sizes, int n_in,
                              void* d_out, int out_size)
{
    const float* x    = (const float*)d_in[0];
    const float* Wq   = (const float*)d_in[1];
    const float* Wk   = (const float*)d_in[2];
    const float* Wv   = (const float*)d_in[3];
    const float* Wgk1 = (const float*)d_in[4];
    const float* Wgk2 = (const float*)d_in[5];
    const float* bgk2 = (const float*)d_in[6];
    const float* Wg   = (const float*)d_in[7];
    const float* gnw  = (const float*)d_in[8];
    const float* Wo   = (const float*)d_in[9];
    float* out = (float*)d_out;

    float *q, *k, *v, *g, *gk, *o, *x16, *C;
    __nv_bfloat16 *xhi, *xlo, *wthi, *wtlo, *wohi, *wolo, *ohi, *olo;
    cudaGetSymbolAddress((void**)&q,    d_q);
    cudaGetSymbolAddress((void**)&k,    d_k);
    cudaGetSymbolAddress((void**)&v,    d_v);
    cudaGetSymbolAddress((void**)&g,    d_gbuf);
    cudaGetSymbolAddress((void**)&gk,   d_gk);
    cudaGetSymbolAddress((void**)&o,    d_o);
    cudaGetSymbolAddress((void**)&x16,  d_x16);
    cudaGetSymbolAddress((void**)&C,    d_C);
    cudaGetSymbolAddress((void**)&xhi,  d_xhi);
    cudaGetSymbolAddress((void**)&xlo,  d_xlo);
    cudaGetSymbolAddress((void**)&wthi, d_wthi);
    cudaGetSymbolAddress((void**)&wtlo, d_wtlo);
    cudaGetSymbolAddress((void**)&wohi, d_wohi);
    cudaGetSymbolAddress((void**)&wolo, d_wolo);
    cudaGetSymbolAddress((void**)&ohi,  d_ohi);
    cudaGetSymbolAddress((void**)&olo,  d_olo);

    cudaFuncSetAttribute((const void*)qkvg_tc_kernel,
                         cudaFuncAttributeMaxDynamicSharedMemorySize, SMEM_DYN);
    cudaFuncSetAttribute((const void*)wo_tc_kernel,
                         cudaFuncAttributeMaxDynamicSharedMemorySize, SMEM_DYN);

    // bf16 splits
    split_kernel<<<(size_t)TB * HDIM / 1024, 256>>>(x, xhi, xlo);
    tsplit_kernel<<<dim3(KD / 32, GEMM_K / 32), 256>>>(Wq, wthi, wtlo, KD);
    tsplit_kernel<<<dim3(KD / 32, GEMM_K / 32), 256>>>(Wk, wthi + (size_t)KD * GEMM_K, wtlo + (size_t)KD * GEMM_K, KD);
    tsplit_kernel<<<dim3(VD / 32, GEMM_K / 32), 256>>>(Wv, wthi + (size_t)2 * KD * GEMM_K, wtlo + (size_t)2 * KD * GEMM_K, VD);
    tsplit_kernel<<<dim3(VD / 32, GEMM_K / 32), 256>>>(Wg, wthi + (size_t)(2 * KD + VD) * GEMM_K, wtlo + (size_t)(2 * KD + VD) * GEMM_K, VD);
    tsplit_kernel<<<dim3(HDIM / 32, GEMM_K / 32), 256>>>(Wo, wohi, wolo, HDIM);

    // fused projections on HMMA tensor cores
    qkvg_tc_kernel<<<dim3(QKVG_NT, TB / 128), 256, SMEM_DYN>>>(xhi, xlo, wthi, wtlo, q, k, v, g);

    // gate path
    gk1_kernel<<<TB, 256>>>(x, Wgk1, x16);
    gk2_kernel<<<TB, 256>>>(x16, Wgk2, bgk2, gk);
    cumsum_kernel<<<BATCH * NCHUNK, 1024>>>(gk);

    // GLA
    chunk_kv_kernel<<<dim3(16, BATCH * HNUM * NCHUNK), 256>>>(k, v, gk, C);
    scan_kernel<<<dim3(16, BATCH * HNUM), 256>>>(gk, C);
    gla_out_kernel<<<dim3(4, BATCH * HNUM * NCHUNK), 256>>>(q, k, v, gk, C, o);

    // epilogue + output GEMM
    post_kernel<<<dim3(TB, HNUM), 256>>>(o, g, gnw, ohi, olo);
    wo_tc_kernel<<<dim3(HDIM / 128, TB / 128), 256, SMEM_DYN>>>(ohi, olo, wohi, wolo, out);
}

// round 12
// speedup vs baseline: 1.7151x; 1.0201x over previous
#include <cuda_runtime.h>
#include <cuda_bf16.h>
#include <math.h>
#include <stdint.h>

// ---------------- problem constants ----------------
#define BATCH   2
#define SEQ     2048
#define HDIM    2048          // hidden size
#define TB      4096          // BATCH*SEQ tokens
#define HNUM    4
#define DKH     256           // HEAD_K
#define DVH     512           // HEAD_V
#define KD      1024          // HNUM*DKH
#define VD      2048          // HNUM*DVH
#define CH      64            // CHUNK
#define NCHUNK  32            // SEQ/CH
#define SCALE   0.0625f       // DKH^-0.5
#define INV_GN  0.0625f       // 1/GATE_NORMALIZER
#define EPS_F   1e-5f

#define GEMM_K  2048          // K dim for every big GEMM
#define BKG     32            // K per SMEM slab
#define NITG    (GEMM_K / BKG) // 64
#define QKVG_NT 48            // 6144/128 output column tiles
#define TPAD    40            // padded row length in bf16 (20 banks -> conflict-free frags)
#define TS      (128 * TPAD)  // bf16 elems per tile

// ---------------- device scratch (no allocation allowed) ----------------
__device__ float d_q   [(size_t)TB * KD];
__device__ float d_k   [(size_t)TB * KD];
__device__ float d_v   [(size_t)TB * VD];
__device__ float d_gbuf[(size_t)TB * VD];
__device__ float d_gk  [(size_t)TB * KD];
__device__ float d_o   [(size_t)TB * VD];
__device__ float d_x16 [(size_t)TB * 16];
__device__ float d_C   [(size_t)BATCH * HNUM * NCHUNK * DKH * DVH];

// bf16 split buffers for tensor-core GEMMs
__device__ __nv_bfloat16 d_xhi [(size_t)TB * HDIM];
__device__ __nv_bfloat16 d_xlo [(size_t)TB * HDIM];
__device__ __nv_bfloat16 d_wthi[(size_t)(2 * KD + 2 * VD) * GEMM_K]; // [6144][2048]
__device__ __nv_bfloat16 d_wtlo[(size_t)(2 * KD + 2 * VD) * GEMM_K];
__device__ __nv_bfloat16 d_wohi[(size_t)HDIM * GEMM_K];              // [2048][2048]
__device__ __nv_bfloat16 d_wolo[(size_t)HDIM * GEMM_K];
__device__ __nv_bfloat16 d_ohi [(size_t)TB * VD];
__device__ __nv_bfloat16 d_olo [(size_t)TB * VD];

// ---------------- packed f32x2 helpers (GLA kernels) ----------------
__device__ __forceinline__ unsigned long long pack2(float a) {
    unsigned long long r;
    asm("mov.b64 %0, {%1, %1};" : "=l"(r) : "f"(a));
    return r;
}
__device__ __forceinline__ unsigned long long fma2(unsigned long long a,
                                                   unsigned long long b,
                                                   unsigned long long c) {
    unsigned long long d;
    asm("fma.rn.f32x2 %0, %1, %2, %3;" : "=l"(d) : "l"(a), "l"(b), "l"(c));
    return d;
}
__device__ __forceinline__ float2 unpack2(unsigned long long v) {
    float2 r;
    asm("mov.b64 {%0, %1}, %2;" : "=f"(r.x), "=f"(r.y) : "l"(v));
    return r;
}

// ---------------- HMMA / cp.async helpers ----------------
__device__ __forceinline__ void mma_bf16(float* c, const uint32_t* a, const uint32_t* b) {
    asm volatile(
        "mma.sync.aligned.m16n8k16.row.col.f32.bf16.bf16.f32 "
        "{%0,%1,%2,%3}, {%4,%5,%6,%7}, {%8,%9}, {%0,%1,%2,%3};"
        : "+f"(c[0]), "+f"(c[1]), "+f"(c[2]), "+f"(c[3])
        : "r"(a[0]), "r"(a[1]), "r"(a[2]), "r"(a[3]), "r"(b[0]), "r"(b[1]));
}
__device__ __forceinline__ void cp_async16(uint32_t dst, const void* src) {
    asm volatile("cp.async.cg.shared.global [%0], [%1], 16;" :: "r"(dst), "l"(src));
}
__device__ __forceinline__ void cp_commit() {
    asm volatile("cp.async.commit_group;");
}
__device__ __forceinline__ void cp_wait0() {
    asm volatile("cp.async.wait_group 0;" ::: "memory");
}
__device__ __forceinline__ uint32_t smem_u32(const void* p) {
    return (uint32_t)__cvta_generic_to_shared(p);
}

// ---------------- split conversion: fp32 -> (hi, lo) bf16 ----------------
__global__ __launch_bounds__(256) void split_kernel(
    const float* __restrict__ in, __nv_bfloat16* __restrict__ hi,
    __nv_bfloat16* __restrict__ lo)
{
    size_t i = (size_t)blockIdx.x * 256 + threadIdx.x;   // one float4 per thread
    float4 v = ((const float4*)in)[i];
    __nv_bfloat16 h0 = __float2bfloat16(v.x);
    __nv_bfloat16 h1 = __float2bfloat16(v.y);
    __nv_bfloat16 h2 = __float2bfloat16(v.z);
    __nv_bfloat16 h3 = __float2bfloat16(v.w);
    __nv_bfloat16 l0 = __float2bfloat16(v.x - __bfloat162float(h0));
    __nv_bfloat16 l1 = __float2bfloat16(v.y - __bfloat162float(h1));
    __nv_bfloat16 l2 = __float2bfloat16(v.z - __bfloat162float(h2));
    __nv_bfloat16 l3 = __float2bfloat16(v.w - __bfloat162float(h3));
    __nv_bfloat162* hp = (__nv_bfloat162*)hi;
    __nv_bfloat162* lp = (__nv_bfloat162*)lo;
    __nv_bfloat162 a; a.x = h0; a.y = h1;
    __nv_bfloat162 b; b.x = h2; b.y = h3;
    hp[i * 2] = a; hp[i * 2 + 1] = b;
    a.x = l0; a.y = l1; b.x = l2; b.y = l3;
    lp[i * 2] = a; lp[i * 2 + 1] = b;
}

// ---------------- transpose + split: W[K=2048][N] -> Wt_hi/lo [N][2048] ----------------
__global__ __launch_bounds__(256) void tsplit_kernel(
    const float* __restrict__ W, __nv_bfloat16* __restrict__ hiT,
    __nv_bfloat16* __restrict__ loT, int N)
{
    __shared__ float t[32][33];
    const int n0 = blockIdx.x * 32, k0 = blockIdx.y * 32;
    const int tx = threadIdx.x & 31, ty = threadIdx.x >> 5;   // 32 x 8
    #pragma unroll
    for (int j = 0; j < 4; j++)
        t[ty + 8 * j][tx] = W[(size_t)(k0 + ty + 8 * j) * N + n0 + tx];
    __syncthreads();
    #pragma unroll
    for (int j = 0; j < 4; j++) {
        float v = t[tx][ty + 8 * j];
        __nv_bfloat16 h = __float2bfloat16(v);
        size_t idx = (size_t)(n0 + ty + 8 * j) * GEMM_K + k0 + tx;
        hiT[idx] = h;
        loT[idx] = __float2bfloat16(v - __bfloat162float(h));
    }
}

// ---------------- HMMA GEMM: 128x128 output tile, K=2048, split bf16 ----------------
__device__ void gemm_mma_body(
    const __nv_bfloat16* __restrict__ Ahi, const __nv_bfloat16* __restrict__ Alo,
    const __nv_bfloat16* __restrict__ Bhi, const __nv_bfloat16* __restrict__ Blo,
    int m0, int nrow0, float* __restrict__ dst, int ldc, int col0)
{
    extern __shared__ __nv_bfloat16 S[];   // 8 tiles of TS: [buf][Ahi,Alo,Bhi,Blo]

    const int tid  = threadIdx.x;
    const int lane = tid & 31, wid = tid >> 5;
    const int wm = wid & 1, wn = wid >> 1;     // 2 x 4 warp grid
    const int g = lane >> 2, t = lane & 3;

    float acc[4][4][4];
    #pragma unroll
    for (int i = 0; i < 4; i++)
        #pragma unroll
        for (int j = 0; j < 4; j++)
            #pragma unroll
            for (int r = 0; r < 4; r++) acc[i][j][r] = 0.f;

    auto tile_load = [&](const __nv_bfloat16* __restrict__ src, int row0, int k0, int sb) {
        #pragma unroll
        for (int j = 0; j < 2; j++) {
            int f = tid + 256 * j;            // 0..511: 128 rows x 4 uint4
            int row = f >> 2, c4 = f & 3;
            cp_async16(smem_u32(&S[sb + row * TPAD + c4 * 8]),
                       src + (size_t)(row0 + row) * GEMM_K + k0 + c4 * 8);
        }
    };

    // preload slab 0
    tile_load(Ahi, m0, 0, 0);
    tile_load(Alo, m0, 0, TS);
    tile_load(Bhi, nrow0, 0, 2 * TS);
    tile_load(Blo, nrow0, 0, 3 * TS);
    cp_commit();

    for (int it = 0; it < NITG; it++) {
        cp_wait0();
        __syncthreads();
        const int sb = (it & 1) * 4 * TS;
        if (it + 1 < NITG) {
            const int nb = ((it + 1) & 1) * 4 * TS;
            const int k0 = (it + 1) * BKG;
            tile_load(Ahi, m0, k0, nb);
            tile_load(Alo, m0, k0, nb + TS);
            tile_load(Bhi, nrow0, k0, nb + 2 * TS);
            tile_load(Blo, nrow0, k0, nb + 3 * TS);
            cp_commit();
        }
        #pragma unroll
        for (int ks = 0; ks < 2; ks++) {
            const int kc = ks * 16;
            uint32_t ah[4][4], al[4][4], bh[4][2], bl[4][2];
            #pragma unroll
            for (int mt = 0; mt < 4; mt++) {
                int r0 = sb + (wm * 64 + mt * 16 + g) * TPAD + kc + 2 * t;
                ah[mt][0] = *(const uint32_t*)&S[r0];
                ah[mt][1] = *(const uint32_t*)&S[r0 + 8 * TPAD];
                ah[mt][2] = *(const uint32_t*)&S[r0 + 8];
                ah[mt][3] = *(const uint32_t*)&S[r0 + 8 * TPAD + 8];
                al[mt][0] = *(const uint32_t*)&S[r0 + TS];
                al[mt][1] = *(const uint32_t*)&S[r0 + TS + 8 * TPAD];
                al[mt][2] = *(const uint32_t*)&S[r0 + TS + 8];
                al[mt][3] = *(const uint32_t*)&S[r0 + TS + 8 * TPAD + 8];
            }
            #pragma unroll
            for (int nt = 0; nt < 4; nt++) {
                int r0 = sb + 2 * TS + (wn * 32 + nt * 8 + g) * TPAD + kc + 2 * t;
                bh[nt][0] = *(const uint32_t*)&S[r0];
                bh[nt][1] = *(const uint32_t*)&S[r0 + 8];
                bl[nt][0] = *(const uint32_t*)&S[r0 + TS];
                bl[nt][1] = *(const uint32_t*)&S[r0 + TS + 8];
            }
            #pragma unroll
            for (int mt = 0; mt < 4; mt++)
                #pragma unroll
                for (int nt = 0; nt < 4; nt++) {
                    mma_bf16(acc[mt][nt], ah[mt], bh[nt]);
                    mma_bf16(acc[mt][nt], ah[mt], bl[nt]);
                    mma_bf16(acc[mt][nt], al[mt], bh[nt]);
                }
        }
        __syncthreads();
    }

    // epilogue
    #pragma unroll
    for (int mt = 0; mt < 4; mt++) {
        int r = m0 + wm * 64 + mt * 16 + g;
        #pragma unroll
        for (int nt = 0; nt < 4; nt++) {
            int cc = col0 + wn * 32 + nt * 8 + 2 * t;
            *(float2*)&dst[(size_t)r * ldc + cc]       = make_float2(acc[mt][nt][0], acc[mt][nt][1]);
            *(float2*)&dst[(size_t)(r + 8) * ldc + cc] = make_float2(acc[mt][nt][2], acc[mt][nt][3]);
        }
    }
}

#define SMEM_DYN (8 * TS * 2)   // 81920 bytes

// fused Q/K/V/G projection GEMM: grid (48 n-tiles, 32 m-tiles)
__global__ __launch_bounds__(256) void qkvg_tc_kernel(
    const __nv_bfloat16* __restrict__ xhi, const __nv_bfloat16* __restrict__ xlo,
    const __nv_bfloat16* __restrict__ wthi, const __nv_bfloat16* __restrict__ wtlo,
    float* __restrict__ q, float* __restrict__ k,
    float* __restrict__ v, float* __restrict__ g)
{
    const int nt = blockIdx.x;
    const int m0 = blockIdx.y * 128;
    float* dst; int ldc, col0;
    if (nt < 8)       { dst = q; ldc = KD; col0 = nt * 128; }
    else if (nt < 16) { dst = k; ldc = KD; col0 = (nt - 8) * 128; }
    else if (nt < 32) { dst = v; ldc = VD; col0 = (nt - 16) * 128; }
    else              { dst = g; ldc = VD; col0 = (nt - 32) * 128; }
    gemm_mma_body(xhi, xlo, wthi, wtlo, m0, nt * 128, dst, ldc, col0);
}

// output GEMM: out = o @ Wo ; grid (16 n-tiles, 32 m-tiles)
__global__ __launch_bounds__(256) void wo_tc_kernel(
    const __nv_bfloat16* __restrict__ ohi, const __nv_bfloat16* __restrict__ olo,
    const __nv_bfloat16* __restrict__ wohi, const __nv_bfloat16* __restrict__ wolo,
    float* __restrict__ out)
{
    const int nt = blockIdx.x;
    const int m0 = blockIdx.y * 128;
    gemm_mma_body(ohi, olo, wohi, wolo, m0, nt * 128, out, HDIM, nt * 128);
}

// ---------------- gate low-rank: x16 = x @ Wgk1 ----------------
__global__ __launch_bounds__(256) void gk1_kernel(
    const float* __restrict__ x, const float* __restrict__ W, float* __restrict__ out)
{
    const int t = blockIdx.x;
    const float* xr = x + (size_t)t * HDIM;
    float acc[16];
    #pragma unroll
    for (int j = 0; j < 16; j++) acc[j] = 0.f;

    for (int i = threadIdx.x; i < HDIM; i += 256) {
        float xv = xr[i];
        const float* wr = W + (size_t)i * 16;
        #pragma unroll
        for (int j = 0; j < 16; j++) acc[j] = fmaf(xv, wr[j], acc[j]);
    }
    #pragma unroll
    for (int j = 0; j < 16; j++)
        #pragma unroll
        for (int off = 16; off > 0; off >>= 1)
            acc[j] += __shfl_down_sync(0xffffffffu, acc[j], off);

    __shared__ float red[8][16];
    const int warp = threadIdx.x >> 5, lane = threadIdx.x & 31;
    if (lane == 0) {
        #pragma unroll
        for (int j = 0; j < 16; j++) red[warp][j] = acc[j];
    }
    __syncthreads();
    if (threadIdx.x < 16) {
        float s = 0.f;
        #pragma unroll
        for (int w = 0; w < 8; w++) s += red[w][threadIdx.x];
        out[(size_t)t * 16 + threadIdx.x] = s;
    }
}

// ---------------- gk = logsigmoid(x16 @ Wgk2 + b) / 16 ----------------
__global__ __launch_bounds__(256) void gk2_kernel(
    const float* __restrict__ x16, const float* __restrict__ W2,
    const float* __restrict__ bias, float* __restrict__ gk)
{
    const int t = blockIdx.x;
    __shared__ float xs[16];
    if (threadIdx.x < 16) xs[threadIdx.x] = x16[(size_t)t * 16 + threadIdx.x];
    __syncthreads();
    for (int j = threadIdx.x; j < KD; j += 256) {
        float s = bias[j];
        #pragma unroll
        for (int r = 0; r < 16; r++) s = fmaf(xs[r], W2[(size_t)r * KD + j], s);
        float ls = fminf(s, 0.f) - log1pf(expf(-fabsf(s)));   // stable log_sigmoid
        gk[(size_t)t * KD + j] = ls * INV_GN;
    }
}

// ---------------- in-chunk inclusive cumsum of gk (in place) ----------------
__global__ __launch_bounds__(1024) void cumsum_kernel(float* __restrict__ gk)
{
    const int bn = blockIdx.x;
    const int b = bn / NCHUNK, n = bn % NCHUNK;
    const size_t t0 = (size_t)b * SEQ + (size_t)n * CH;
    const int c = threadIdx.x;
    float s = 0.f;
    for (int i = 0; i < CH; i++) {
        size_t idx = (t0 + i) * KD + c;
        s += gk[idx];
        gk[idx] = s;
    }
}

// ---------------- prep: q <- q*exp(gc)*SCALE, k <- k*exp(-gc) (in place) ----------------
// Hoists ~84M expf out of chunk_kv/gla_out into one 8.4M-exp pass.
__global__ __launch_bounds__(256) void prep_kernel(
    float* __restrict__ q, float* __restrict__ k, const float* __restrict__ gc)
{
    size_t i = (size_t)blockIdx.x * 256 + threadIdx.x;   // one float4 per thread
    float4 qv = ((const float4*)q)[i];
    float4 kv = ((const float4*)k)[i];
    float4 gv = ((const float4*)gc)[i];
    float e0 = expf(gv.x), e1 = expf(gv.y), e2 = expf(gv.z), e3 = expf(gv.w);
    qv.x *= e0 * SCALE; qv.y *= e1 * SCALE; qv.z *= e2 * SCALE; qv.w *= e3 * SCALE;
    kv.x /= e0; kv.y /= e1; kv.z /= e2; kv.w /= e3;
    ((float4*)q)[i] = qv;
    ((float4*)k)[i] = kv;
}

// ---------------- GLA phase 1: C[bhn] = k_dec^T @ v  (k pre-gated; per-col exp(g_last)) ----
__global__ __launch_bounds__(256) void chunk_kv_kernel(
    const float* __restrict__ k, const float* __restrict__ v,
    const float* __restrict__ gc, float* __restrict__ C)
{
    const int bhn = blockIdx.y;
    const int n = bhn % NCHUNK;
    const int bh = bhn / NCHUNK;
    const int h = bh % HNUM, b = bh / HNUM;
    const int dk0 = (blockIdx.x >> 3) * 128;
    const int dv0 = (blockIdx.x & 7) * 64;
    const size_t t0 = (size_t)b * SEQ + (size_t)n * CH;
    const int kc = h * DKH + dk0;
    const int vc = h * DVH + dv0;

    __shared__ __align__(16) float kd[64][128];
    __shared__ __align__(16) float vs[64][64];
    __shared__ float egl[128];

    const int tid = threadIdx.x;
    if (tid < 128) egl[tid] = expf(gc[(t0 + 63) * KD + kc + tid]);
    __syncthreads();

    // kdec = (k*exp(-g)) * exp(g_last)   [k already pre-gated by prep]
    #pragma unroll
    for (int r = 0; r < 8; r++) {
        int f = tid + 256 * r;
        int c = f >> 5;
        int off = (f & 31) << 2;
        float4 kv = *(const float4*)(k + (t0 + c) * KD + kc + off);
        float4 o4;
        o4.x = kv.x * egl[off + 0];
        o4.y = kv.y * egl[off + 1];
        o4.z = kv.z * egl[off + 2];
        o4.w = kv.w * egl[off + 3];
        *(float4*)&kd[c][off] = o4;
    }
    #pragma unroll
    for (int r = 0; r < 4; r++) {
        int f = tid + 256 * r;
        int c = f >> 4;
        int off = (f & 15) << 2;
        *(float4*)&vs[c][off] = *(const float4*)(v + (t0 + c) * VD + vc + off);
    }
    __syncthreads();

    const int tx = tid & 15, ty = tid >> 4;
    unsigned long long acc[8][2];
    #pragma unroll
    for (int i = 0; i < 8; i++) { acc[i][0] = 0ull; acc[i][1] = 0ull; }

    #pragma unroll 8
    for (int c = 0; c < 64; c++) {
        float4 af0 = *(const float4*)&kd[c][ty * 8];
        float4 af1 = *(const float4*)&kd[c][ty * 8 + 4];
        ulonglong2 bq = *(const ulonglong2*)&vs[c][tx * 4];
        float a[8] = { af0.x, af0.y, af0.z, af0.w, af1.x, af1.y, af1.z, af1.w };
        #pragma unroll
        for (int i = 0; i < 8; i++) {
            unsigned long long av = pack2(a[i]);
            acc[i][0] = fma2(av, bq.x, acc[i][0]);
            acc[i][1] = fma2(av, bq.y, acc[i][1]);
        }
    }

    const size_t cbase = (size_t)bhn * DKH * DVH;
    #pragma unroll
    for (int i = 0; i < 8; i++) {
        float2 p0 = unpack2(acc[i][0]);
        float2 p1 = unpack2(acc[i][1]);
        float* Cp = C + cbase + (size_t)(dk0 + ty * 8 + i) * DVH + dv0 + tx * 4;
        *(float4*)Cp = make_float4(p0.x, p0.y, p1.x, p1.y);
    }
}

// ---------------- GLA scan ----------------
__global__ __launch_bounds__(256) void scan_kernel(
    const float* __restrict__ gc, float* __restrict__ C)
{
    const int bh = blockIdx.y;
    const int h = bh % HNUM, b = bh / HNUM;
    const int dv0 = blockIdx.x * 32;
    const int tid = threadIdx.x;

    __shared__ float Ssm[256 * 32];
    __shared__ float eg[256];

    #pragma unroll
    for (int r = 0; r < 32; r++) Ssm[tid + 256 * r] = 0.f;

    for (int n = 0; n < NCHUNK; n++) {
        const size_t t0 = (size_t)b * SEQ + (size_t)n * CH;
        eg[tid] = expf(gc[(t0 + 63) * KD + h * DKH + tid]);
        __syncthreads();
        const size_t base = (size_t)((bh * NCHUNK) + n) * DKH * DVH;
        #pragma unroll
        for (int r = 0; r < 32; r++) {
            int e = tid + 256 * r;
            int dk = e >> 5;
            int dv = dv0 + (e & 31);
            size_t idx = base + (size_t)dk * DVH + dv;
            float cv = C[idx];
            float s  = Ssm[e];
            C[idx] = s;
            Ssm[e] = fmaf(s, eg[dk], cv);
        }
        __syncthreads();
    }
}

// ---------------- GLA phase 2 (q,k pre-gated: slab fills are plain copies) ----------------
__global__ __launch_bounds__(256) void gla_out_kernel(
    const float* __restrict__ q, const float* __restrict__ k,
    const float* __restrict__ v,
    const float* __restrict__ C, float* __restrict__ o)
{
    const int bhn = blockIdx.y;
    const int n = bhn % NCHUNK;
    const int bh = bhn / NCHUNK;
    const int h = bh % HNUM, b = bh / HNUM;
    const int dv0 = blockIdx.x * 128;
    const size_t t0 = (size_t)b * SEQ + (size_t)n * CH;
    const int kc = h * DKH;
    const int vc = h * DVH + dv0;
    const int tid = threadIdx.x, tx = tid & 15, ty = tid >> 4;

    __shared__ __align__(16) float pool[64 * 65 + 32 * 64 + 32 * 128];
    float* Asm = pool;
    float* P1  = pool + 64 * 65;
    float* P2  = pool + 64 * 65 + 32 * 64;

    unsigned long long accA[4][2];
    #pragma unroll
    for (int i = 0; i < 4; i++) { accA[i][0] = 0ull; accA[i][1] = 0ull; }

    for (int d0 = 0; d0 < DKH; d0 += 32) {
        #pragma unroll
        for (int r = 0; r < 2; r++) {
            int f = tid + 256 * r;
            int c = f >> 3;
            int off = (f & 7) << 2;
            size_t base = (t0 + c) * KD + kc + d0 + off;
            float4 qv = *(const float4*)(q + base);
            float4 kv = *(const float4*)(k + base);
            P1[(off + 0) * 64 + c] = qv.x;
            P1[(off + 1) * 64 + c] = qv.y;
            P1[(off + 2) * 64 + c] = qv.z;
            P1[(off + 3) * 64 + c] = qv.w;
            P2[(off + 0) * 64 + c] = kv.x;
            P2[(off + 1) * 64 + c] = kv.y;
            P2[(off + 2) * 64 + c] = kv.z;
            P2[(off + 3) * 64 + c] = kv.w;
        }
        __syncthreads();
        #pragma unroll
        for (int kk = 0; kk < 32; kk++) {
            float4 a4 = *(const float4*)&P1[kk * 64 + ty * 4];
            ulonglong2 bq = *(const ulonglong2*)&P2[kk * 64 + tx * 4];
            float a[4] = { a4.x, a4.y, a4.z, a4.w };
            #pragma unroll
            for (int i = 0; i < 4; i++) {
                unsigned long long av = pack2(a[i]);
                accA[i][0] = fma2(av, bq.x, accA[i][0]);
                accA[i][1] = fma2(av, bq.y, accA[i][1]);
            }
        }
        __syncthreads();
    }
    #pragma unroll
    for (int i = 0; i < 4; i++) {
        float2 p0 = unpack2(accA[i][0]);
        float2 p1 = unpack2(accA[i][1]);
        float vals[4] = { p0.x, p0.y, p1.x, p1.y };
        int ri = ty * 4 + i;
        #pragma unroll
        for (int j = 0; j < 4; j++) {
            int cj = tx * 4 + j;
            Asm[ri * 65 + cj] = (ri >= cj) ? vals[j] : 0.f;
        }
    }
    __syncthreads();

    unsigned long long acc[4][4];
    #pragma unroll
    for (int i = 0; i < 4; i++)
        #pragma unroll
        for (int j = 0; j < 4; j++) acc[i][j] = 0ull;

    for (int j0 = 0; j0 < 64; j0 += 32) {
        #pragma unroll
        for (int r = 0; r < 4; r++) {
            int f = tid + 256 * r;
            int c = f >> 5;
            int off = (f & 31) << 2;
            *(float4*)&P2[c * 128 + off] =
                *(const float4*)(v + (t0 + j0 + c) * VD + vc + off);
        }
        __syncthreads();
        #pragma unroll
        for (int jj = 0; jj < 32; jj++) {
            ulonglong2 b0 = *(const ulonglong2*)&P2[jj * 128 + tx * 4];
            ulonglong2 b1 = *(const ulonglong2*)&P2[jj * 128 + 64 + tx * 4];
            unsigned long long bv[4] = { b0.x, b0.y, b1.x, b1.y };
            #pragma unroll
            for (int ii = 0; ii < 4; ii++) {
                unsigned long long av = pack2(Asm[(ty * 4 + ii) * 65 + j0 + jj]);
                #pragma unroll
                for (int jp = 0; jp < 4; jp++)
                    acc[ii][jp] = fma2(av, bv[jp], acc[ii][jp]);
            }
        }
        __syncthreads();
    }

    const size_t sb = (size_t)bhn * DKH * DVH;
    for (int d0 = 0; d0 < DKH; d0 += 32) {
        #pragma unroll
        for (int r = 0; r < 2; r++) {
            int f = tid + 256 * r;
            int c = f >> 3;
            int off = (f & 7) << 2;
            float4 qv = *(const float4*)(q + (t0 + c) * KD + kc + d0 + off);
            P1[(off + 0) * 64 + c] = qv.x;
            P1[(off + 1) * 64 + c] = qv.y;
            P1[(off + 2) * 64 + c] = qv.z;
            P1[(off + 3) * 64 + c] = qv.w;
        }
        #pragma unroll
        for (int r = 0; r < 4; r++) {
            int f = tid + 256 * r;
            int c = f >> 5;
            int off = (f & 31) << 2;
            *(float4*)&P2[c * 128 + off] =
                *(const float4*)(C + sb + (size_t)(d0 + c) * DVH + dv0 + off);
        }
        __syncthreads();
        #pragma unroll
        for (int kk = 0; kk < 32; kk++) {
            float4 a4 = *(const float4*)&P1[kk * 64 + ty * 4];
            ulonglong2 b0 = *(const ulonglong2*)&P2[kk * 128 + tx * 4];
            ulonglong2 b1 = *(const ulonglong2*)&P2[kk * 128 + 64 + tx * 4];
            unsigned long long bv[4] = { b0.x, b0.y, b1.x, b1.y };
            float a[4] = { a4.x, a4.y, a4.z, a4.w };
            #pragma unroll
            for (int ii = 0; ii < 4; ii++) {
                unsigned long long av = pack2(a[ii]);
                #pragma unroll
                for (int jp = 0; jp < 4; jp++)
                    acc[ii][jp] = fma2(av, bv[jp], acc[ii][jp]);
            }
        }
        __syncthreads();
    }

    #pragma unroll
    for (int ii = 0; ii < 4; ii++) {
        size_t row = t0 + ty * 4 + ii;
        float2 p0 = unpack2(acc[ii][0]);
        float2 p1 = unpack2(acc[ii][1]);
        float2 p2 = unpack2(acc[ii][2]);
        float2 p3 = unpack2(acc[ii][3]);
        float* op = o + row * VD + vc;
        *(float4*)(op + tx * 4)      = make_float4(p0.x, p0.y, p1.x, p1.y);
        *(float4*)(op + 64 + tx * 4) = make_float4(p2.x, p2.y, p3.x, p3.y);
    }
}

// ---------------- rmsnorm * g_norm_weight * silu(g) -> bf16 split ----------------
__global__ __launch_bounds__(256) void post_kernel(
    const float* __restrict__ o, const float* __restrict__ g, const float* __restrict__ w,
    __nv_bfloat16* __restrict__ ohi, __nv_bfloat16* __restrict__ olo)
{
    const int t = blockIdx.x, h = blockIdx.y;
    const size_t base = (size_t)t * VD + (size_t)h * DVH;
    const int tid = threadIdx.x;

    float v0 = o[base + tid];
    float v1 = o[base + tid + 256];
    float ss = v0 * v0 + v1 * v1;
    #pragma unroll
    for (int off = 16; off > 0; off >>= 1)
        ss += __shfl_down_sync(0xffffffffu, ss, off);

    __shared__ float red[8];
    __shared__ float inv_s;
    if ((tid & 31) == 0) red[tid >> 5] = ss;
    __syncthreads();
    if (tid == 0) {
        float s = 0.f;
        #pragma unroll
        for (int wi = 0; wi < 8; wi++) s += red[wi];
        inv_s = rsqrtf(s * (1.f / DVH) + EPS_F);
    }
    __syncthreads();
    const float inv = inv_s;

    float g0 = g[base + tid];
    float g1 = g[base + tid + 256];
    float s0 = g0 / (1.f + expf(-g0));
    float s1 = g1 / (1.f + expf(-g1));
    float r0 = v0 * inv * w[tid]       * s0;
    float r1 = v1 * inv * w[tid + 256] * s1;

    __nv_bfloat16 h0 = __float2bfloat16(r0);
    __nv_bfloat16 h1 = __float2bfloat16(r1);
    ohi[base + tid]       = h0;
    ohi[base + tid + 256] = h1;
    olo[base + tid]       = __float2bfloat16(r0 - __bfloat162float(h0));
    olo[base + tid + 256] = __float2bfloat16(r1 - __bfloat162float(h1));
}

// ---------------- launch ----------------
extern "C" void kernel_launch(void* const* d_in, const int* in_sizes, int n_in,
                              void* d_out, int out_size)
{
    const float* x    = (const float*)d_in[0];
    const float* Wq   = (const float*)d_in[1];
    const float* Wk   = (const float*)d_in[2];
    const float* Wv   = (const float*)d_in[3];
    const float* Wgk1 = (const float*)d_in[4];
    const float* Wgk2 = (const float*)d_in[5];
    const float* bgk2 = (const float*)d_in[6];
    const float* Wg   = (const float*)d_in[7];
    const float* gnw  = (const float*)d_in[8];
    const float* Wo   = (const float*)d_in[9];
    float* out = (float*)d_out;

    float *q, *k, *v, *g, *gk, *o, *x16, *C;
    __nv_bfloat16 *xhi, *xlo, *wthi, *wtlo, *wohi, *wolo, *ohi, *olo;
    cudaGetSymbolAddress((void**)&q,    d_q);
    cudaGetSymbolAddress((void**)&k,    d_k);
    cudaGetSymbolAddress((void**)&v,    d_v);
    cudaGetSymbolAddress((void**)&g,    d_gbuf);
    cudaGetSymbolAddress((void**)&gk,   d_gk);
    cudaGetSymbolAddress((void**)&o,    d_o);
    cudaGetSymbolAddress((void**)&x16,  d_x16);
    cudaGetSymbolAddress((void**)&C,    d_C);
    cudaGetSymbolAddress((void**)&xhi,  d_xhi);
    cudaGetSymbolAddress((void**)&xlo,  d_xlo);
    cudaGetSymbolAddress((void**)&wthi, d_wthi);
    cudaGetSymbolAddress((void**)&wtlo, d_wtlo);
    cudaGetSymbolAddress((void**)&wohi, d_wohi);
    cudaGetSymbolAddress((void**)&wolo, d_wolo);
    cudaGetSymbolAddress((void**)&ohi,  d_ohi);
    cudaGetSymbolAddress((void**)&olo,  d_olo);

    cudaFuncSetAttribute((const void*)qkvg_tc_kernel,
                         cudaFuncAttributeMaxDynamicSharedMemorySize, SMEM_DYN);
    cudaFuncSetAttribute((const void*)wo_tc_kernel,
                         cudaFuncAttributeMaxDynamicSharedMemorySize, SMEM_DYN);

    // bf16 splits
    split_kernel<<<(size_t)TB * HDIM / 1024, 256>>>(x, xhi, xlo);
    tsplit_kernel<<<dim3(KD / 32, GEMM_K / 32), 256>>>(Wq, wthi, wtlo, KD);
    tsplit_kernel<<<dim3(KD / 32, GEMM_K / 32), 256>>>(Wk, wthi + (size_t)KD * GEMM_K, wtlo + (size_t)KD * GEMM_K, KD);
    tsplit_kernel<<<dim3(VD / 32, GEMM_K / 32), 256>>>(Wv, wthi + (size_t)2 * KD * GEMM_K, wtlo + (size_t)2 * KD * GEMM_K, VD);
    tsplit_kernel<<<dim3(VD / 32, GEMM_K / 32), 256>>>(Wg, wthi + (size_t)(2 * KD + VD) * GEMM_K, wtlo + (size_t)(2 * KD + VD) * GEMM_K, VD);
    tsplit_kernel<<<dim3(HDIM / 32, GEMM_K / 32), 256>>>(Wo, wohi, wolo, HDIM);

    // fused projections on HMMA tensor cores
    qkvg_tc_kernel<<<dim3(QKVG_NT, TB / 128), 256, SMEM_DYN>>>(xhi, xlo, wthi, wtlo, q, k, v, g);

    // gate path
    gk1_kernel<<<TB, 256>>>(x, Wgk1, x16);
    gk2_kernel<<<TB, 256>>>(x16, Wgk2, bgk2, gk);
    cumsum_kernel<<<BATCH * NCHUNK, 1024>>>(gk);

    // pre-gate q,k (hoists expf out of the GLA hot loops)
    prep_kernel<<<(size_t)TB * KD / 1024, 256>>>(q, k, gk);

    // GLA
    chunk_kv_kernel<<<dim3(16, BATCH * HNUM * NCHUNK), 256>>>(k, v, gk, C);
    scan_kernel<<<dim3(16, BATCH * HNUM), 256>>>(gk, C);
    gla_out_kernel<<<dim3(4, BATCH * HNUM * NCHUNK), 256>>>(q, k, v, C, o);

    // epilogue + output GEMM
    post_kernel<<<dim3(TB, HNUM), 256>>>(o, g, gnw, ohi, olo);
    wo_tc_kernel<<<dim3(HDIM / 128, TB / 128), 256, SMEM_DYN>>>(ohi, olo, wohi, wolo, out);
}

// round 13
// speedup vs baseline: 1.8050x; 1.0524x over previous
#include <cuda_runtime.h>
#include <cuda_bf16.h>
#include <math.h>
#include <stdint.h>

// ---------------- problem constants ----------------
#define BATCH   2
#define SEQ     2048
#define HDIM    2048          // hidden size
#define TB      4096          // BATCH*SEQ tokens
#define HNUM    4
#define DKH     256           // HEAD_K
#define DVH     512           // HEAD_V
#define KD      1024          // HNUM*DKH
#define VD      2048          // HNUM*DVH
#define CH      64            // CHUNK
#define NCHUNK  32            // SEQ/CH
#define SCALE   0.0625f       // DKH^-0.5
#define INV_GN  0.0625f       // 1/GATE_NORMALIZER
#define EPS_F   1e-5f

#define GEMM_K  2048          // K dim for every big GEMM
#define BKG     32            // K per SMEM slab
#define NITG    (GEMM_K / BKG) // 64
#define QKVG_NT 48            // 6144/128 output column tiles
#define TPAD    40            // padded row length in bf16 (20 banks -> conflict-free frags + LDSM)
#define TS      (128 * TPAD)  // bf16 elems per tile

// ---------------- device scratch (no allocation allowed) ----------------
__device__ float d_q   [(size_t)TB * KD];
__device__ float d_k   [(size_t)TB * KD];
__device__ float d_v   [(size_t)TB * VD];
__device__ float d_gbuf[(size_t)TB * VD];
__device__ float d_gk  [(size_t)TB * KD];
__device__ float d_o   [(size_t)TB * VD];
__device__ float d_x16 [(size_t)TB * 16];
__device__ float d_C   [(size_t)BATCH * HNUM * NCHUNK * DKH * DVH];

// bf16 split buffers for tensor-core GEMMs
__device__ __nv_bfloat16 d_xhi [(size_t)TB * HDIM];
__device__ __nv_bfloat16 d_xlo [(size_t)TB * HDIM];
__device__ __nv_bfloat16 d_wthi[(size_t)(2 * KD + 2 * VD) * GEMM_K]; // [6144][2048]
__device__ __nv_bfloat16 d_wtlo[(size_t)(2 * KD + 2 * VD) * GEMM_K];
__device__ __nv_bfloat16 d_wohi[(size_t)HDIM * GEMM_K];              // [2048][2048]
__device__ __nv_bfloat16 d_wolo[(size_t)HDIM * GEMM_K];
__device__ __nv_bfloat16 d_ohi [(size_t)TB * VD];
__device__ __nv_bfloat16 d_olo [(size_t)TB * VD];

// ---------------- packed f32x2 helpers (GLA kernels) ----------------
__device__ __forceinline__ unsigned long long pack2(float a) {
    unsigned long long r;
    asm("mov.b64 %0, {%1, %1};" : "=l"(r) : "f"(a));
    return r;
}
__device__ __forceinline__ unsigned long long fma2(unsigned long long a,
                                                   unsigned long long b,
                                                   unsigned long long c) {
    unsigned long long d;
    asm("fma.rn.f32x2 %0, %1, %2, %3;" : "=l"(d) : "l"(a), "l"(b), "l"(c));
    return d;
}
__device__ __forceinline__ float2 unpack2(unsigned long long v) {
    float2 r;
    asm("mov.b64 {%0, %1}, %2;" : "=f"(r.x), "=f"(r.y) : "l"(v));
    return r;
}

// ---------------- HMMA / cp.async / ldmatrix helpers ----------------
__device__ __forceinline__ void mma_bf16(float* c, const uint32_t* a, const uint32_t* b) {
    asm volatile(
        "mma.sync.aligned.m16n8k16.row.col.f32.bf16.bf16.f32 "
        "{%0,%1,%2,%3}, {%4,%5,%6,%7}, {%8,%9}, {%0,%1,%2,%3};"
        : "+f"(c[0]), "+f"(c[1]), "+f"(c[2]), "+f"(c[3])
        : "r"(a[0]), "r"(a[1]), "r"(a[2]), "r"(a[3]), "r"(b[0]), "r"(b[1]));
}
__device__ __forceinline__ void ldsm_x4(uint32_t* r, uint32_t addr) {
    asm volatile("ldmatrix.sync.aligned.m8n8.x4.shared.b16 {%0,%1,%2,%3}, [%4];"
        : "=r"(r[0]), "=r"(r[1]), "=r"(r[2]), "=r"(r[3]) : "r"(addr));
}
__device__ __forceinline__ void cp_async16(uint32_t dst, const void* src) {
    asm volatile("cp.async.cg.shared.global [%0], [%1], 16;" :: "r"(dst), "l"(src));
}
__device__ __forceinline__ void cp_commit() {
    asm volatile("cp.async.commit_group;");
}
__device__ __forceinline__ void cp_wait0() {
    asm volatile("cp.async.wait_group 0;" ::: "memory");
}
__device__ __forceinline__ uint32_t smem_u32(const void* p) {
    return (uint32_t)__cvta_generic_to_shared(p);
}

// ---------------- split conversion: fp32 -> (hi, lo) bf16 ----------------
__global__ __launch_bounds__(256) void split_kernel(
    const float* __restrict__ in, __nv_bfloat16* __restrict__ hi,
    __nv_bfloat16* __restrict__ lo)
{
    size_t i = (size_t)blockIdx.x * 256 + threadIdx.x;   // one float4 per thread
    float4 v = ((const float4*)in)[i];
    __nv_bfloat16 h0 = __float2bfloat16(v.x);
    __nv_bfloat16 h1 = __float2bfloat16(v.y);
    __nv_bfloat16 h2 = __float2bfloat16(v.z);
    __nv_bfloat16 h3 = __float2bfloat16(v.w);
    __nv_bfloat16 l0 = __float2bfloat16(v.x - __bfloat162float(h0));
    __nv_bfloat16 l1 = __float2bfloat16(v.y - __bfloat162float(h1));
    __nv_bfloat16 l2 = __float2bfloat16(v.z - __bfloat162float(h2));
    __nv_bfloat16 l3 = __float2bfloat16(v.w - __bfloat162float(h3));
    __nv_bfloat162* hp = (__nv_bfloat162*)hi;
    __nv_bfloat162* lp = (__nv_bfloat162*)lo;
    __nv_bfloat162 a; a.x = h0; a.y = h1;
    __nv_bfloat162 b; b.x = h2; b.y = h3;
    hp[i * 2] = a; hp[i * 2 + 1] = b;
    a.x = l0; a.y = l1; b.x = l2; b.y = l3;
    lp[i * 2] = a; lp[i * 2 + 1] = b;
}

// ---------------- transpose + split for ALL weights in ONE launch ----------------
// tiles: Wq 2048, Wk 2048, Wv 4096, Wg 4096, Wo 4096  (32x32 tiles)
__global__ __launch_bounds__(256) void tsplit_all_kernel(
    const float* __restrict__ Wq, const float* __restrict__ Wk,
    const float* __restrict__ Wv, const float* __restrict__ Wg,
    const float* __restrict__ Wo,
    __nv_bfloat16* __restrict__ wthi, __nv_bfloat16* __restrict__ wtlo,
    __nv_bfloat16* __restrict__ wohi, __nv_bfloat16* __restrict__ wolo)
{
    int idx = blockIdx.x;
    const float* W; __nv_bfloat16 *hiT, *loT; int N, tile;
    if (idx < 2048)       { W = Wq; hiT = wthi;                               loT = wtlo;                               N = KD; tile = idx; }
    else if (idx < 4096)  { W = Wk; hiT = wthi + (size_t)KD * GEMM_K;         loT = wtlo + (size_t)KD * GEMM_K;         N = KD; tile = idx - 2048; }
    else if (idx < 8192)  { W = Wv; hiT = wthi + (size_t)2 * KD * GEMM_K;     loT = wtlo + (size_t)2 * KD * GEMM_K;     N = VD; tile = idx - 4096; }
    else if (idx < 12288) { W = Wg; hiT = wthi + (size_t)(2 * KD + VD) * GEMM_K; loT = wtlo + (size_t)(2 * KD + VD) * GEMM_K; N = VD; tile = idx - 8192; }
    else                  { W = Wo; hiT = wohi;                               loT = wolo;                               N = HDIM; tile = idx - 12288; }
    const int ntiles = N / 32;
    const int n0 = (tile % ntiles) * 32, k0 = (tile / ntiles) * 32;

    __shared__ float t[32][33];
    const int tx = threadIdx.x & 31, ty = threadIdx.x >> 5;   // 32 x 8
    #pragma unroll
    for (int j = 0; j < 4; j++)
        t[ty + 8 * j][tx] = W[(size_t)(k0 + ty + 8 * j) * N + n0 + tx];
    __syncthreads();
    #pragma unroll
    for (int j = 0; j < 4; j++) {
        float v = t[tx][ty + 8 * j];
        __nv_bfloat16 h = __float2bfloat16(v);
        size_t oidx = (size_t)(n0 + ty + 8 * j) * GEMM_K + k0 + tx;
        hiT[oidx] = h;
        loT[oidx] = __float2bfloat16(v - __bfloat162float(h));
    }
}

// ---------------- HMMA GEMM: 128x128 output tile, K=2048, split bf16, ldmatrix frags ----
__device__ void gemm_mma_body(
    const __nv_bfloat16* __restrict__ Ahi, const __nv_bfloat16* __restrict__ Alo,
    const __nv_bfloat16* __restrict__ Bhi, const __nv_bfloat16* __restrict__ Blo,
    int m0, int nrow0, float* __restrict__ dst, int ldc, int col0)
{
    extern __shared__ __nv_bfloat16 S[];   // 8 tiles of TS: [buf][Ahi,Alo,Bhi,Blo]

    const int tid  = threadIdx.x;
    const int lane = tid & 31, wid = tid >> 5;
    const int wm = wid & 1, wn = wid >> 1;     // 2 x 4 warp grid
    const int g = lane >> 2, t = lane & 3;
    const uint32_t Sb = smem_u32(S);

    // ldmatrix per-lane offsets (elements)
    // A x4: m0=rows0-7 k0 | m1=rows8-15 k0 | m2=rows0-7 k8 | m3=rows8-15 k8
    const int a_lane = (lane & 15) * TPAD + (lane >> 4) * 8;
    // B x4 (two 8-row n-tiles): g0=n0-7 k0 | g1=n0-7 k8 | g2=n8-15 k0 | g3=n8-15 k8
    const int b_lane = ((lane >> 4) * 8 + (lane & 7)) * TPAD + ((lane >> 3) & 1) * 8;

    float acc[4][4][4];
    #pragma unroll
    for (int i = 0; i < 4; i++)
        #pragma unroll
        for (int j = 0; j < 4; j++)
            #pragma unroll
            for (int r = 0; r < 4; r++) acc[i][j][r] = 0.f;

    auto tile_load = [&](const __nv_bfloat16* __restrict__ src, int row0, int k0, int sb) {
        #pragma unroll
        for (int j = 0; j < 2; j++) {
            int f = tid + 256 * j;            // 0..511: 128 rows x 4 uint4
            int row = f >> 2, c4 = f & 3;
            cp_async16(smem_u32(&S[sb + row * TPAD + c4 * 8]),
                       src + (size_t)(row0 + row) * GEMM_K + k0 + c4 * 8);
        }
    };

    // preload slab 0
    tile_load(Ahi, m0, 0, 0);
    tile_load(Alo, m0, 0, TS);
    tile_load(Bhi, nrow0, 0, 2 * TS);
    tile_load(Blo, nrow0, 0, 3 * TS);
    cp_commit();

    for (int it = 0; it < NITG; it++) {
        cp_wait0();
        __syncthreads();
        const int sb = (it & 1) * 4 * TS;
        if (it + 1 < NITG) {
            const int nb = ((it + 1) & 1) * 4 * TS;
            const int k0 = (it + 1) * BKG;
            tile_load(Ahi, m0, k0, nb);
            tile_load(Alo, m0, k0, nb + TS);
            tile_load(Bhi, nrow0, k0, nb + 2 * TS);
            tile_load(Blo, nrow0, k0, nb + 3 * TS);
            cp_commit();
        }
        #pragma unroll
        for (int ks = 0; ks < 2; ks++) {
            const int kc = ks * 16;
            uint32_t ah[4][4], al[4][4], bh[2][4], bl[2][4];
            #pragma unroll
            for (int mt = 0; mt < 4; mt++) {
                uint32_t addr = Sb + 2u * (uint32_t)(sb + (wm * 64 + mt * 16) * TPAD + kc + a_lane);
                ldsm_x4(ah[mt], addr);
                ldsm_x4(al[mt], addr + 2u * TS);
            }
            #pragma unroll
            for (int p = 0; p < 2; p++) {   // each covers nt = 2p, 2p+1
                uint32_t addr = Sb + 2u * (uint32_t)(sb + 2 * TS + (wn * 32 + p * 16) * TPAD + kc + b_lane);
                ldsm_x4(bh[p], addr);
                ldsm_x4(bl[p], addr + 2u * TS);
            }
            #pragma unroll
            for (int mt = 0; mt < 4; mt++)
                #pragma unroll
                for (int nt = 0; nt < 4; nt++) {
                    const uint32_t* bhp = &bh[nt >> 1][(nt & 1) * 2];
                    const uint32_t* blp = &bl[nt >> 1][(nt & 1) * 2];
                    mma_bf16(acc[mt][nt], ah[mt], bhp);
                    mma_bf16(acc[mt][nt], ah[mt], blp);
                    mma_bf16(acc[mt][nt], al[mt], bhp);
                }
        }
        __syncthreads();
    }

    // epilogue
    #pragma unroll
    for (int mt = 0; mt < 4; mt++) {
        int r = m0 + wm * 64 + mt * 16 + g;
        #pragma unroll
        for (int nt = 0; nt < 4; nt++) {
            int cc = col0 + wn * 32 + nt * 8 + 2 * t;
            *(float2*)&dst[(size_t)r * ldc + cc]       = make_float2(acc[mt][nt][0], acc[mt][nt][1]);
            *(float2*)&dst[(size_t)(r + 8) * ldc + cc] = make_float2(acc[mt][nt][2], acc[mt][nt][3]);
        }
    }
}

#define SMEM_DYN (8 * TS * 2)   // 81920 bytes

// fused Q/K/V/G projection GEMM: grid (48 n-tiles, 32 m-tiles)
__global__ __launch_bounds__(256) void qkvg_tc_kernel(
    const __nv_bfloat16* __restrict__ xhi, const __nv_bfloat16* __restrict__ xlo,
    const __nv_bfloat16* __restrict__ wthi, const __nv_bfloat16* __restrict__ wtlo,
    float* __restrict__ q, float* __restrict__ k,
    float* __restrict__ v, float* __restrict__ g)
{
    const int nt = blockIdx.x;
    const int m0 = blockIdx.y * 128;
    float* dst; int ldc, col0;
    if (nt < 8)       { dst = q; ldc = KD; col0 = nt * 128; }
    else if (nt < 16) { dst = k; ldc = KD; col0 = (nt - 8) * 128; }
    else if (nt < 32) { dst = v; ldc = VD; col0 = (nt - 16) * 128; }
    else              { dst = g; ldc = VD; col0 = (nt - 32) * 128; }
    gemm_mma_body(xhi, xlo, wthi, wtlo, m0, nt * 128, dst, ldc, col0);
}

// output GEMM: out = o @ Wo ; grid (16 n-tiles, 32 m-tiles)
__global__ __launch_bounds__(256) void wo_tc_kernel(
    const __nv_bfloat16* __restrict__ ohi, const __nv_bfloat16* __restrict__ olo,
    const __nv_bfloat16* __restrict__ wohi, const __nv_bfloat16* __restrict__ wolo,
    float* __restrict__ out)
{
    const int nt = blockIdx.x;
    const int m0 = blockIdx.y * 128;
    gemm_mma_body(ohi, olo, wohi, wolo, m0, nt * 128, out, HDIM, nt * 128);
}

// ---------------- gate low-rank: x16 = x @ Wgk1 ----------------
__global__ __launch_bounds__(256) void gk1_kernel(
    const float* __restrict__ x, const float* __restrict__ W, float* __restrict__ out)
{
    const int t = blockIdx.x;
    const float* xr = x + (size_t)t * HDIM;
    float acc[16];
    #pragma unroll
    for (int j = 0; j < 16; j++) acc[j] = 0.f;

    for (int i = threadIdx.x; i < HDIM; i += 256) {
        float xv = xr[i];
        const float* wr = W + (size_t)i * 16;
        #pragma unroll
        for (int j = 0; j < 16; j++) acc[j] = fmaf(xv, wr[j], acc[j]);
    }
    #pragma unroll
    for (int j = 0; j < 16; j++)
        #pragma unroll
        for (int off = 16; off > 0; off >>= 1)
            acc[j] += __shfl_down_sync(0xffffffffu, acc[j], off);

    __shared__ float red[8][16];
    const int warp = threadIdx.x >> 5, lane = threadIdx.x & 31;
    if (lane == 0) {
        #pragma unroll
        for (int j = 0; j < 16; j++) red[warp][j] = acc[j];
    }
    __syncthreads();
    if (threadIdx.x < 16) {
        float s = 0.f;
        #pragma unroll
        for (int w = 0; w < 8; w++) s += red[w][threadIdx.x];
        out[(size_t)t * 16 + threadIdx.x] = s;
    }
}

// ---------------- gk = logsigmoid(x16 @ Wgk2 + b) / 16 ----------------
__global__ __launch_bounds__(256) void gk2_kernel(
    const float* __restrict__ x16, const float* __restrict__ W2,
    const float* __restrict__ bias, float* __restrict__ gk)
{
    const int t = blockIdx.x;
    __shared__ float xs[16];
    if (threadIdx.x < 16) xs[threadIdx.x] = x16[(size_t)t * 16 + threadIdx.x];
    __syncthreads();
    for (int j = threadIdx.x; j < KD; j += 256) {
        float s = bias[j];
        #pragma unroll
        for (int r = 0; r < 16; r++) s = fmaf(xs[r], W2[(size_t)r * KD + j], s);
        float ls = fminf(s, 0.f) - log1pf(expf(-fabsf(s)));   // stable log_sigmoid
        gk[(size_t)t * KD + j] = ls * INV_GN;
    }
}

// ---------------- in-chunk inclusive cumsum of gk (in place) ----------------
__global__ __launch_bounds__(1024) void cumsum_kernel(float* __restrict__ gk)
{
    const int bn = blockIdx.x;
    const int b = bn / NCHUNK, n = bn % NCHUNK;
    const size_t t0 = (size_t)b * SEQ + (size_t)n * CH;
    const int c = threadIdx.x;
    float s = 0.f;
    for (int i = 0; i < CH; i++) {
        size_t idx = (t0 + i) * KD + c;
        s += gk[idx];
        gk[idx] = s;
    }
}

// ---------------- prep: q <- q*exp(gc)*SCALE, k <- k*exp(-gc) (in place) ----------------
__global__ __launch_bounds__(256) void prep_kernel(
    float* __restrict__ q, float* __restrict__ k, const float* __restrict__ gc)
{
    size_t i = (size_t)blockIdx.x * 256 + threadIdx.x;   // one float4 per thread
    float4 qv = ((const float4*)q)[i];
    float4 kv = ((const float4*)k)[i];
    float4 gv = ((const float4*)gc)[i];
    float e0 = expf(gv.x), e1 = expf(gv.y), e2 = expf(gv.z), e3 = expf(gv.w);
    qv.x *= e0 * SCALE; qv.y *= e1 * SCALE; qv.z *= e2 * SCALE; qv.w *= e3 * SCALE;
    kv.x /= e0; kv.y /= e1; kv.z /= e2; kv.w /= e3;
    ((float4*)q)[i] = qv;
    ((float4*)k)[i] = kv;
}

// ---------------- GLA phase 1: C[bhn] = k_dec^T @ v ----------------
__global__ __launch_bounds__(256) void chunk_kv_kernel(
    const float* __restrict__ k, const float* __restrict__ v,
    const float* __restrict__ gc, float* __restrict__ C)
{
    const int bhn = blockIdx.y;
    const int n = bhn % NCHUNK;
    const int bh = bhn / NCHUNK;
    const int h = bh % HNUM, b = bh / HNUM;
    const int dk0 = (blockIdx.x >> 3) * 128;
    const int dv0 = (blockIdx.x & 7) * 64;
    const size_t t0 = (size_t)b * SEQ + (size_t)n * CH;
    const int kc = h * DKH + dk0;
    const int vc = h * DVH + dv0;

    __shared__ __align__(16) float kd[64][128];
    __shared__ __align__(16) float vs[64][64];
    __shared__ float egl[128];

    const int tid = threadIdx.x;
    if (tid < 128) egl[tid] = expf(gc[(t0 + 63) * KD + kc + tid]);
    __syncthreads();

    #pragma unroll
    for (int r = 0; r < 8; r++) {
        int f = tid + 256 * r;
        int c = f >> 5;
        int off = (f & 31) << 2;
        float4 kv = *(const float4*)(k + (t0 + c) * KD + kc + off);
        float4 o4;
        o4.x = kv.x * egl[off + 0];
        o4.y = kv.y * egl[off + 1];
        o4.z = kv.z * egl[off + 2];
        o4.w = kv.w * egl[off + 3];
        *(float4*)&kd[c][off] = o4;
    }
    #pragma unroll
    for (int r = 0; r < 4; r++) {
        int f = tid + 256 * r;
        int c = f >> 4;
        int off = (f & 15) << 2;
        *(float4*)&vs[c][off] = *(const float4*)(v + (t0 + c) * VD + vc + off);
    }
    __syncthreads();

    const int tx = tid & 15, ty = tid >> 4;
    unsigned long long acc[8][2];
    #pragma unroll
    for (int i = 0; i < 8; i++) { acc[i][0] = 0ull; acc[i][1] = 0ull; }

    #pragma unroll 8
    for (int c = 0; c < 64; c++) {
        float4 af0 = *(const float4*)&kd[c][ty * 8];
        float4 af1 = *(const float4*)&kd[c][ty * 8 + 4];
        ulonglong2 bq = *(const ulonglong2*)&vs[c][tx * 4];
        float a[8] = { af0.x, af0.y, af0.z, af0.w, af1.x, af1.y, af1.z, af1.w };
        #pragma unroll
        for (int i = 0; i < 8; i++) {
            unsigned long long av = pack2(a[i]);
            acc[i][0] = fma2(av, bq.x, acc[i][0]);
            acc[i][1] = fma2(av, bq.y, acc[i][1]);
        }
    }

    const size_t cbase = (size_t)bhn * DKH * DVH;
    #pragma unroll
    for (int i = 0; i < 8; i++) {
        float2 p0 = unpack2(acc[i][0]);
        float2 p1 = unpack2(acc[i][1]);
        float* Cp = C + cbase + (size_t)(dk0 + ty * 8 + i) * DVH + dv0 + tx * 4;
        *(float4*)Cp = make_float4(p0.x, p0.y, p1.x, p1.y);
    }
}

// ---------------- GLA scan ----------------
__global__ __launch_bounds__(256) void scan_kernel(
    const float* __restrict__ gc, float* __restrict__ C)
{
    const int bh = blockIdx.y;
    const int h = bh % HNUM, b = bh / HNUM;
    const int dv0 = blockIdx.x * 32;
    const int tid = threadIdx.x;

    __shared__ float Ssm[256 * 32];
    __shared__ float eg[256];

    #pragma unroll
    for (int r = 0; r < 32; r++) Ssm[tid + 256 * r] = 0.f;

    for (int n = 0; n < NCHUNK; n++) {
        const size_t t0 = (size_t)b * SEQ + (size_t)n * CH;
        eg[tid] = expf(gc[(t0 + 63) * KD + h * DKH + tid]);
        __syncthreads();
        const size_t base = (size_t)((bh * NCHUNK) + n) * DKH * DVH;
        #pragma unroll
        for (int r = 0; r < 32; r++) {
            int e = tid + 256 * r;
            int dk = e >> 5;
            int dv = dv0 + (e & 31);
            size_t idx = base + (size_t)dk * DVH + dv;
            float cv = C[idx];
            float s  = Ssm[e];
            C[idx] = s;
            Ssm[e] = fmaf(s, eg[dk], cv);
        }
        __syncthreads();
    }
}

// ---------------- GLA phase 2 (q,k pre-gated) ----------------
__global__ __launch_bounds__(256) void gla_out_kernel(
    const float* __restrict__ q, const float* __restrict__ k,
    const float* __restrict__ v,
    const float* __restrict__ C, float* __restrict__ o)
{
    const int bhn = blockIdx.y;
    const int n = bhn % NCHUNK;
    const int bh = bhn / NCHUNK;
    const int h = bh % HNUM, b = bh / HNUM;
    const int dv0 = blockIdx.x * 128;
    const size_t t0 = (size_t)b * SEQ + (size_t)n * CH;
    const int kc = h * DKH;
    const int vc = h * DVH + dv0;
    const int tid = threadIdx.x, tx = tid & 15, ty = tid >> 4;

    __shared__ __align__(16) float pool[64 * 65 + 32 * 64 + 32 * 128];
    float* Asm = pool;
    float* P1  = pool + 64 * 65;
    float* P2  = pool + 64 * 65 + 32 * 64;

    unsigned long long accA[4][2];
    #pragma unroll
    for (int i = 0; i < 4; i++) { accA[i][0] = 0ull; accA[i][1] = 0ull; }

    for (int d0 = 0; d0 < DKH; d0 += 32) {
        #pragma unroll
        for (int r = 0; r < 2; r++) {
            int f = tid + 256 * r;
            int c = f >> 3;
            int off = (f & 7) << 2;
            size_t base = (t0 + c) * KD + kc + d0 + off;
            float4 qv = *(const float4*)(q + base);
            float4 kv = *(const float4*)(k + base);
            P1[(off + 0) * 64 + c] = qv.x;
            P1[(off + 1) * 64 + c] = qv.y;
            P1[(off + 2) * 64 + c] = qv.z;
            P1[(off + 3) * 64 + c] = qv.w;
            P2[(off + 0) * 64 + c] = kv.x;
            P2[(off + 1) * 64 + c] = kv.y;
            P2[(off + 2) * 64 + c] = kv.z;
            P2[(off + 3) * 64 + c] = kv.w;
        }
        __syncthreads();
        #pragma unroll
        for (int kk = 0; kk < 32; kk++) {
            float4 a4 = *(const float4*)&P1[kk * 64 + ty * 4];
            ulonglong2 bq = *(const ulonglong2*)&P2[kk * 64 + tx * 4];
            float a[4] = { a4.x, a4.y, a4.z, a4.w };
            #pragma unroll
            for (int i = 0; i < 4; i++) {
                unsigned long long av = pack2(a[i]);
                accA[i][0] = fma2(av, bq.x, accA[i][0]);
                accA[i][1] = fma2(av, bq.y, accA[i][1]);
            }
        }
        __syncthreads();
    }
    #pragma unroll
    for (int i = 0; i < 4; i++) {
        float2 p0 = unpack2(accA[i][0]);
        float2 p1 = unpack2(accA[i][1]);
        float vals[4] = { p0.x, p0.y, p1.x, p1.y };
        int ri = ty * 4 + i;
        #pragma unroll
        for (int j = 0; j < 4; j++) {
            int cj = tx * 4 + j;
            Asm[ri * 65 + cj] = (ri >= cj) ? vals[j] : 0.f;
        }
    }
    __syncthreads();

    unsigned long long acc[4][4];
    #pragma unroll
    for (int i = 0; i < 4; i++)
        #pragma unroll
        for (int j = 0; j < 4; j++) acc[i][j] = 0ull;

    for (int j0 = 0; j0 < 64; j0 += 32) {
        #pragma unroll
        for (int r = 0; r < 4; r++) {
            int f = tid + 256 * r;
            int c = f >> 5;
            int off = (f & 31) << 2;
            *(float4*)&P2[c * 128 + off] =
                *(const float4*)(v + (t0 + j0 + c) * VD + vc + off);
        }
        __syncthreads();
        #pragma unroll
        for (int jj = 0; jj < 32; jj++) {
            ulonglong2 b0 = *(const ulonglong2*)&P2[jj * 128 + tx * 4];
            ulonglong2 b1 = *(const ulonglong2*)&P2[jj * 128 + 64 + tx * 4];
            unsigned long long bv[4] = { b0.x, b0.y, b1.x, b1.y };
            #pragma unroll
            for (int ii = 0; ii < 4; ii++) {
                unsigned long long av = pack2(Asm[(ty * 4 + ii) * 65 + j0 + jj]);
                #pragma unroll
                for (int jp = 0; jp < 4; jp++)
                    acc[ii][jp] = fma2(av, bv[jp], acc[ii][jp]);
            }
        }
        __syncthreads();
    }

    const size_t sb = (size_t)bhn * DKH * DVH;
    for (int d0 = 0; d0 < DKH; d0 += 32) {
        #pragma unroll
        for (int r = 0; r < 2; r++) {
            int f = tid + 256 * r;
            int c = f >> 3;
            int off = (f & 7) << 2;
            float4 qv = *(const float4*)(q + (t0 + c) * KD + kc + d0 + off);
            P1[(off + 0) * 64 + c] = qv.x;
            P1[(off + 1) * 64 + c] = qv.y;
            P1[(off + 2) * 64 + c] = qv.z;
            P1[(off + 3) * 64 + c] = qv.w;
        }
        #pragma unroll
        for (int r = 0; r < 4; r++) {
            int f = tid + 256 * r;
            int c = f >> 5;
            int off = (f & 31) << 2;
            *(float4*)&P2[c * 128 + off] =
                *(const float4*)(C + sb + (size_t)(d0 + c) * DVH + dv0 + off);
        }
        __syncthreads();
        #pragma unroll
        for (int kk = 0; kk < 32; kk++) {
            float4 a4 = *(const float4*)&P1[kk * 64 + ty * 4];
            ulonglong2 b0 = *(const ulonglong2*)&P2[kk * 128 + tx * 4];
            ulonglong2 b1 = *(const ulonglong2*)&P2[kk * 128 + 64 + tx * 4];
            unsigned long long bv[4] = { b0.x, b0.y, b1.x, b1.y };
            float a[4] = { a4.x, a4.y, a4.z, a4.w };
            #pragma unroll
            for (int ii = 0; ii < 4; ii++) {
                unsigned long long av = pack2(a[ii]);
                #pragma unroll
                for (int jp = 0; jp < 4; jp++)
                    acc[ii][jp] = fma2(av, bv[jp], acc[ii][jp]);
            }
        }
        __syncthreads();
    }

    #pragma unroll
    for (int ii = 0; ii < 4; ii++) {
        size_t row = t0 + ty * 4 + ii;
        float2 p0 = unpack2(acc[ii][0]);
        float2 p1 = unpack2(acc[ii][1]);
        float2 p2 = unpack2(acc[ii][2]);
        float2 p3 = unpack2(acc[ii][3]);
        float* op = o + row * VD + vc;
        *(float4*)(op + tx * 4)      = make_float4(p0.x, p0.y, p1.x, p1.y);
        *(float4*)(op + 64 + tx * 4) = make_float4(p2.x, p2.y, p3.x, p3.y);
    }
}

// ---------------- rmsnorm * g_norm_weight * silu(g) -> bf16 split ----------------
__global__ __launch_bounds__(256) void post_kernel(
    const float* __restrict__ o, const float* __restrict__ g, const float* __restrict__ w,
    __nv_bfloat16* __restrict__ ohi, __nv_bfloat16* __restrict__ olo)
{
    const int t = blockIdx.x, h = blockIdx.y;
    const size_t base = (size_t)t * VD + (size_t)h * DVH;
    const int tid = threadIdx.x;

    float v0 = o[base + tid];
    float v1 = o[base + tid + 256];
    float ss = v0 * v0 + v1 * v1;
    #pragma unroll
    for (int off = 16; off > 0; off >>= 1)
        ss += __shfl_down_sync(0xffffffffu, ss, off);

    __shared__ float red[8];
    __shared__ float inv_s;
    if ((tid & 31) == 0) red[tid >> 5] = ss;
    __syncthreads();
    if (tid == 0) {
        float s = 0.f;
        #pragma unroll
        for (int wi = 0; wi < 8; wi++) s += red[wi];
        inv_s = rsqrtf(s * (1.f / DVH) + EPS_F);
    }
    __syncthreads();
    const float inv = inv_s;

    float g0 = g[base + tid];
    float g1 = g[base + tid + 256];
    float s0 = g0 / (1.f + expf(-g0));
    float s1 = g1 / (1.f + expf(-g1));
    float r0 = v0 * inv * w[tid]       * s0;
    float r1 = v1 * inv * w[tid + 256] * s1;

    __nv_bfloat16 h0 = __float2bfloat16(r0);
    __nv_bfloat16 h1 = __float2bfloat16(r1);
    ohi[base + tid]       = h0;
    ohi[base + tid + 256] = h1;
    olo[base + tid]       = __float2bfloat16(r0 - __bfloat162float(h0));
    olo[base + tid + 256] = __float2bfloat16(r1 - __bfloat162float(h1));
}

// ---------------- launch ----------------
extern "C" void kernel_launch(void* const* d_in, const int* in_sizes, int n_in,
                              void* d_out, int out_size)
{
    const float* x    = (const float*)d_in[0];
    const float* Wq   = (const float*)d_in[1];
    const float* Wk   = (const float*)d_in[2];
    const float* Wv   = (const float*)d_in[3];
    const float* Wgk1 = (const float*)d_in[4];
    const float* Wgk2 = (const float*)d_in[5];
    const float* bgk2 = (const float*)d_in[6];
    const float* Wg   = (const float*)d_in[7];
    const float* gnw  = (const float*)d_in[8];
    const float* Wo   = (const float*)d_in[9];
    float* out = (float*)d_out;

    float *q, *k, *v, *g, *gk, *o, *x16, *C;
    __nv_bfloat16 *xhi, *xlo, *wthi, *wtlo, *wohi, *wolo, *ohi, *olo;
    cudaGetSymbolAddress((void**)&q,    d_q);
    cudaGetSymbolAddress((void**)&k,    d_k);
    cudaGetSymbolAddress((void**)&v,    d_v);
    cudaGetSymbolAddress((void**)&g,    d_gbuf);
    cudaGetSymbolAddress((void**)&gk,   d_gk);
    cudaGetSymbolAddress((void**)&o,    d_o);
    cudaGetSymbolAddress((void**)&x16,  d_x16);
    cudaGetSymbolAddress((void**)&C,    d_C);
    cudaGetSymbolAddress((void**)&xhi,  d_xhi);
    cudaGetSymbolAddress((void**)&xlo,  d_xlo);
    cudaGetSymbolAddress((void**)&wthi, d_wthi);
    cudaGetSymbolAddress((void**)&wtlo, d_wtlo);
    cudaGetSymbolAddress((void**)&wohi, d_wohi);
    cudaGetSymbolAddress((void**)&wolo, d_wolo);
    cudaGetSymbolAddress((void**)&ohi,  d_ohi);
    cudaGetSymbolAddress((void**)&olo,  d_olo);

    cudaFuncSetAttribute((const void*)qkvg_tc_kernel,
                         cudaFuncAttributeMaxDynamicSharedMemorySize, SMEM_DYN);
    cudaFuncSetAttribute((const void*)wo_tc_kernel,
                         cudaFuncAttributeMaxDynamicSharedMemorySize, SMEM_DYN);

    // launch order places qkvg_tc at index 5 so ncu (-s 5 -c 1) profiles it
    split_kernel<<<(size_t)TB * HDIM / 1024, 256>>>(x, xhi, xlo);                    // 0
    tsplit_all_kernel<<<16384, 256>>>(Wq, Wk, Wv, Wg, Wo, wthi, wtlo, wohi, wolo);   // 1
    gk1_kernel<<<TB, 256>>>(x, Wgk1, x16);                                           // 2
    gk2_kernel<<<TB, 256>>>(x16, Wgk2, bgk2, gk);                                    // 3
    cumsum_kernel<<<BATCH * NCHUNK, 1024>>>(gk);                                     // 4
    qkvg_tc_kernel<<<dim3(QKVG_NT, TB / 128), 256, SMEM_DYN>>>(xhi, xlo, wthi, wtlo, q, k, v, g); // 5

    prep_kernel<<<(size_t)TB * KD / 1024, 256>>>(q, k, gk);

    chunk_kv_kernel<<<dim3(16, BATCH * HNUM * NCHUNK), 256>>>(k, v, gk, C);
    scan_kernel<<<dim3(16, BATCH * HNUM), 256>>>(gk, C);
    gla_out_kernel<<<dim3(4, BATCH * HNUM * NCHUNK), 256>>>(q, k, v, C, o);

    post_kernel<<<dim3(TB, HNUM), 256>>>(o, g, gnw, ohi, olo);
    wo_tc_kernel<<<dim3(HDIM / 128, TB / 128), 256, SMEM_DYN>>>(ohi, olo, wohi, wolo, out);
}

// round 16
// speedup vs baseline: 1.8652x; 1.0334x over previous
#include <cuda_runtime.h>
#include <cuda_bf16.h>
#include <math.h>
#include <stdint.h>

// ---------------- problem constants ----------------
#define BATCH   2
#define SEQ     2048
#define HDIM    2048
#define TB      4096
#define HNUM    4
#define DKH     256
#define DVH     512
#define KD      1024
#define VD      2048
#define CH      64
#define NCHUNK  32
#define SCALE   0.0625f
#define INV_GN  0.0625f
#define EPS_F   1e-5f

#define GEMM_K  2048
#define BKG     32
#define NITG    (GEMM_K / BKG)
#define QKVG_NT 48
#define TPAD    40
#define TS      (128 * TPAD)

// GLA HMMA tile pads (row stride ≡ 4 banks -> conflict-free ldsm)
#define TPK     136   // 128 + 8
#define TPV     72    // 64 + 8
#define TPQ     72
#define TPS     136

// ---------------- device scratch (aliased aggressively; ~386 MB total) ----------------
__device__ float d_q   [(size_t)TB * KD];   // later reused as ohi (bf16)
__device__ float d_k   [(size_t)TB * KD];   // later reused as olo (bf16)
__device__ float d_v   [(size_t)TB * VD];
__device__ float d_gbuf[(size_t)TB * VD];
__device__ float d_gk  [(size_t)TB * KD];
__device__ float d_o   [(size_t)TB * VD];
__device__ float d_x16 [(size_t)TB * 16];
__device__ float d_C   [(size_t)BATCH * HNUM * NCHUNK * DKH * DVH];

__device__ __nv_bfloat16 d_xhi [(size_t)TB * HDIM];   // later reused as qhi|khi
__device__ __nv_bfloat16 d_xlo [(size_t)TB * HDIM];   // later reused as qlo|klo
__device__ __nv_bfloat16 d_wthi[(size_t)(2 * KD + 2 * VD) * GEMM_K];  // later vhi
__device__ __nv_bfloat16 d_wtlo[(size_t)(2 * KD + 2 * VD) * GEMM_K];  // later vlo
__device__ __nv_bfloat16 d_wohi[(size_t)HDIM * GEMM_K];
__device__ __nv_bfloat16 d_wolo[(size_t)HDIM * GEMM_K];

// ---------------- HMMA / cp.async / ldmatrix helpers ----------------
__device__ __forceinline__ void mma_bf16(float* c, const uint32_t* a, const uint32_t* b) {
    asm volatile(
        "mma.sync.aligned.m16n8k16.row.col.f32.bf16.bf16.f32 "
        "{%0,%1,%2,%3}, {%4,%5,%6,%7}, {%8,%9}, {%0,%1,%2,%3};"
        : "+f"(c[0]), "+f"(c[1]), "+f"(c[2]), "+f"(c[3])
        : "r"(a[0]), "r"(a[1]), "r"(a[2]), "r"(a[3]), "r"(b[0]), "r"(b[1]));
}
__device__ __forceinline__ void ldsm_x4(uint32_t* r, uint32_t addr) {
    asm volatile("ldmatrix.sync.aligned.m8n8.x4.shared.b16 {%0,%1,%2,%3}, [%4];"
        : "=r"(r[0]), "=r"(r[1]), "=r"(r[2]), "=r"(r[3]) : "r"(addr));
}
__device__ __forceinline__ void ldsm_x4_t(uint32_t* r, uint32_t addr) {
    asm volatile("ldmatrix.sync.aligned.m8n8.x4.trans.shared.b16 {%0,%1,%2,%3}, [%4];"
        : "=r"(r[0]), "=r"(r[1]), "=r"(r[2]), "=r"(r[3]) : "r"(addr));
}
__device__ __forceinline__ void cp_async16(uint32_t dst, const void* src) {
    asm volatile("cp.async.cg.shared.global [%0], [%1], 16;" :: "r"(dst), "l"(src));
}
__device__ __forceinline__ void cp_commit() { asm volatile("cp.async.commit_group;"); }
__device__ __forceinline__ void cp_wait0()  { asm volatile("cp.async.wait_group 0;" ::: "memory"); }
__device__ __forceinline__ uint32_t smem_u32(const void* p) {
    return (uint32_t)__cvta_generic_to_shared(p);
}

// ---------------- split conversion: fp32 -> (hi, lo) bf16 ----------------
__global__ __launch_bounds__(256) void split_kernel(
    const float* __restrict__ in, __nv_bfloat16* __restrict__ hi,
    __nv_bfloat16* __restrict__ lo)
{
    size_t i = (size_t)blockIdx.x * 256 + threadIdx.x;
    float4 v = ((const float4*)in)[i];
    __nv_bfloat16 h[4], l[4];
    float f[4] = { v.x, v.y, v.z, v.w };
    #pragma unroll
    for (int j = 0; j < 4; j++) {
        h[j] = __float2bfloat16(f[j]);
        l[j] = __float2bfloat16(f[j] - __bfloat162float(h[j]));
    }
    *(uint2*)&hi[i * 4] = *(uint2*)h;
    *(uint2*)&lo[i * 4] = *(uint2*)l;
}

// ---------------- transpose + split for ALL weights in ONE launch ----------------
__global__ __launch_bounds__(256) void tsplit_all_kernel(
    const float* __restrict__ Wq, const float* __restrict__ Wk,
    const float* __restrict__ Wv, const float* __restrict__ Wg,
    const float* __restrict__ Wo,
    __nv_bfloat16* __restrict__ wthi, __nv_bfloat16* __restrict__ wtlo,
    __nv_bfloat16* __restrict__ wohi, __nv_bfloat16* __restrict__ wolo)
{
    int idx = blockIdx.x;
    const float* W; __nv_bfloat16 *hiT, *loT; int N, tile;
    if (idx < 2048)       { W = Wq; hiT = wthi;                                  loT = wtlo;                                  N = KD; tile = idx; }
    else if (idx < 4096)  { W = Wk; hiT = wthi + (size_t)KD * GEMM_K;            loT = wtlo + (size_t)KD * GEMM_K;            N = KD; tile = idx - 2048; }
    else if (idx < 8192)  { W = Wv; hiT = wthi + (size_t)2 * KD * GEMM_K;        loT = wtlo + (size_t)2 * KD * GEMM_K;        N = VD; tile = idx - 4096; }
    else if (idx < 12288) { W = Wg; hiT = wthi + (size_t)(2 * KD + VD) * GEMM_K; loT = wtlo + (size_t)(2 * KD + VD) * GEMM_K; N = VD; tile = idx - 8192; }
    else                  { W = Wo; hiT = wohi;                                  loT = wolo;                                  N = HDIM; tile = idx - 12288; }
    const int ntiles = N / 32;
    const int n0 = (tile % ntiles) * 32, k0 = (tile / ntiles) * 32;

    __shared__ float t[32][33];
    const int tx = threadIdx.x & 31, ty = threadIdx.x >> 5;
    #pragma unroll
    for (int j = 0; j < 4; j++)
        t[ty + 8 * j][tx] = W[(size_t)(k0 + ty + 8 * j) * N + n0 + tx];
    __syncthreads();
    #pragma unroll
    for (int j = 0; j < 4; j++) {
        float v = t[tx][ty + 8 * j];
        __nv_bfloat16 h = __float2bfloat16(v);
        size_t oidx = (size_t)(n0 + ty + 8 * j) * GEMM_K + k0 + tx;
        hiT[oidx] = h;
        loT[oidx] = __float2bfloat16(v - __bfloat162float(h));
    }
}

// ---------------- HMMA GEMM body ----------------
__device__ void gemm_mma_body(
    const __nv_bfloat16* __restrict__ Ahi, const __nv_bfloat16* __restrict__ Alo,
    const __nv_bfloat16* __restrict__ Bhi, const __nv_bfloat16* __restrict__ Blo,
    int m0, int nrow0, float* __restrict__ dst, int ldc, int col0)
{
    extern __shared__ __nv_bfloat16 S[];

    const int tid  = threadIdx.x;
    const int lane = tid & 31, wid = tid >> 5;
    const int wm = wid & 1, wn = wid >> 1;
    const int g = lane >> 2, t = lane & 3;
    const uint32_t Sb = smem_u32(S);

    const int a_lane = (lane & 15) * TPAD + (lane >> 4) * 8;
    const int b_lane = ((lane >> 4) * 8 + (lane & 7)) * TPAD + ((lane >> 3) & 1) * 8;

    float acc[4][4][4];
    #pragma unroll
    for (int i = 0; i < 4; i++)
        #pragma unroll
        for (int j = 0; j < 4; j++)
            #pragma unroll
            for (int r = 0; r < 4; r++) acc[i][j][r] = 0.f;

    auto tile_load = [&](const __nv_bfloat16* __restrict__ src, int row0, int k0, int sb) {
        #pragma unroll
        for (int j = 0; j < 2; j++) {
            int f = tid + 256 * j;
            int row = f >> 2, c4 = f & 3;
            cp_async16(smem_u32(&S[sb + row * TPAD + c4 * 8]),
                       src + (size_t)(row0 + row) * GEMM_K + k0 + c4 * 8);
        }
    };

    tile_load(Ahi, m0, 0, 0);
    tile_load(Alo, m0, 0, TS);
    tile_load(Bhi, nrow0, 0, 2 * TS);
    tile_load(Blo, nrow0, 0, 3 * TS);
    cp_commit();

    for (int it = 0; it < NITG; it++) {
        cp_wait0();
        __syncthreads();
        const int sb = (it & 1) * 4 * TS;
        if (it + 1 < NITG) {
            const int nb = ((it + 1) & 1) * 4 * TS;
            const int k0 = (it + 1) * BKG;
            tile_load(Ahi, m0, k0, nb);
            tile_load(Alo, m0, k0, nb + TS);
            tile_load(Bhi, nrow0, k0, nb + 2 * TS);
            tile_load(Blo, nrow0, k0, nb + 3 * TS);
            cp_commit();
        }
        #pragma unroll
        for (int ks = 0; ks < 2; ks++) {
            const int kc = ks * 16;
            uint32_t ah[4][4], al[4][4], bh[2][4], bl[2][4];
            #pragma unroll
            for (int mt = 0; mt < 4; mt++) {
                uint32_t addr = Sb + 2u * (uint32_t)(sb + (wm * 64 + mt * 16) * TPAD + kc + a_lane);
                ldsm_x4(ah[mt], addr);
                ldsm_x4(al[mt], addr + 2u * TS);
            }
            #pragma unroll
            for (int p = 0; p < 2; p++) {
                uint32_t addr = Sb + 2u * (uint32_t)(sb + 2 * TS + (wn * 32 + p * 16) * TPAD + kc + b_lane);
                ldsm_x4(bh[p], addr);
                ldsm_x4(bl[p], addr + 2u * TS);
            }
            #pragma unroll
            for (int mt = 0; mt < 4; mt++)
                #pragma unroll
                for (int nt = 0; nt < 4; nt++) {
                    const uint32_t* bhp = &bh[nt >> 1][(nt & 1) * 2];
                    const uint32_t* blp = &bl[nt >> 1][(nt & 1) * 2];
                    mma_bf16(acc[mt][nt], ah[mt], bhp);
                    mma_bf16(acc[mt][nt], ah[mt], blp);
                    mma_bf16(acc[mt][nt], al[mt], bhp);
                }
        }
        __syncthreads();
    }

    #pragma unroll
    for (int mt = 0; mt < 4; mt++) {
        int r = m0 + wm * 64 + mt * 16 + g;
        #pragma unroll
        for (int nt = 0; nt < 4; nt++) {
            int cc = col0 + wn * 32 + nt * 8 + 2 * t;
            *(float2*)&dst[(size_t)r * ldc + cc]       = make_float2(acc[mt][nt][0], acc[mt][nt][1]);
            *(float2*)&dst[(size_t)(r + 8) * ldc + cc] = make_float2(acc[mt][nt][2], acc[mt][nt][3]);
        }
    }
}

#define SMEM_DYN (8 * TS * 2)

__global__ __launch_bounds__(256) void qkvg_tc_kernel(
    const __nv_bfloat16* __restrict__ xhi, const __nv_bfloat16* __restrict__ xlo,
    const __nv_bfloat16* __restrict__ wthi, const __nv_bfloat16* __restrict__ wtlo,
    float* __restrict__ q, float* __restrict__ k,
    float* __restrict__ v, float* __restrict__ g)
{
    const int nt = blockIdx.x;
    const int m0 = blockIdx.y * 128;
    float* dst; int ldc, col0;
    if (nt < 8)       { dst = q; ldc = KD; col0 = nt * 128; }
    else if (nt < 16) { dst = k; ldc = KD; col0 = (nt - 8) * 128; }
    else if (nt < 32) { dst = v; ldc = VD; col0 = (nt - 16) * 128; }
    else              { dst = g; ldc = VD; col0 = (nt - 32) * 128; }
    gemm_mma_body(xhi, xlo, wthi, wtlo, m0, nt * 128, dst, ldc, col0);
}

__global__ __launch_bounds__(256) void wo_tc_kernel(
    const __nv_bfloat16* __restrict__ ohi, const __nv_bfloat16* __restrict__ olo,
    const __nv_bfloat16* __restrict__ wohi, const __nv_bfloat16* __restrict__ wolo,
    float* __restrict__ out)
{
    gemm_mma_body(ohi, olo, wohi, wolo, blockIdx.y * 128, blockIdx.x * 128, out, HDIM, blockIdx.x * 128);
}

// ---------------- gate path ----------------
__global__ __launch_bounds__(256) void gk1_kernel(
    const float* __restrict__ x, const float* __restrict__ W, float* __restrict__ out)
{
    const int t = blockIdx.x;
    const float* xr = x + (size_t)t * HDIM;
    float acc[16];
    #pragma unroll
    for (int j = 0; j < 16; j++) acc[j] = 0.f;
    for (int i = threadIdx.x; i < HDIM; i += 256) {
        float xv = xr[i];
        const float* wr = W + (size_t)i * 16;
        #pragma unroll
        for (int j = 0; j < 16; j++) acc[j] = fmaf(xv, wr[j], acc[j]);
    }
    #pragma unroll
    for (int j = 0; j < 16; j++)
        #pragma unroll
        for (int off = 16; off > 0; off >>= 1)
            acc[j] += __shfl_down_sync(0xffffffffu, acc[j], off);
    __shared__ float red[8][16];
    const int warp = threadIdx.x >> 5, lane = threadIdx.x & 31;
    if (lane == 0) {
        #pragma unroll
        for (int j = 0; j < 16; j++) red[warp][j] = acc[j];
    }
    __syncthreads();
    if (threadIdx.x < 16) {
        float s = 0.f;
        #pragma unroll
        for (int w = 0; w < 8; w++) s += red[w][threadIdx.x];
        out[(size_t)t * 16 + threadIdx.x] = s;
    }
}

__global__ __launch_bounds__(256) void gk2_kernel(
    const float* __restrict__ x16, const float* __restrict__ W2,
    const float* __restrict__ bias, float* __restrict__ gk)
{
    const int t = blockIdx.x;
    __shared__ float xs[16];
    if (threadIdx.x < 16) xs[threadIdx.x] = x16[(size_t)t * 16 + threadIdx.x];
    __syncthreads();
    for (int j = threadIdx.x; j < KD; j += 256) {
        float s = bias[j];
        #pragma unroll
        for (int r = 0; r < 16; r++) s = fmaf(xs[r], W2[(size_t)r * KD + j], s);
        float ls = fminf(s, 0.f) - log1pf(expf(-fabsf(s)));
        gk[(size_t)t * KD + j] = ls * INV_GN;
    }
}

__global__ __launch_bounds__(1024) void cumsum_kernel(float* __restrict__ gk)
{
    const int bn = blockIdx.x;
    const int b = bn / NCHUNK, n = bn % NCHUNK;
    const size_t t0 = (size_t)b * SEQ + (size_t)n * CH;
    const int c = threadIdx.x;
    float s = 0.f;
    for (int i = 0; i < CH; i++) {
        size_t idx = (t0 + i) * KD + c;
        s += gk[idx];
        gk[idx] = s;
    }
}

// ---------------- prep: gated q,k -> bf16 (hi,lo) splits ----------------
__global__ __launch_bounds__(256) void prep_kernel(
    const float* __restrict__ q, const float* __restrict__ k, const float* __restrict__ gc,
    __nv_bfloat16* __restrict__ qhi, __nv_bfloat16* __restrict__ qlo,
    __nv_bfloat16* __restrict__ khi, __nv_bfloat16* __restrict__ klo)
{
    size_t i = (size_t)blockIdx.x * 256 + threadIdx.x;
    float4 qv = ((const float4*)q)[i];
    float4 kv = ((const float4*)k)[i];
    float4 gv = ((const float4*)gc)[i];
    float qf[4], kf[4];
    float e0 = expf(gv.x), e1 = expf(gv.y), e2 = expf(gv.z), e3 = expf(gv.w);
    qf[0] = qv.x * e0 * SCALE; qf[1] = qv.y * e1 * SCALE;
    qf[2] = qv.z * e2 * SCALE; qf[3] = qv.w * e3 * SCALE;
    kf[0] = kv.x / e0; kf[1] = kv.y / e1; kf[2] = kv.z / e2; kf[3] = kv.w / e3;
    __nv_bfloat16 qh[4], ql[4], kh[4], kl[4];
    #pragma unroll
    for (int j = 0; j < 4; j++) {
        qh[j] = __float2bfloat16(qf[j]);
        ql[j] = __float2bfloat16(qf[j] - __bfloat162float(qh[j]));
        kh[j] = __float2bfloat16(kf[j]);
        kl[j] = __float2bfloat16(kf[j] - __bfloat162float(kh[j]));
    }
    *(uint2*)&qhi[i * 4] = *(uint2*)qh;
    *(uint2*)&qlo[i * 4] = *(uint2*)ql;
    *(uint2*)&khi[i * 4] = *(uint2*)kh;
    *(uint2*)&klo[i * 4] = *(uint2*)kl;
}

// ---------------- GLA phase 1 (HMMA): C[bhn] = k_dec^T @ v ----------------
// block: 128 dk x 64 dv, K = 64 tokens; 8 warps (4m x 2n), warp tile 32x32
#define CKV_SMEM ((2 * 64 * TPK + 2 * 64 * TPV) * 2)   // bytes = 53248
__global__ __launch_bounds__(256) void chunk_kv_kernel(
    const __nv_bfloat16* __restrict__ khi, const __nv_bfloat16* __restrict__ klo,
    const __nv_bfloat16* __restrict__ vhi, const __nv_bfloat16* __restrict__ vlo,
    const float* __restrict__ gc, float* __restrict__ C)
{
    extern __shared__ __nv_bfloat16 SM[];
    __nv_bfloat16* kdh = SM;                     // [64][TPK]
    __nv_bfloat16* kdl = SM + 64 * TPK;
    __nv_bfloat16* vsh = SM + 2 * 64 * TPK;      // [64][TPV]
    __nv_bfloat16* vsl = SM + 2 * 64 * TPK + 64 * TPV;
    __shared__ float egl[128];

    const int bhn = blockIdx.y;
    const int n = bhn % NCHUNK;
    const int bh = bhn / NCHUNK;
    const int h = bh % HNUM, b = bh / HNUM;
    const int dk0 = (blockIdx.x >> 3) * 128;
    const int dv0 = (blockIdx.x & 7) * 64;
    const size_t t0 = (size_t)b * SEQ + (size_t)n * CH;
    const int kc = h * DKH + dk0;
    const int vc = h * DVH + dv0;
    const int tid = threadIdx.x;

    if (tid < 128) egl[tid] = expf(gc[(t0 + 63) * KD + kc + tid]);
    __syncthreads();

    // stage kdec = (khi+klo)*egl, re-split
    #pragma unroll
    for (int r = 0; r < 4; r++) {
        int f = tid + 256 * r;            // 1024: 64 rows x 16 uint4
        int row = f >> 4, off = (f & 15) * 8;
        uint4 hv = *(const uint4*)&khi[(t0 + row) * KD + kc + off];
        uint4 lv = *(const uint4*)&klo[(t0 + row) * KD + kc + off];
        const __nv_bfloat16* hp = (const __nv_bfloat16*)&hv;
        const __nv_bfloat16* lp = (const __nv_bfloat16*)&lv;
        __nv_bfloat16 oh[8], ol[8];
        #pragma unroll
        for (int i = 0; i < 8; i++) {
            float x = (__bfloat162float(hp[i]) + __bfloat162float(lp[i])) * egl[off + i];
            __nv_bfloat16 hh = __float2bfloat16(x);
            oh[i] = hh; ol[i] = __float2bfloat16(x - __bfloat162float(hh));
        }
        *(uint4*)&kdh[row * TPK + off] = *(uint4*)oh;
        *(uint4*)&kdl[row * TPK + off] = *(uint4*)ol;
    }
    // stage v (direct bf16 copies)
    #pragma unroll
    for (int r = 0; r < 2; r++) {
        int f = tid + 256 * r;            // 512: 64 rows x 8 uint4
        int row = f >> 3, off = (f & 7) * 8;
        *(uint4*)&vsh[row * TPV + off] = *(const uint4*)&vhi[(t0 + row) * VD + vc + off];
        *(uint4*)&vsl[row * TPV + off] = *(const uint4*)&vlo[(t0 + row) * VD + vc + off];
    }
    __syncthreads();

    const int lane = tid & 31, wid = tid >> 5;
    const int wm = wid & 3, wn = wid >> 2;       // 4m x 2n
    const int g = lane >> 2, t = lane & 3;
    const int sub = lane >> 3, rr = lane & 7;
    const int a_kr = ((sub >> 1) & 1) * 8 + rr;  // A (trans)
    const int a_mc = (sub & 1) * 8;
    const int b_kr = (sub & 1) * 8 + rr;         // B (trans)
    const int b_nc = (sub >> 1) * 8;
    const uint32_t kdh_b = smem_u32(kdh), kdl_b = smem_u32(kdl);
    const uint32_t vsh_b = smem_u32(vsh), vsl_b = smem_u32(vsl);

    float acc[2][4][4];
    #pragma unroll
    for (int i = 0; i < 2; i++)
        #pragma unroll
        for (int j = 0; j < 4; j++)
            #pragma unroll
            for (int r = 0; r < 4; r++) acc[i][j][r] = 0.f;

    #pragma unroll
    for (int kb = 0; kb < 64; kb += 16) {
        uint32_t ah[2][4], al[2][4], bh[2][4], bl[2][4];
        #pragma unroll
        for (int mt = 0; mt < 2; mt++) {
            uint32_t off = 2u * (uint32_t)((kb + a_kr) * TPK + wm * 32 + mt * 16 + a_mc);
            ldsm_x4_t(ah[mt], kdh_b + off);
            ldsm_x4_t(al[mt], kdl_b + off);
        }
        #pragma unroll
        for (int p = 0; p < 2; p++) {
            uint32_t off = 2u * (uint32_t)((kb + b_kr) * TPV + wn * 32 + p * 16 + b_nc);
            ldsm_x4_t(bh[p], vsh_b + off);
            ldsm_x4_t(bl[p], vsl_b + off);
        }
        #pragma unroll
        for (int mt = 0; mt < 2; mt++)
            #pragma unroll
            for (int nt = 0; nt < 4; nt++) {
                const uint32_t* bhp = &bh[nt >> 1][(nt & 1) * 2];
                const uint32_t* blp = &bl[nt >> 1][(nt & 1) * 2];
                mma_bf16(acc[mt][nt], ah[mt], bhp);
                mma_bf16(acc[mt][nt], ah[mt], blp);
                mma_bf16(acc[mt][nt], al[mt], bhp);
            }
    }

    const size_t cbase = (size_t)bhn * DKH * DVH;
    #pragma unroll
    for (int mt = 0; mt < 2; mt++) {
        int row = dk0 + wm * 32 + mt * 16 + g;
        #pragma unroll
        for (int nt = 0; nt < 4; nt++) {
            int cc = dv0 + wn * 32 + nt * 8 + 2 * t;
            *(float2*)&C[cbase + (size_t)row * DVH + cc]       = make_float2(acc[mt][nt][0], acc[mt][nt][1]);
            *(float2*)&C[cbase + (size_t)(row + 8) * DVH + cc] = make_float2(acc[mt][nt][2], acc[mt][nt][3]);
        }
    }
}

// ---------------- GLA scan (fp32 C) ----------------
__global__ __launch_bounds__(256) void scan_kernel(
    const float* __restrict__ gc, float* __restrict__ C)
{
    const int bh = blockIdx.y;
    const int h = bh % HNUM, b = bh / HNUM;
    const int dv0 = blockIdx.x * 32;
    const int tid = threadIdx.x;
    __shared__ float Ssm[256 * 32];
    __shared__ float eg[256];
    #pragma unroll
    for (int r = 0; r < 32; r++) Ssm[tid + 256 * r] = 0.f;
    for (int n = 0; n < NCHUNK; n++) {
        const size_t t0 = (size_t)b * SEQ + (size_t)n * CH;
        eg[tid] = expf(gc[(t0 + 63) * KD + h * DKH + tid]);
        __syncthreads();
        const size_t base = (size_t)((bh * NCHUNK) + n) * DKH * DVH;
        #pragma unroll
        for (int r = 0; r < 32; r++) {
            int e = tid + 256 * r;
            int dk = e >> 5;
            int dv = dv0 + (e & 31);
            size_t idx = base + (size_t)dk * DVH + dv;
            float cv = C[idx];
            float s  = Ssm[e];
            C[idx] = s;
            Ssm[e] = fmaf(s, eg[dk], cv);
        }
        __syncthreads();
    }
}

// ---------------- GLA phase 2 (HMMA): o = tril(q k^T) @ v + q @ S ----------------
#define GLA_SMEM ((4 * 64 * TPQ + 2 * 64 * TPS) * 2)   // bytes = 71680
__global__ __launch_bounds__(256) void gla_out_kernel(
    const __nv_bfloat16* __restrict__ qhi, const __nv_bfloat16* __restrict__ qlo,
    const __nv_bfloat16* __restrict__ khi, const __nv_bfloat16* __restrict__ klo,
    const __nv_bfloat16* __restrict__ vhi, const __nv_bfloat16* __restrict__ vlo,
    const float* __restrict__ C, float* __restrict__ o)
{
    extern __shared__ __nv_bfloat16 SM[];
    __nv_bfloat16* P0 = SM;                       // [64][TPQ] : q_hi / A_hi
    __nv_bfloat16* P1 = SM + 64 * TPQ;            // q_lo / A_lo
    __nv_bfloat16* P2 = SM + 2 * 64 * TPQ;        // k_hi / q_hi(C)
    __nv_bfloat16* P3 = SM + 3 * 64 * TPQ;        // k_lo / q_lo(C)
    __nv_bfloat16* V0 = SM + 4 * 64 * TPQ;        // [64][TPS] : v_hi / S_hi
    __nv_bfloat16* V1 = SM + 4 * 64 * TPQ + 64 * TPS;

    const int bhn = blockIdx.y;
    const int n = bhn % NCHUNK;
    const int bh = bhn / NCHUNK;
    const int h = bh % HNUM, b = bh / HNUM;
    const int dv0 = blockIdx.x * 128;
    const size_t t0 = (size_t)b * SEQ + (size_t)n * CH;
    const int kc = h * DKH;
    const int vc = h * DVH + dv0;
    const int tid = threadIdx.x;
    const int lane = tid & 31, wid = tid >> 5;
    const int g = lane >> 2, t = lane & 3;

    const int anl = (lane & 15) * TPQ + (lane >> 4) * 8;
    const int bnl = ((lane >> 4) * 8 + (lane & 7)) * TPQ + ((lane >> 3) & 1) * 8;
    const int sub = lane >> 3, rr = lane & 7;
    const int bt_kr = (sub & 1) * 8 + rr;
    const int bt_nc = (sub >> 1) * 8;

    const uint32_t P0b = smem_u32(P0), P1b = smem_u32(P1);
    const uint32_t P2b = smem_u32(P2), P3b = smem_u32(P3);
    const uint32_t V0b = smem_u32(V0), V1b = smem_u32(V1);

    // ---- Phase A: A = q k^T over K=256, warp grid 2m x 4n (tile 32x16) ----
    const int wmA = wid & 1, wnA = wid >> 1;
    float accA[2][2][4];
    #pragma unroll
    for (int i = 0; i < 2; i++)
        #pragma unroll
        for (int j = 0; j < 2; j++)
            #pragma unroll
            for (int r = 0; r < 4; r++) accA[i][j][r] = 0.f;

    for (int d0 = 0; d0 < DKH; d0 += 64) {
        #pragma unroll
        for (int r = 0; r < 8; r++) {
            int f = tid + 256 * r;
            int arr = f >> 9, pos = f & 511;
            int row = pos >> 3, off = (pos & 7) * 8;
            const __nv_bfloat16* src = (arr == 0) ? qhi : (arr == 1) ? qlo : (arr == 2) ? khi : klo;
            __nv_bfloat16* dstp = (arr == 0) ? P0 : (arr == 1) ? P1 : (arr == 2) ? P2 : P3;
            *(uint4*)&dstp[row * TPQ + off] =
                *(const uint4*)&src[(t0 + row) * KD + kc + d0 + off];
        }
        __syncthreads();
        #pragma unroll
        for (int kb = 0; kb < 64; kb += 16) {
            uint32_t ah[2][4], al[2][4], bhv[4], blv[4];
            #pragma unroll
            for (int mt = 0; mt < 2; mt++) {
                uint32_t off = 2u * (uint32_t)((wmA * 32 + mt * 16) * TPQ + kb + anl);
                ldsm_x4(ah[mt], P0b + off);
                ldsm_x4(al[mt], P1b + off);
            }
            {
                uint32_t off = 2u * (uint32_t)(wnA * 16 * TPQ + kb + bnl);
                ldsm_x4(bhv, P2b + off);
                ldsm_x4(blv, P3b + off);
            }
            #pragma unroll
            for (int mt = 0; mt < 2; mt++)
                #pragma unroll
                for (int nt = 0; nt < 2; nt++) {
                    const uint32_t* bhp = &bhv[nt * 2];
                    const uint32_t* blp = &blv[nt * 2];
                    mma_bf16(accA[mt][nt], ah[mt], bhp);
                    mma_bf16(accA[mt][nt], ah[mt], blp);
                    mma_bf16(accA[mt][nt], al[mt], bhp);
                }
        }
        __syncthreads();
    }

    // ---- mask tril, split A -> P0(hi), P1(lo); stage v -> V0,V1 ----
    #pragma unroll
    for (int mt = 0; mt < 2; mt++) {
        #pragma unroll
        for (int nt = 0; nt < 2; nt++) {
            int m = wmA * 32 + mt * 16 + g;
            int cn = wnA * 16 + nt * 8 + 2 * t;
            float v0 = (m >= cn) ? accA[mt][nt][0] : 0.f;
            float v1 = (m >= cn + 1) ? accA[mt][nt][1] : 0.f;
            float v2 = (m + 8 >= cn) ? accA[mt][nt][2] : 0.f;
            float v3 = (m + 8 >= cn + 1) ? accA[mt][nt][3] : 0.f;
            __nv_bfloat16 hp[2], lp[2];
            hp[0] = __float2bfloat16(v0); lp[0] = __float2bfloat16(v0 - __bfloat162float(hp[0]));
            hp[1] = __float2bfloat16(v1); lp[1] = __float2bfloat16(v1 - __bfloat162float(hp[1]));
            *(uint32_t*)&P0[m * TPQ + cn] = *(uint32_t*)hp;
            *(uint32_t*)&P1[m * TPQ + cn] = *(uint32_t*)lp;
            hp[0] = __float2bfloat16(v2); lp[0] = __float2bfloat16(v2 - __bfloat162float(hp[0]));
            hp[1] = __float2bfloat16(v3); lp[1] = __float2bfloat16(v3 - __bfloat162float(hp[1]));
            *(uint32_t*)&P0[(m + 8) * TPQ + cn] = *(uint32_t*)hp;
            *(uint32_t*)&P1[(m + 8) * TPQ + cn] = *(uint32_t*)lp;
        }
    }
    #pragma unroll
    for (int r = 0; r < 8; r++) {
        int f = tid + 256 * r;                 // 2048: 2 arrays x 64 rows x 16 uint4
        int arr = f >> 10, pos = f & 1023;
        int row = pos >> 4, off = (pos & 15) * 8;
        const __nv_bfloat16* src = arr ? vlo : vhi;
        __nv_bfloat16* dstp = arr ? V1 : V0;
        *(uint4*)&dstp[row * TPS + off] = *(const uint4*)&src[(t0 + row) * VD + vc + off];
    }
    __syncthreads();

    // ---- Phase B: o = A @ v (K=64), warp grid 2m x 4n (tile 32x32) ----
    const int wm = wid & 1, wn = wid >> 1;
    float acc[2][4][4];
    #pragma unroll
    for (int i = 0; i < 2; i++)
        #pragma unroll
        for (int j = 0; j < 4; j++)
            #pragma unroll
            for (int r = 0; r < 4; r++) acc[i][j][r] = 0.f;

    #pragma unroll
    for (int kb = 0; kb < 64; kb += 16) {
        uint32_t ah[2][4], al[2][4], bh[2][4], bl[2][4];
        #pragma unroll
        for (int mt = 0; mt < 2; mt++) {
            uint32_t off = 2u * (uint32_t)((wm * 32 + mt * 16) * TPQ + kb + anl);
            ldsm_x4(ah[mt], P0b + off);
            ldsm_x4(al[mt], P1b + off);
        }
        #pragma unroll
        for (int p = 0; p < 2; p++) {
            uint32_t off = 2u * (uint32_t)((kb + bt_kr) * TPS + wn * 32 + p * 16 + bt_nc);
            ldsm_x4_t(bh[p], V0b + off);
            ldsm_x4_t(bl[p], V1b + off);
        }
        #pragma unroll
        for (int mt = 0; mt < 2; mt++)
            #pragma unroll
            for (int nt = 0; nt < 4; nt++) {
                const uint32_t* bhp = &bh[nt >> 1][(nt & 1) * 2];
                const uint32_t* blp = &bl[nt >> 1][(nt & 1) * 2];
                mma_bf16(acc[mt][nt], ah[mt], bhp);
                mma_bf16(acc[mt][nt], ah[mt], blp);
                mma_bf16(acc[mt][nt], al[mt], bhp);
            }
    }

    // ---- Phase C: o += q @ S (K=256) ----
    const size_t sb = (size_t)bhn * DKH * DVH;
    for (int d0 = 0; d0 < DKH; d0 += 64) {
        __syncthreads();
        #pragma unroll
        for (int r = 0; r < 4; r++) {
            int f = tid + 256 * r;             // 1024: 2 arrays x 512
            int arr = f >> 9, pos = f & 511;
            int row = pos >> 3, off = (pos & 7) * 8;
            const __nv_bfloat16* src = arr ? qlo : qhi;
            __nv_bfloat16* dstp = arr ? P3 : P2;
            *(uint4*)&dstp[row * TPQ + off] =
                *(const uint4*)&src[(t0 + row) * KD + kc + d0 + off];
        }
        #pragma unroll
        for (int r = 0; r < 8; r++) {
            int f = tid + 256 * r;             // 2048 float4: 64 rows x 32
            int row = f >> 5, off = (f & 31) * 4;
            float4 cv = *(const float4*)&C[sb + (size_t)(d0 + row) * DVH + dv0 + off];
            float cf[4] = { cv.x, cv.y, cv.z, cv.w };
            __nv_bfloat16 hh[4], ll[4];
            #pragma unroll
            for (int i = 0; i < 4; i++) {
                hh[i] = __float2bfloat16(cf[i]);
                ll[i] = __float2bfloat16(cf[i] - __bfloat162float(hh[i]));
            }
            *(uint2*)&V0[row * TPS + off] = *(uint2*)hh;
            *(uint2*)&V1[row * TPS + off] = *(uint2*)ll;
        }
        __syncthreads();
        #pragma unroll
        for (int kb = 0; kb < 64; kb += 16) {
            uint32_t ah[2][4], al[2][4], bh[2][4], bl[2][4];
            #pragma unroll
            for (int mt = 0; mt < 2; mt++) {
                uint32_t off = 2u * (uint32_t)((wm * 32 + mt * 16) * TPQ + kb + anl);
                ldsm_x4(ah[mt], P2b + off);
                ldsm_x4(al[mt], P3b + off);
            }
            #pragma unroll
            for (int p = 0; p < 2; p++) {
                uint32_t off = 2u * (uint32_t)((kb + bt_kr) * TPS + wn * 32 + p * 16 + bt_nc);
                ldsm_x4_t(bh[p], V0b + off);
                ldsm_x4_t(bl[p], V1b + off);
            }
            #pragma unroll
            for (int mt = 0; mt < 2; mt++)
                #pragma unroll
                for (int nt = 0; nt < 4; nt++) {
                    const uint32_t* bhp = &bh[nt >> 1][(nt & 1) * 2];
                    const uint32_t* blp = &bl[nt >> 1][(nt & 1) * 2];
                    mma_bf16(acc[mt][nt], ah[mt], bhp);
                    mma_bf16(acc[mt][nt], ah[mt], blp);
                    mma_bf16(acc[mt][nt], al[mt], bhp);
                }
        }
    }

    // ---- store o ----
    #pragma unroll
    for (int mt = 0; mt < 2; mt++) {
        size_t row = t0 + wm * 32 + mt * 16 + g;
        #pragma unroll
        for (int nt = 0; nt < 4; nt++) {
            int cc = vc + wn * 32 + nt * 8 + 2 * t;
            *(float2*)&o[row * VD + cc]       = make_float2(acc[mt][nt][0], acc[mt][nt][1]);
            *(float2*)&o[(row + 8) * VD + cc] = make_float2(acc[mt][nt][2], acc[mt][nt][3]);
        }
    }
}

// ---------------- rmsnorm * g_norm_weight * silu(g) -> bf16 split ----------------
__global__ __launch_bounds__(256) void post_kernel(
    const float* __restrict__ o, const float* __restrict__ g, const float* __restrict__ w,
    __nv_bfloat16* __restrict__ ohi, __nv_bfloat16* __restrict__ olo)
{
    const int t = blockIdx.x, h = blockIdx.y;
    const size_t base = (size_t)t * VD + (size_t)h * DVH;
    const int tid = threadIdx.x;

    float v0 = o[base + tid];
    float v1 = o[base + tid + 256];
    float ss = v0 * v0 + v1 * v1;
    #pragma unroll
    for (int off = 16; off > 0; off >>= 1)
        ss += __shfl_down_sync(0xffffffffu, ss, off);

    __shared__ float red[8];
    __shared__ float inv_s;
    if ((tid & 31) == 0) red[tid >> 5] = ss;
    __syncthreads();
    if (tid == 0) {
        float s = 0.f;
        #pragma unroll
        for (int wi = 0; wi < 8; wi++) s += red[wi];
        inv_s = rsqrtf(s * (1.f / DVH) + EPS_F);
    }
    __syncthreads();
    const float inv = inv_s;

    float g0 = g[base + tid];
    float g1 = g[base + tid + 256];
    float s0 = g0 / (1.f + expf(-g0));
    float s1 = g1 / (1.f + expf(-g1));
    float r0 = v0 * inv * w[tid]       * s0;
    float r1 = v1 * inv * w[tid + 256] * s1;

    __nv_bfloat16 h0 = __float2bfloat16(r0);
    __nv_bfloat16 h1 = __float2bfloat16(r1);
    ohi[base + tid]       = h0;
    ohi[base + tid + 256] = h1;
    olo[base + tid]       = __float2bfloat16(r0 - __bfloat162float(h0));
    olo[base + tid + 256] = __float2bfloat16(r1 - __bfloat162float(h1));
}

// ---------------- launch ----------------
extern "C" void kernel_launch(void* const* d_in, const int* in_sizes, int n_in,
                              void* d_out, int out_size)
{
    const float* x    = (const float*)d_in[0];
    const float* Wq   = (const float*)d_in[1];
    const float* Wk   = (const float*)d_in[2];
    const float* Wv   = (const float*)d_in[3];
    const float* Wgk1 = (const float*)d_in[4];
    const float* Wgk2 = (const float*)d_in[5];
    const float* bgk2 = (const float*)d_in[6];
    const float* Wg   = (const float*)d_in[7];
    const float* gnw  = (const float*)d_in[8];
    const float* Wo   = (const float*)d_in[9];
    float* out = (float*)d_out;

    float *q, *k, *v, *g, *gk, *o, *x16, *C;
    __nv_bfloat16 *xhi, *xlo, *wthi, *wtlo, *wohi, *wolo;
    cudaGetSymbolAddress((void**)&q,    d_q);
    cudaGetSymbolAddress((void**)&k,    d_k);
    cudaGetSymbolAddress((void**)&v,    d_v);
    cudaGetSymbolAddress((void**)&g,    d_gbuf);
    cudaGetSymbolAddress((void**)&gk,   d_gk);
    cudaGetSymbolAddress((void**)&o,    d_o);
    cudaGetSymbolAddress((void**)&x16,  d_x16);
    cudaGetSymbolAddress((void**)&C,    d_C);
    cudaGetSymbolAddress((void**)&xhi,  d_xhi);
    cudaGetSymbolAddress((void**)&xlo,  d_xlo);
    cudaGetSymbolAddress((void**)&wthi, d_wthi);
    cudaGetSymbolAddress((void**)&wtlo, d_wtlo);
    cudaGetSymbolAddress((void**)&wohi, d_wohi);
    cudaGetSymbolAddress((void**)&wolo, d_wolo);

    // ---- buffer aliasing (lifetimes verified against launch order) ----
    // x splits dead after qkvg -> host q/k splits
    __nv_bfloat16* qhi = xhi;
    __nv_bfloat16* khi = xhi + (size_t)TB * KD;
    __nv_bfloat16* qlo = xlo;
    __nv_bfloat16* klo = xlo + (size_t)TB * KD;
    // qkvg weight splits dead after qkvg -> host v splits
    __nv_bfloat16* vhi = wthi;
    __nv_bfloat16* vlo = wtlo;
    // fp32 q/k dead after prep -> host o splits (TB*VD*2B == TB*KD*4B exactly)
    __nv_bfloat16* ohi = (__nv_bfloat16*)q;
    __nv_bfloat16* olo = (__nv_bfloat16*)k;

    cudaFuncSetAttribute((const void*)qkvg_tc_kernel,
                         cudaFuncAttributeMaxDynamicSharedMemorySize, SMEM_DYN);
    cudaFuncSetAttribute((const void*)wo_tc_kernel,
                         cudaFuncAttributeMaxDynamicSharedMemorySize, SMEM_DYN);
    cudaFuncSetAttribute((const void*)chunk_kv_kernel,
                         cudaFuncAttributeMaxDynamicSharedMemorySize, CKV_SMEM);
    cudaFuncSetAttribute((const void*)gla_out_kernel,
                         cudaFuncAttributeMaxDynamicSharedMemorySize, GLA_SMEM);

    split_kernel<<<(size_t)TB * HDIM / 1024, 256>>>(x, xhi, xlo);
    tsplit_all_kernel<<<16384, 256>>>(Wq, Wk, Wv, Wg, Wo, wthi, wtlo, wohi, wolo);
    gk1_kernel<<<TB, 256>>>(x, Wgk1, x16);
    gk2_kernel<<<TB, 256>>>(x16, Wgk2, bgk2, gk);
    cumsum_kernel<<<BATCH * NCHUNK, 1024>>>(gk);
    qkvg_tc_kernel<<<dim3(QKVG_NT, TB / 128), 256, SMEM_DYN>>>(xhi, xlo, wthi, wtlo, q, k, v, g);

    split_kernel<<<(size_t)TB * VD / 1024, 256>>>(v, vhi, vlo);        // overwrites wthi/wtlo (dead)
    prep_kernel<<<(size_t)TB * KD / 1024, 256>>>(q, k, gk, qhi, qlo, khi, klo);  // overwrites xhi/xlo (dead)

    chunk_kv_kernel<<<dim3(16, BATCH * HNUM * NCHUNK), 256, CKV_SMEM>>>(khi, klo, vhi, vlo, gk, C);
    scan_kernel<<<dim3(16, BATCH * HNUM), 256>>>(gk, C);
    gla_out_kernel<<<dim3(4, BATCH * HNUM * NCHUNK), 256, GLA_SMEM>>>(qhi, qlo, khi, klo, vhi, vlo, C, o);

    post_kernel<<<dim3(TB, HNUM), 256>>>(o, g, gnw, ohi, olo);          // overwrites fp32 q/k (dead)
    wo_tc_kernel<<<dim3(HDIM / 128, TB / 128), 256, SMEM_DYN>>>(ohi, olo, wohi, wolo, out);
}

// round 17
// speedup vs baseline: 2.0804x; 1.1154x over previous
#include <cuda_runtime.h>
#include <cuda_bf16.h>
#include <cuda_fp16.h>
#include <math.h>
#include <stdint.h>

// ---------------- problem constants ----------------
#define BATCH   2
#define SEQ     2048
#define HDIM    2048
#define TB      4096
#define HNUM    4
#define DKH     256
#define DVH     512
#define KD      1024
#define VD      2048
#define CH      64
#define NCHUNK  32
#define SCALE   0.0625f
#define INV_GN  0.0625f
#define EPS_F   1e-5f

#define GEMM_K  2048
#define BKG     32
#define NITG    (GEMM_K / BKG)
#define QKVG_NT 48
#define TPAD    40
#define TS      (128 * TPAD)

// GLA HMMA tile pads (row stride ≡ 4 banks -> conflict-free ldsm)
#define TPK     136
#define TPV     72
#define TPQ     72
#define TPS     136

// ---------------- device scratch ----------------
__device__ float d_q   [(size_t)TB * KD];   // reused as oh (fp16) after prep
__device__ float d_k   [(size_t)TB * KD];
__device__ float d_v   [(size_t)TB * VD];   // reused as qlo|klo (bf16) after v-split
__device__ float d_gbuf[(size_t)TB * VD];
__device__ float d_gk  [(size_t)TB * KD];
__device__ float d_o   [(size_t)TB * VD];
__device__ float d_x16 [(size_t)TB * 16];
__device__ float d_C   [(size_t)BATCH * HNUM * NCHUNK * DKH * DVH];

__device__ __half d_xh  [(size_t)TB * HDIM];                        // reused as qhi|khi (bf16)
__device__ __half d_wthi[(size_t)(2 * KD + 2 * VD) * GEMM_K];       // reused as vhi (bf16)
__device__ __half d_wtlo[(size_t)(2 * KD + 2 * VD) * GEMM_K];       // reused as vlo (bf16)
__device__ __half d_wohi[(size_t)HDIM * GEMM_K];
__device__ __half d_wolo[(size_t)HDIM * GEMM_K];

// ---------------- MMA / cp.async / ldmatrix helpers ----------------
__device__ __forceinline__ void mma_bf16(float* c, const uint32_t* a, const uint32_t* b) {
    asm volatile(
        "mma.sync.aligned.m16n8k16.row.col.f32.bf16.bf16.f32 "
        "{%0,%1,%2,%3}, {%4,%5,%6,%7}, {%8,%9}, {%0,%1,%2,%3};"
        : "+f"(c[0]), "+f"(c[1]), "+f"(c[2]), "+f"(c[3])
        : "r"(a[0]), "r"(a[1]), "r"(a[2]), "r"(a[3]), "r"(b[0]), "r"(b[1]));
}
__device__ __forceinline__ void mma_f16(float* c, const uint32_t* a, const uint32_t* b) {
    asm volatile(
        "mma.sync.aligned.m16n8k16.row.col.f32.f16.f16.f32 "
        "{%0,%1,%2,%3}, {%4,%5,%6,%7}, {%8,%9}, {%0,%1,%2,%3};"
        : "+f"(c[0]), "+f"(c[1]), "+f"(c[2]), "+f"(c[3])
        : "r"(a[0]), "r"(a[1]), "r"(a[2]), "r"(a[3]), "r"(b[0]), "r"(b[1]));
}
__device__ __forceinline__ void ldsm_x4(uint32_t* r, uint32_t addr) {
    asm volatile("ldmatrix.sync.aligned.m8n8.x4.shared.b16 {%0,%1,%2,%3}, [%4];"
        : "=r"(r[0]), "=r"(r[1]), "=r"(r[2]), "=r"(r[3]) : "r"(addr));
}
__device__ __forceinline__ void ldsm_x4_t(uint32_t* r, uint32_t addr) {
    asm volatile("ldmatrix.sync.aligned.m8n8.x4.trans.shared.b16 {%0,%1,%2,%3}, [%4];"
        : "=r"(r[0]), "=r"(r[1]), "=r"(r[2]), "=r"(r[3]) : "r"(addr));
}
__device__ __forceinline__ void cp_async16(uint32_t dst, const void* src) {
    asm volatile("cp.async.cg.shared.global [%0], [%1], 16;" :: "r"(dst), "l"(src));
}
__device__ __forceinline__ void cp_commit() { asm volatile("cp.async.commit_group;"); }
__device__ __forceinline__ void cp_wait0()  { asm volatile("cp.async.wait_group 0;" ::: "memory"); }
__device__ __forceinline__ uint32_t smem_u32(const void* p) {
    return (uint32_t)__cvta_generic_to_shared(p);
}

// ---------------- fp32 -> fp16 (single, rounded) ----------------
__global__ __launch_bounds__(256) void cvth_kernel(
    const float* __restrict__ in, __half* __restrict__ out)
{
    size_t i = (size_t)blockIdx.x * 256 + threadIdx.x;
    float4 v = ((const float4*)in)[i];
    __half h[4] = { __float2half(v.x), __float2half(v.y),
                    __float2half(v.z), __float2half(v.w) };
    *(uint2*)&out[i * 4] = *(uint2*)h;
}

// ---------------- fp32 -> (hi, lo) bf16 split (GLA v) ----------------
__global__ __launch_bounds__(256) void split_kernel(
    const float* __restrict__ in, __nv_bfloat16* __restrict__ hi,
    __nv_bfloat16* __restrict__ lo)
{
    size_t i = (size_t)blockIdx.x * 256 + threadIdx.x;
    float4 v = ((const float4*)in)[i];
    __nv_bfloat16 h[4], l[4];
    float f[4] = { v.x, v.y, v.z, v.w };
    #pragma unroll
    for (int j = 0; j < 4; j++) {
        h[j] = __float2bfloat16(f[j]);
        l[j] = __float2bfloat16(f[j] - __bfloat162float(h[j]));
    }
    *(uint2*)&hi[i * 4] = *(uint2*)h;
    *(uint2*)&lo[i * 4] = *(uint2*)l;
}

// ---------------- transpose + fp16 split for ALL weights in ONE launch ----------------
__global__ __launch_bounds__(256) void tsplit_all_kernel(
    const float* __restrict__ Wq, const float* __restrict__ Wk,
    const float* __restrict__ Wv, const float* __restrict__ Wg,
    const float* __restrict__ Wo,
    __half* __restrict__ wthi, __half* __restrict__ wtlo,
    __half* __restrict__ wohi, __half* __restrict__ wolo)
{
    int idx = blockIdx.x;
    const float* W; __half *hiT, *loT; int N, tile;
    if (idx < 2048)       { W = Wq; hiT = wthi;                                  loT = wtlo;                                  N = KD; tile = idx; }
    else if (idx < 4096)  { W = Wk; hiT = wthi + (size_t)KD * GEMM_K;            loT = wtlo + (size_t)KD * GEMM_K;            N = KD; tile = idx - 2048; }
    else if (idx < 8192)  { W = Wv; hiT = wthi + (size_t)2 * KD * GEMM_K;        loT = wtlo + (size_t)2 * KD * GEMM_K;        N = VD; tile = idx - 4096; }
    else if (idx < 12288) { W = Wg; hiT = wthi + (size_t)(2 * KD + VD) * GEMM_K; loT = wtlo + (size_t)(2 * KD + VD) * GEMM_K; N = VD; tile = idx - 8192; }
    else                  { W = Wo; hiT = wohi;                                  loT = wolo;                                  N = HDIM; tile = idx - 12288; }
    const int ntiles = N / 32;
    const int n0 = (tile % ntiles) * 32, k0 = (tile / ntiles) * 32;

    __shared__ float t[32][33];
    const int tx = threadIdx.x & 31, ty = threadIdx.x >> 5;
    #pragma unroll
    for (int j = 0; j < 4; j++)
        t[ty + 8 * j][tx] = W[(size_t)(k0 + ty + 8 * j) * N + n0 + tx];
    __syncthreads();
    #pragma unroll
    for (int j = 0; j < 4; j++) {
        float v = t[tx][ty + 8 * j];
        __half h = __float2half(v);
        size_t oidx = (size_t)(n0 + ty + 8 * j) * GEMM_K + k0 + tx;
        hiT[oidx] = h;
        loT[oidx] = __float2half(v - __half2float(h));
    }
}

// ---------------- fp16 HMMA GEMM: A single, B (hi,lo), 2 products ----------------
// regions per buffer: A @0, Bh @TS, Bl @2TS ; buffers stride 3*TS
__device__ void gemm_mma_body(
    const __half* __restrict__ A, const __half* __restrict__ Bhi,
    const __half* __restrict__ Blo,
    int m0, int nrow0, float* __restrict__ dst, int ldc, int col0)
{
    extern __shared__ __align__(16) unsigned char SRAW[];
    __half* S = (__half*)SRAW;

    const int tid  = threadIdx.x;
    const int lane = tid & 31, wid = tid >> 5;
    const int wm = wid & 1, wn = wid >> 1;
    const int g = lane >> 2, t = lane & 3;
    const uint32_t Sb = smem_u32(S);

    const int a_lane = (lane & 15) * TPAD + (lane >> 4) * 8;
    const int b_lane = ((lane >> 4) * 8 + (lane & 7)) * TPAD + ((lane >> 3) & 1) * 8;

    float acc[4][4][4];
    #pragma unroll
    for (int i = 0; i < 4; i++)
        #pragma unroll
        for (int j = 0; j < 4; j++)
            #pragma unroll
            for (int r = 0; r < 4; r++) acc[i][j][r] = 0.f;

    auto tile_load = [&](const __half* __restrict__ src, int row0, int k0, int sb) {
        #pragma unroll
        for (int j = 0; j < 2; j++) {
            int f = tid + 256 * j;
            int row = f >> 2, c4 = f & 3;
            cp_async16(smem_u32(&S[sb + row * TPAD + c4 * 8]),
                       src + (size_t)(row0 + row) * GEMM_K + k0 + c4 * 8);
        }
    };

    tile_load(A,   m0, 0, 0);
    tile_load(Bhi, nrow0, 0, TS);
    tile_load(Blo, nrow0, 0, 2 * TS);
    cp_commit();

    for (int it = 0; it < NITG; it++) {
        cp_wait0();
        __syncthreads();
        const int sb = (it & 1) * 3 * TS;
        if (it + 1 < NITG) {
            const int nb = ((it + 1) & 1) * 3 * TS;
            const int k0 = (it + 1) * BKG;
            tile_load(A,   m0, k0, nb);
            tile_load(Bhi, nrow0, k0, nb + TS);
            tile_load(Blo, nrow0, k0, nb + 2 * TS);
            cp_commit();
        }
        #pragma unroll
        for (int ks = 0; ks < 2; ks++) {
            const int kc = ks * 16;
            uint32_t ah[4][4], bh[2][4], bl[2][4];
            #pragma unroll
            for (int mt = 0; mt < 4; mt++) {
                uint32_t addr = Sb + 2u * (uint32_t)(sb + (wm * 64 + mt * 16) * TPAD + kc + a_lane);
                ldsm_x4(ah[mt], addr);
            }
            #pragma unroll
            for (int p = 0; p < 2; p++) {
                uint32_t addr = Sb + 2u * (uint32_t)(sb + TS + (wn * 32 + p * 16) * TPAD + kc + b_lane);
                ldsm_x4(bh[p], addr);
                ldsm_x4(bl[p], addr + 2u * (uint32_t)TS);
            }
            #pragma unroll
            for (int mt = 0; mt < 4; mt++)
                #pragma unroll
                for (int nt = 0; nt < 4; nt++) {
                    const uint32_t* bhp = &bh[nt >> 1][(nt & 1) * 2];
                    const uint32_t* blp = &bl[nt >> 1][(nt & 1) * 2];
                    mma_f16(acc[mt][nt], ah[mt], bhp);
                    mma_f16(acc[mt][nt], ah[mt], blp);
                }
        }
        __syncthreads();
    }

    #pragma unroll
    for (int mt = 0; mt < 4; mt++) {
        int r = m0 + wm * 64 + mt * 16 + g;
        #pragma unroll
        for (int nt = 0; nt < 4; nt++) {
            int cc = col0 + wn * 32 + nt * 8 + 2 * t;
            *(float2*)&dst[(size_t)r * ldc + cc]       = make_float2(acc[mt][nt][0], acc[mt][nt][1]);
            *(float2*)&dst[(size_t)(r + 8) * ldc + cc] = make_float2(acc[mt][nt][2], acc[mt][nt][3]);
        }
    }
}

#define SMEM_DYN (6 * TS * 2)   // 61440 bytes

__global__ __launch_bounds__(256) void qkvg_tc_kernel(
    const __half* __restrict__ xh,
    const __half* __restrict__ wthi, const __half* __restrict__ wtlo,
    float* __restrict__ q, float* __restrict__ k,
    float* __restrict__ v, float* __restrict__ g)
{
    const int nt = blockIdx.x;
    const int m0 = blockIdx.y * 128;
    float* dst; int ldc, col0;
    if (nt < 8)       { dst = q; ldc = KD; col0 = nt * 128; }
    else if (nt < 16) { dst = k; ldc = KD; col0 = (nt - 8) * 128; }
    else if (nt < 32) { dst = v; ldc = VD; col0 = (nt - 16) * 128; }
    else              { dst = g; ldc = VD; col0 = (nt - 32) * 128; }
    gemm_mma_body(xh, wthi, wtlo, m0, nt * 128, dst, ldc, col0);
}

__global__ __launch_bounds__(256) void wo_tc_kernel(
    const __half* __restrict__ oh,
    const __half* __restrict__ wohi, const __half* __restrict__ wolo,
    float* __restrict__ out)
{
    gemm_mma_body(oh, wohi, wolo, blockIdx.y * 128, blockIdx.x * 128, out, HDIM, blockIdx.x * 128);
}

// ---------------- gate path ----------------
__global__ __launch_bounds__(256) void gk1_kernel(
    const float* __restrict__ x, const float* __restrict__ W, float* __restrict__ out)
{
    const int t = blockIdx.x;
    const float* xr = x + (size_t)t * HDIM;
    float acc[16];
    #pragma unroll
    for (int j = 0; j < 16; j++) acc[j] = 0.f;
    for (int i = threadIdx.x; i < HDIM; i += 256) {
        float xv = xr[i];
        const float* wr = W + (size_t)i * 16;
        #pragma unroll
        for (int j = 0; j < 16; j++) acc[j] = fmaf(xv, wr[j], acc[j]);
    }
    #pragma unroll
    for (int j = 0; j < 16; j++)
        #pragma unroll
        for (int off = 16; off > 0; off >>= 1)
            acc[j] += __shfl_down_sync(0xffffffffu, acc[j], off);
    __shared__ float red[8][16];
    const int warp = threadIdx.x >> 5, lane = threadIdx.x & 31;
    if (lane == 0) {
        #pragma unroll
        for (int j = 0; j < 16; j++) red[warp][j] = acc[j];
    }
    __syncthreads();
    if (threadIdx.x < 16) {
        float s = 0.f;
        #pragma unroll
        for (int w = 0; w < 8; w++) s += red[w][threadIdx.x];
        out[(size_t)t * 16 + threadIdx.x] = s;
    }
}

__global__ __launch_bounds__(256) void gk2_kernel(
    const float* __restrict__ x16, const float* __restrict__ W2,
    const float* __restrict__ bias, float* __restrict__ gk)
{
    const int t = blockIdx.x;
    __shared__ float xs[16];
    if (threadIdx.x < 16) xs[threadIdx.x] = x16[(size_t)t * 16 + threadIdx.x];
    __syncthreads();
    for (int j = threadIdx.x; j < KD; j += 256) {
        float s = bias[j];
        #pragma unroll
        for (int r = 0; r < 16; r++) s = fmaf(xs[r], W2[(size_t)r * KD + j], s);
        float ls = fminf(s, 0.f) - log1pf(expf(-fabsf(s)));
        gk[(size_t)t * KD + j] = ls * INV_GN;
    }
}

__global__ __launch_bounds__(1024) void cumsum_kernel(float* __restrict__ gk)
{
    const int bn = blockIdx.x;
    const int b = bn / NCHUNK, n = bn % NCHUNK;
    const size_t t0 = (size_t)b * SEQ + (size_t)n * CH;
    const int c = threadIdx.x;
    float s = 0.f;
    for (int i = 0; i < CH; i++) {
        size_t idx = (t0 + i) * KD + c;
        s += gk[idx];
        gk[idx] = s;
    }
}

// ---------------- prep: gated q,k -> bf16 (hi,lo) splits (GLA inputs) ----------------
__global__ __launch_bounds__(256) void prep_kernel(
    const float* __restrict__ q, const float* __restrict__ k, const float* __restrict__ gc,
    __nv_bfloat16* __restrict__ qhi, __nv_bfloat16* __restrict__ qlo,
    __nv_bfloat16* __restrict__ khi, __nv_bfloat16* __restrict__ klo)
{
    size_t i = (size_t)blockIdx.x * 256 + threadIdx.x;
    float4 qv = ((const float4*)q)[i];
    float4 kv = ((const float4*)k)[i];
    float4 gv = ((const float4*)gc)[i];
    float qf[4], kf[4];
    float e0 = expf(gv.x), e1 = expf(gv.y), e2 = expf(gv.z), e3 = expf(gv.w);
    qf[0] = qv.x * e0 * SCALE; qf[1] = qv.y * e1 * SCALE;
    qf[2] = qv.z * e2 * SCALE; qf[3] = qv.w * e3 * SCALE;
    kf[0] = kv.x / e0; kf[1] = kv.y / e1; kf[2] = kv.z / e2; kf[3] = kv.w / e3;
    __nv_bfloat16 qh[4], ql[4], kh[4], kl[4];
    #pragma unroll
    for (int j = 0; j < 4; j++) {
        qh[j] = __float2bfloat16(qf[j]);
        ql[j] = __float2bfloat16(qf[j] - __bfloat162float(qh[j]));
        kh[j] = __float2bfloat16(kf[j]);
        kl[j] = __float2bfloat16(kf[j] - __bfloat162float(kh[j]));
    }
    *(uint2*)&qhi[i * 4] = *(uint2*)qh;
    *(uint2*)&qlo[i * 4] = *(uint2*)ql;
    *(uint2*)&khi[i * 4] = *(uint2*)kh;
    *(uint2*)&klo[i * 4] = *(uint2*)kl;
}

// ---------------- GLA phase 1 (HMMA bf16): C[bhn] = k_dec^T @ v ----------------
#define CKV_SMEM ((2 * 64 * TPK + 2 * 64 * TPV) * 2)   // 53248 B
__global__ __launch_bounds__(256) void chunk_kv_kernel(
    const __nv_bfloat16* __restrict__ khi, const __nv_bfloat16* __restrict__ klo,
    const __nv_bfloat16* __restrict__ vhi, const __nv_bfloat16* __restrict__ vlo,
    const float* __restrict__ gc, float* __restrict__ C)
{
    extern __shared__ __align__(16) unsigned char SRAW[];
    __nv_bfloat16* SM = (__nv_bfloat16*)SRAW;
    __nv_bfloat16* kdh = SM;
    __nv_bfloat16* kdl = SM + 64 * TPK;
    __nv_bfloat16* vsh = SM + 2 * 64 * TPK;
    __nv_bfloat16* vsl = SM + 2 * 64 * TPK + 64 * TPV;
    __shared__ float egl[128];

    const int bhn = blockIdx.y;
    const int n = bhn % NCHUNK;
    const int bh = bhn / NCHUNK;
    const int h = bh % HNUM, b = bh / HNUM;
    const int dk0 = (blockIdx.x >> 3) * 128;
    const int dv0 = (blockIdx.x & 7) * 64;
    const size_t t0 = (size_t)b * SEQ + (size_t)n * CH;
    const int kc = h * DKH + dk0;
    const int vc = h * DVH + dv0;
    const int tid = threadIdx.x;

    if (tid < 128) egl[tid] = expf(gc[(t0 + 63) * KD + kc + tid]);
    __syncthreads();

    #pragma unroll
    for (int r = 0; r < 4; r++) {
        int f = tid + 256 * r;
        int row = f >> 4, off = (f & 15) * 8;
        uint4 hv = *(const uint4*)&khi[(t0 + row) * KD + kc + off];
        uint4 lv = *(const uint4*)&klo[(t0 + row) * KD + kc + off];
        const __nv_bfloat16* hp = (const __nv_bfloat16*)&hv;
        const __nv_bfloat16* lp = (const __nv_bfloat16*)&lv;
        __nv_bfloat16 oh[8], ol[8];
        #pragma unroll
        for (int i = 0; i < 8; i++) {
            float x = (__bfloat162float(hp[i]) + __bfloat162float(lp[i])) * egl[off + i];
            __nv_bfloat16 hh = __float2bfloat16(x);
            oh[i] = hh; ol[i] = __float2bfloat16(x - __bfloat162float(hh));
        }
        *(uint4*)&kdh[row * TPK + off] = *(uint4*)oh;
        *(uint4*)&kdl[row * TPK + off] = *(uint4*)ol;
    }
    #pragma unroll
    for (int r = 0; r < 2; r++) {
        int f = tid + 256 * r;
        int row = f >> 3, off = (f & 7) * 8;
        *(uint4*)&vsh[row * TPV + off] = *(const uint4*)&vhi[(t0 + row) * VD + vc + off];
        *(uint4*)&vsl[row * TPV + off] = *(const uint4*)&vlo[(t0 + row) * VD + vc + off];
    }
    __syncthreads();

    const int lane = tid & 31, wid = tid >> 5;
    const int wm = wid & 3, wn = wid >> 2;
    const int g = lane >> 2, t = lane & 3;
    const int sub = lane >> 3, rr = lane & 7;
    const int a_kr = ((sub >> 1) & 1) * 8 + rr;
    const int a_mc = (sub & 1) * 8;
    const int b_kr = (sub & 1) * 8 + rr;
    const int b_nc = (sub >> 1) * 8;
    const uint32_t kdh_b = smem_u32(kdh), kdl_b = smem_u32(kdl);
    const uint32_t vsh_b = smem_u32(vsh), vsl_b = smem_u32(vsl);

    float acc[2][4][4];
    #pragma unroll
    for (int i = 0; i < 2; i++)
        #pragma unroll
        for (int j = 0; j < 4; j++)
            #pragma unroll
            for (int r = 0; r < 4; r++) acc[i][j][r] = 0.f;

    #pragma unroll
    for (int kb = 0; kb < 64; kb += 16) {
        uint32_t ah[2][4], al[2][4], bh[2][4], bl[2][4];
        #pragma unroll
        for (int mt = 0; mt < 2; mt++) {
            uint32_t off = 2u * (uint32_t)((kb + a_kr) * TPK + wm * 32 + mt * 16 + a_mc);
            ldsm_x4_t(ah[mt], kdh_b + off);
            ldsm_x4_t(al[mt], kdl_b + off);
        }
        #pragma unroll
        for (int p = 0; p < 2; p++) {
            uint32_t off = 2u * (uint32_t)((kb + b_kr) * TPV + wn * 32 + p * 16 + b_nc);
            ldsm_x4_t(bh[p], vsh_b + off);
            ldsm_x4_t(bl[p], vsl_b + off);
        }
        #pragma unroll
        for (int mt = 0; mt < 2; mt++)
            #pragma unroll
            for (int nt = 0; nt < 4; nt++) {
                const uint32_t* bhp = &bh[nt >> 1][(nt & 1) * 2];
                const uint32_t* blp = &bl[nt >> 1][(nt & 1) * 2];
                mma_bf16(acc[mt][nt], ah[mt], bhp);
                mma_bf16(acc[mt][nt], ah[mt], blp);
                mma_bf16(acc[mt][nt], al[mt], bhp);
            }
    }

    const size_t cbase = (size_t)bhn * DKH * DVH;
    #pragma unroll
    for (int mt = 0; mt < 2; mt++) {
        int row = dk0 + wm * 32 + mt * 16 + g;
        #pragma unroll
        for (int nt = 0; nt < 4; nt++) {
            int cc = dv0 + wn * 32 + nt * 8 + 2 * t;
            *(float2*)&C[cbase + (size_t)row * DVH + cc]       = make_float2(acc[mt][nt][0], acc[mt][nt][1]);
            *(float2*)&C[cbase + (size_t)(row + 8) * DVH + cc] = make_float2(acc[mt][nt][2], acc[mt][nt][3]);
        }
    }
}

// ---------------- GLA scan (fp32 C) ----------------
__global__ __launch_bounds__(256) void scan_kernel(
    const float* __restrict__ gc, float* __restrict__ C)
{
    const int bh = blockIdx.y;
    const int h = bh % HNUM, b = bh / HNUM;
    const int dv0 = blockIdx.x * 32;
    const int tid = threadIdx.x;
    __shared__ float Ssm[256 * 32];
    __shared__ float eg[256];
    #pragma unroll
    for (int r = 0; r < 32; r++) Ssm[tid + 256 * r] = 0.f;
    for (int n = 0; n < NCHUNK; n++) {
        const size_t t0 = (size_t)b * SEQ + (size_t)n * CH;
        eg[tid] = expf(gc[(t0 + 63) * KD + h * DKH + tid]);
        __syncthreads();
        const size_t base = (size_t)((bh * NCHUNK) + n) * DKH * DVH;
        #pragma unroll
        for (int r = 0; r < 32; r++) {
            int e = tid + 256 * r;
            int dk = e >> 5;
            int dv = dv0 + (e & 31);
            size_t idx = base + (size_t)dk * DVH + dv;
            float cv = C[idx];
            float s  = Ssm[e];
            C[idx] = s;
            Ssm[e] = fmaf(s, eg[dk], cv);
        }
        __syncthreads();
    }
}

// ---------------- GLA phase 2 (HMMA bf16): o = tril(q k^T) @ v + q @ S ----------------
#define GLA_SMEM ((4 * 64 * TPQ + 2 * 64 * TPS) * 2)   // 71680 B
__global__ __launch_bounds__(256) void gla_out_kernel(
    const __nv_bfloat16* __restrict__ qhi, const __nv_bfloat16* __restrict__ qlo,
    const __nv_bfloat16* __restrict__ khi, const __nv_bfloat16* __restrict__ klo,
    const __nv_bfloat16* __restrict__ vhi, const __nv_bfloat16* __restrict__ vlo,
    const float* __restrict__ C, float* __restrict__ o)
{
    extern __shared__ __align__(16) unsigned char SRAW[];
    __nv_bfloat16* SM = (__nv_bfloat16*)SRAW;
    __nv_bfloat16* P0 = SM;
    __nv_bfloat16* P1 = SM + 64 * TPQ;
    __nv_bfloat16* P2 = SM + 2 * 64 * TPQ;
    __nv_bfloat16* P3 = SM + 3 * 64 * TPQ;
    __nv_bfloat16* V0 = SM + 4 * 64 * TPQ;
    __nv_bfloat16* V1 = SM + 4 * 64 * TPQ + 64 * TPS;

    const int bhn = blockIdx.y;
    const int n = bhn % NCHUNK;
    const int bh = bhn / NCHUNK;
    const int h = bh % HNUM, b = bh / HNUM;
    const int dv0 = blockIdx.x * 128;
    const size_t t0 = (size_t)b * SEQ + (size_t)n * CH;
    const int kc = h * DKH;
    const int vc = h * DVH + dv0;
    const int tid = threadIdx.x;
    const int lane = tid & 31, wid = tid >> 5;
    const int g = lane >> 2, t = lane & 3;

    const int anl = (lane & 15) * TPQ + (lane >> 4) * 8;
    const int bnl = ((lane >> 4) * 8 + (lane & 7)) * TPQ + ((lane >> 3) & 1) * 8;
    const int sub = lane >> 3, rr = lane & 7;
    const int bt_kr = (sub & 1) * 8 + rr;
    const int bt_nc = (sub >> 1) * 8;

    const uint32_t P0b = smem_u32(P0), P1b = smem_u32(P1);
    const uint32_t P2b = smem_u32(P2), P3b = smem_u32(P3);
    const uint32_t V0b = smem_u32(V0), V1b = smem_u32(V1);

    const int wmA = wid & 1, wnA = wid >> 1;
    float accA[2][2][4];
    #pragma unroll
    for (int i = 0; i < 2; i++)
        #pragma unroll
        for (int j = 0; j < 2; j++)
            #pragma unroll
            for (int r = 0; r < 4; r++) accA[i][j][r] = 0.f;

    for (int d0 = 0; d0 < DKH; d0 += 64) {
        #pragma unroll
        for (int r = 0; r < 8; r++) {
            int f = tid + 256 * r;
            int arr = f >> 9, pos = f & 511;
            int row = pos >> 3, off = (pos & 7) * 8;
            const __nv_bfloat16* src = (arr == 0) ? qhi : (arr == 1) ? qlo : (arr == 2) ? khi : klo;
            __nv_bfloat16* dstp = (arr == 0) ? P0 : (arr == 1) ? P1 : (arr == 2) ? P2 : P3;
            *(uint4*)&dstp[row * TPQ + off] =
                *(const uint4*)&src[(t0 + row) * KD + kc + d0 + off];
        }
        __syncthreads();
        #pragma unroll
        for (int kb = 0; kb < 64; kb += 16) {
            uint32_t ah[2][4], al[2][4], bhv[4], blv[4];
            #pragma unroll
            for (int mt = 0; mt < 2; mt++) {
                uint32_t off = 2u * (uint32_t)((wmA * 32 + mt * 16) * TPQ + kb + anl);
                ldsm_x4(ah[mt], P0b + off);
                ldsm_x4(al[mt], P1b + off);
            }
            {
                uint32_t off = 2u * (uint32_t)(wnA * 16 * TPQ + kb + bnl);
                ldsm_x4(bhv, P2b + off);
                ldsm_x4(blv, P3b + off);
            }
            #pragma unroll
            for (int mt = 0; mt < 2; mt++)
                #pragma unroll
                for (int nt = 0; nt < 2; nt++) {
                    const uint32_t* bhp = &bhv[nt * 2];
                    const uint32_t* blp = &blv[nt * 2];
                    mma_bf16(accA[mt][nt], ah[mt], bhp);
                    mma_bf16(accA[mt][nt], ah[mt], blp);
                    mma_bf16(accA[mt][nt], al[mt], bhp);
                }
        }
        __syncthreads();
    }

    #pragma unroll
    for (int mt = 0; mt < 2; mt++) {
        #pragma unroll
        for (int nt = 0; nt < 2; nt++) {
            int m = wmA * 32 + mt * 16 + g;
            int cn = wnA * 16 + nt * 8 + 2 * t;
            float v0 = (m >= cn) ? accA[mt][nt][0] : 0.f;
            float v1 = (m >= cn + 1) ? accA[mt][nt][1] : 0.f;
            float v2 = (m + 8 >= cn) ? accA[mt][nt][2] : 0.f;
            float v3 = (m + 8 >= cn + 1) ? accA[mt][nt][3] : 0.f;
            __nv_bfloat16 hp[2], lp[2];
            hp[0] = __float2bfloat16(v0); lp[0] = __float2bfloat16(v0 - __bfloat162float(hp[0]));
            hp[1] = __float2bfloat16(v1); lp[1] = __float2bfloat16(v1 - __bfloat162float(hp[1]));
            *(uint32_t*)&P0[m * TPQ + cn] = *(uint32_t*)hp;
            *(uint32_t*)&P1[m * TPQ + cn] = *(uint32_t*)lp;
            hp[0] = __float2bfloat16(v2); lp[0] = __float2bfloat16(v2 - __bfloat162float(hp[0]));
            hp[1] = __float2bfloat16(v3); lp[1] = __float2bfloat16(v3 - __bfloat162float(hp[1]));
            *(uint32_t*)&P0[(m + 8) * TPQ + cn] = *(uint32_t*)hp;
            *(uint32_t*)&P1[(m + 8) * TPQ + cn] = *(uint32_t*)lp;
        }
    }
    #pragma unroll
    for (int r = 0; r < 8; r++) {
        int f = tid + 256 * r;
        int arr = f >> 10, pos = f & 1023;
        int row = pos >> 4, off = (pos & 15) * 8;
        const __nv_bfloat16* src = arr ? vlo : vhi;
        __nv_bfloat16* dstp = arr ? V1 : V0;
        *(uint4*)&dstp[row * TPS + off] = *(const uint4*)&src[(t0 + row) * VD + vc + off];
    }
    __syncthreads();

    const int wm = wid & 1, wn = wid >> 1;
    float acc[2][4][4];
    #pragma unroll
    for (int i = 0; i < 2; i++)
        #pragma unroll
        for (int j = 0; j < 4; j++)
            #pragma unroll
            for (int r = 0; r < 4; r++) acc[i][j][r] = 0.f;

    #pragma unroll
    for (int kb = 0; kb < 64; kb += 16) {
        uint32_t ah[2][4], al[2][4], bh[2][4], bl[2][4];
        #pragma unroll
        for (int mt = 0; mt < 2; mt++) {
            uint32_t off = 2u * (uint32_t)((wm * 32 + mt * 16) * TPQ + kb + anl);
            ldsm_x4(ah[mt], P0b + off);
            ldsm_x4(al[mt], P1b + off);
        }
        #pragma unroll
        for (int p = 0; p < 2; p++) {
            uint32_t off = 2u * (uint32_t)((kb + bt_kr) * TPS + wn * 32 + p * 16 + bt_nc);
            ldsm_x4_t(bh[p], V0b + off);
            ldsm_x4_t(bl[p], V1b + off);
        }
        #pragma unroll
        for (int mt = 0; mt < 2; mt++)
            #pragma unroll
            for (int nt = 0; nt < 4; nt++) {
                const uint32_t* bhp = &bh[nt >> 1][(nt & 1) * 2];
                const uint32_t* blp = &bl[nt >> 1][(nt & 1) * 2];
                mma_bf16(acc[mt][nt], ah[mt], bhp);
                mma_bf16(acc[mt][nt], ah[mt], blp);
                mma_bf16(acc[mt][nt], al[mt], bhp);
            }
    }

    const size_t sb = (size_t)bhn * DKH * DVH;
    for (int d0 = 0; d0 < DKH; d0 += 64) {
        __syncthreads();
        #pragma unroll
        for (int r = 0; r < 4; r++) {
            int f = tid + 256 * r;
            int arr = f >> 9, pos = f & 511;
            int row = pos >> 3, off = (pos & 7) * 8;
            const __nv_bfloat16* src = arr ? qlo : qhi;
            __nv_bfloat16* dstp = arr ? P3 : P2;
            *(uint4*)&dstp[row * TPQ + off] =
                *(const uint4*)&src[(t0 + row) * KD + kc + d0 + off];
        }
        #pragma unroll
        for (int r = 0; r < 8; r++) {
            int f = tid + 256 * r;
            int row = f >> 5, off = (f & 31) * 4;
            float4 cv = *(const float4*)&C[sb + (size_t)(d0 + row) * DVH + dv0 + off];
            float cf[4] = { cv.x, cv.y, cv.z, cv.w };
            __nv_bfloat16 hh[4], ll[4];
            #pragma unroll
            for (int i = 0; i < 4; i++) {
                hh[i] = __float2bfloat16(cf[i]);
                ll[i] = __float2bfloat16(cf[i] - __bfloat162float(hh[i]));
            }
            *(uint2*)&V0[row * TPS + off] = *(uint2*)hh;
            *(uint2*)&V1[row * TPS + off] = *(uint2*)ll;
        }
        __syncthreads();
        #pragma unroll
        for (int kb = 0; kb < 64; kb += 16) {
            uint32_t ah[2][4], al[2][4], bh[2][4], bl[2][4];
            #pragma unroll
            for (int mt = 0; mt < 2; mt++) {
                uint32_t off = 2u * (uint32_t)((wm * 32 + mt * 16) * TPQ + kb + anl);
                ldsm_x4(ah[mt], P2b + off);
                ldsm_x4(al[mt], P3b + off);
            }
            #pragma unroll
            for (int p = 0; p < 2; p++) {
                uint32_t off = 2u * (uint32_t)((kb + bt_kr) * TPS + wn * 32 + p * 16 + bt_nc);
                ldsm_x4_t(bh[p], V0b + off);
                ldsm_x4_t(bl[p], V1b + off);
            }
            #pragma unroll
            for (int mt = 0; mt < 2; mt++)
                #pragma unroll
                for (int nt = 0; nt < 4; nt++) {
                    const uint32_t* bhp = &bh[nt >> 1][(nt & 1) * 2];
                    const uint32_t* blp = &bl[nt >> 1][(nt & 1) * 2];
                    mma_bf16(acc[mt][nt], ah[mt], bhp);
                    mma_bf16(acc[mt][nt], ah[mt], blp);
                    mma_bf16(acc[mt][nt], al[mt], bhp);
                }
        }
    }

    #pragma unroll
    for (int mt = 0; mt < 2; mt++) {
        size_t row = t0 + wm * 32 + mt * 16 + g;
        #pragma unroll
        for (int nt = 0; nt < 4; nt++) {
            int cc = vc + wn * 32 + nt * 8 + 2 * t;
            *(float2*)&o[row * VD + cc]       = make_float2(acc[mt][nt][0], acc[mt][nt][1]);
            *(float2*)&o[(row + 8) * VD + cc] = make_float2(acc[mt][nt][2], acc[mt][nt][3]);
        }
    }
}

// ---------------- rmsnorm * g_norm_weight * silu(g) -> fp16 (single) ----------------
__global__ __launch_bounds__(256) void post_kernel(
    const float* __restrict__ o, const float* __restrict__ g, const float* __restrict__ w,
    __half* __restrict__ oh)
{
    const int t = blockIdx.x, h = blockIdx.y;
    const size_t base = (size_t)t * VD + (size_t)h * DVH;
    const int tid = threadIdx.x;

    float v0 = o[base + tid];
    float v1 = o[base + tid + 256];
    float ss = v0 * v0 + v1 * v1;
    #pragma unroll
    for (int off = 16; off > 0; off >>= 1)
        ss += __shfl_down_sync(0xffffffffu, ss, off);

    __shared__ float red[8];
    __shared__ float inv_s;
    if ((tid & 31) == 0) red[tid >> 5] = ss;
    __syncthreads();
    if (tid == 0) {
        float s = 0.f;
        #pragma unroll
        for (int wi = 0; wi < 8; wi++) s += red[wi];
        inv_s = rsqrtf(s * (1.f / DVH) + EPS_F);
    }
    __syncthreads();
    const float inv = inv_s;

    float g0 = g[base + tid];
    float g1 = g[base + tid + 256];
    float s0 = g0 / (1.f + expf(-g0));
    float s1 = g1 / (1.f + expf(-g1));
    oh[base + tid]       = __float2half(v0 * inv * w[tid]       * s0);
    oh[base + tid + 256] = __float2half(v1 * inv * w[tid + 256] * s1);
}

// ---------------- launch ----------------
extern "C" void kernel_launch(void* const* d_in, const int* in_sizes, int n_in,
                              void* d_out, int out_size)
{
    const float* x    = (const float*)d_in[0];
    const float* Wq   = (const float*)d_in[1];
    const float* Wk   = (const float*)d_in[2];
    const float* Wv   = (const float*)d_in[3];
    const float* Wgk1 = (const float*)d_in[4];
    const float* Wgk2 = (const float*)d_in[5];
    const float* bgk2 = (const float*)d_in[6];
    const float* Wg   = (const float*)d_in[7];
    const float* gnw  = (const float*)d_in[8];
    const float* Wo   = (const float*)d_in[9];
    float* out = (float*)d_out;

    float *q, *k, *v, *g, *gk, *o, *x16, *C;
    __half *xh, *wthi, *wtlo, *wohi, *wolo;
    cudaGetSymbolAddress((void**)&q,    d_q);
    cudaGetSymbolAddress((void**)&k,    d_k);
    cudaGetSymbolAddress((void**)&v,    d_v);
    cudaGetSymbolAddress((void**)&g,    d_gbuf);
    cudaGetSymbolAddress((void**)&gk,   d_gk);
    cudaGetSymbolAddress((void**)&o,    d_o);
    cudaGetSymbolAddress((void**)&x16,  d_x16);
    cudaGetSymbolAddress((void**)&C,    d_C);
    cudaGetSymbolAddress((void**)&xh,   d_xh);
    cudaGetSymbolAddress((void**)&wthi, d_wthi);
    cudaGetSymbolAddress((void**)&wtlo, d_wtlo);
    cudaGetSymbolAddress((void**)&wohi, d_wohi);
    cudaGetSymbolAddress((void**)&wolo, d_wolo);

    // ---- aliasing (lifetimes stream-ordered) ----
    // xh dead after qkvg -> qhi|khi (bf16, exactly TB*HDIM halves = 2*TB*KD bf16)
    __nv_bfloat16* qhi = (__nv_bfloat16*)xh;
    __nv_bfloat16* khi = qhi + (size_t)TB * KD;
    // v fp32 dead after v-split -> qlo|klo
    __nv_bfloat16* qlo = (__nv_bfloat16*)v;
    __nv_bfloat16* klo = qlo + (size_t)TB * KD;
    // qkvg weight splits dead after qkvg -> v splits
    __nv_bfloat16* vhi = (__nv_bfloat16*)wthi;
    __nv_bfloat16* vlo = (__nv_bfloat16*)wtlo;
    // fp32 q dead after prep -> oh (TB*VD halves == TB*KD floats)
    __half* oh = (__half*)q;

    cudaFuncSetAttribute((const void*)qkvg_tc_kernel,
                         cudaFuncAttributeMaxDynamicSharedMemorySize, SMEM_DYN);
    cudaFuncSetAttribute((const void*)wo_tc_kernel,
                         cudaFuncAttributeMaxDynamicSharedMemorySize, SMEM_DYN);
    cudaFuncSetAttribute((const void*)chunk_kv_kernel,
                         cudaFuncAttributeMaxDynamicSharedMemorySize, CKV_SMEM);
    cudaFuncSetAttribute((const void*)gla_out_kernel,
                         cudaFuncAttributeMaxDynamicSharedMemorySize, GLA_SMEM);

    cvth_kernel<<<(size_t)TB * HDIM / 1024, 256>>>(x, xh);
    tsplit_all_kernel<<<16384, 256>>>(Wq, Wk, Wv, Wg, Wo, wthi, wtlo, wohi, wolo);
    gk1_kernel<<<TB, 256>>>(x, Wgk1, x16);
    gk2_kernel<<<TB, 256>>>(x16, Wgk2, bgk2, gk);
    cumsum_kernel<<<BATCH * NCHUNK, 1024>>>(gk);
    qkvg_tc_kernel<<<dim3(QKVG_NT, TB / 128), 256, SMEM_DYN>>>(xh, wthi, wtlo, q, k, v, g);

    split_kernel<<<(size_t)TB * VD / 1024, 256>>>(v, vhi, vlo);            // wt splits dead
    prep_kernel<<<(size_t)TB * KD / 1024, 256>>>(q, k, gk, qhi, qlo, khi, klo); // xh, v fp32 dead

    chunk_kv_kernel<<<dim3(16, BATCH * HNUM * NCHUNK), 256, CKV_SMEM>>>(khi, klo, vhi, vlo, gk, C);
    scan_kernel<<<dim3(16, BATCH * HNUM), 256>>>(gk, C);
    gla_out_kernel<<<dim3(4, BATCH * HNUM * NCHUNK), 256, GLA_SMEM>>>(qhi, qlo, khi, klo, vhi, vlo, C, o);

    post_kernel<<<dim3(TB, HNUM), 256>>>(o, g, gnw, oh);                    // fp32 q dead
    wo_tc_kernel<<<dim3(HDIM / 128, TB / 128), 256, SMEM_DYN>>>(oh, wohi, wolo, out);
}